// round 1
// baseline (speedup 1.0000x reference)
#include <cuda_runtime.h>
#include <math.h>

#define B_   2
#define S_   2048
#define D_   2048
#define H_   16
#define HKV_ 4
#define HD_  128
#define NT   (B_ * S_)          // 4096 tokens

// ---------------- scratch (device globals; no allocation allowed) ----------
__device__ float g_qproj[NT * H_ * HD_];    // [b,s,H,HD]
__device__ float g_kproj[NT * HKV_ * HD_];  // [b,s,HKV,HD]
__device__ float g_vproj[NT * HKV_ * HD_];
__device__ float g_q[NT * H_ * HD_];        // [B,H,S,HD]
__device__ float g_k[NT * HKV_ * HD_];      // [B,HKV,S,HD]
__device__ float g_v[NT * HKV_ * HD_];
__device__ float g_attn[NT * H_ * HD_];     // [b,s,H,HD]

// ---------------- classic 128x128x8 SGEMM, 256 threads, 8x8 per thread -----
__global__ __launch_bounds__(256) void sgemm128(
    const float* __restrict__ A, const float* __restrict__ B,
    float* __restrict__ C, int M, int N, int K)
{
    const int BM = 128, BN = 128, BK = 8, TM = 8, TN = 8;
    __shared__ float As[BK][BM];
    __shared__ float Bs[BK][BN];

    const int tid = threadIdx.x;
    const int tr = tid / 16;            // 0..15 -> rows tr*8..tr*8+7
    const int tc = tid % 16;            // 0..15 -> cols tc*8..tc*8+7

    // A tile load: 128x8 floats, one float4 per thread
    const int a_row = tid >> 1;         // 0..127
    const int a_col = (tid & 1) << 2;   // 0 or 4
    // B tile load: 8x128 floats, one float4 per thread
    const int b_row = tid >> 5;         // 0..7
    const int b_col = (tid & 31) << 2;  // 0..124

    const float* Ab = A + (size_t)blockIdx.y * BM * K;
    const float* Bb = B + (size_t)blockIdx.x * BN;

    float acc[TM][TN];
#pragma unroll
    for (int i = 0; i < TM; i++)
#pragma unroll
        for (int j = 0; j < TN; j++) acc[i][j] = 0.f;

    for (int k0 = 0; k0 < K; k0 += BK) {
        float4 av = *(const float4*)(Ab + (size_t)a_row * K + k0 + a_col);
        As[a_col + 0][a_row] = av.x;
        As[a_col + 1][a_row] = av.y;
        As[a_col + 2][a_row] = av.z;
        As[a_col + 3][a_row] = av.w;
        *(float4*)(&Bs[b_row][b_col]) =
            *(const float4*)(Bb + (size_t)(k0 + b_row) * N + b_col);
        __syncthreads();

#pragma unroll
        for (int kk = 0; kk < BK; kk++) {
            float4 a0 = *(const float4*)(&As[kk][tr * TM]);
            float4 a1 = *(const float4*)(&As[kk][tr * TM + 4]);
            float4 b0 = *(const float4*)(&Bs[kk][tc * TN]);
            float4 b1 = *(const float4*)(&Bs[kk][tc * TN + 4]);
            float ar[TM] = {a0.x, a0.y, a0.z, a0.w, a1.x, a1.y, a1.z, a1.w};
            float br[TN] = {b0.x, b0.y, b0.z, b0.w, b1.x, b1.y, b1.z, b1.w};
#pragma unroll
            for (int i = 0; i < TM; i++)
#pragma unroll
                for (int j = 0; j < TN; j++)
                    acc[i][j] += ar[i] * br[j];
        }
        __syncthreads();
    }

    float* Cb = C + (size_t)blockIdx.y * BM * N + (size_t)blockIdx.x * BN;
#pragma unroll
    for (int i = 0; i < TM; i++) {
        float* crow = Cb + (size_t)(tr * TM + i) * N + tc * TN;
        *(float4*)(crow)     = make_float4(acc[i][0], acc[i][1], acc[i][2], acc[i][3]);
        *(float4*)(crow + 4) = make_float4(acc[i][4], acc[i][5], acc[i][6], acc[i][7]);
    }
}

// ------------- RMSNorm + RoPE + head-major transpose (Q,K) + V transpose ---
// grid: (NT, H_ + 2*HKV_), block: 128 threads (one per head dim)
__global__ void norm_rope_kernel(
    const float* __restrict__ qp, const float* __restrict__ kp,
    const float* __restrict__ vp, const float* __restrict__ qw,
    const float* __restrict__ kw, const int* __restrict__ pos_ids,
    float* __restrict__ Qt, float* __restrict__ Kt, float* __restrict__ Vt)
{
    const int token = blockIdx.x;
    const int b = token / S_, s = token % S_;
    const int hid = blockIdx.y;
    const int d = threadIdx.x;

    if (hid >= H_ + HKV_) {          // V: pure transpose, whole block here
        int h = hid - H_ - HKV_;
        Vt[(((size_t)b * HKV_ + h) * S_ + s) * HD_ + d] =
            vp[((size_t)token * HKV_ + h) * HD_ + d];
        return;
    }

    const bool isq = hid < H_;
    const int h = isq ? hid : hid - H_;
    const int nh = isq ? H_ : HKV_;
    const float* src = isq ? qp : kp;

    float x = src[((size_t)token * nh + h) * HD_ + d];

    // RMS: mean of squares over 128 dims
    float ss = x * x;
#pragma unroll
    for (int o = 16; o > 0; o >>= 1) ss += __shfl_xor_sync(0xffffffffu, ss, o);
    __shared__ float sbuf[4];
    if ((d & 31) == 0) sbuf[d >> 5] = ss;
    __syncthreads();
    float var = (sbuf[0] + sbuf[1] + sbuf[2] + sbuf[3]) * (1.0f / HD_);
    float r = rsqrtf(var + 1e-6f);
    const float* w = isq ? qw : kw;
    float xn = w[d] * (x * r);

    __shared__ float xs[HD_];
    xs[d] = xn;
    __syncthreads();
    float rot = (d < 64) ? -xs[d + 64] : xs[d - 64];

    int p = pos_ids[token];
    float inv = powf(10000.0f, -(float)(2 * (d & 63)) / 128.0f);
    float ang = (float)p * inv;
    float out = xn * cosf(ang) + rot * sinf(ang);

    float* dst = isq ? Qt : Kt;
    dst[(((size_t)b * nh + h) * S_ + s) * HD_ + d] = out;
}

// ---------------- fp32 causal flash attention, GQA ------------------------
// BM=128 query rows per block, BN=64 key rows per iteration, 256 threads.
// Thread (tr=tid/8, tc=tid%8): scores rows tr*4+[0,4), cols tc*8+[0,8);
// output rows tr*4+[0,4), dims tc*16+[0,16).
#define FBM 128
#define FBN 64
#define QP  132
#define KP  132
#define VP  132
#define PP  68
#define FLASH_SMEM ((FBM*QP + FBN*KP + FBN*VP + FBM*PP) * sizeof(float))

__global__ __launch_bounds__(256) void flash_kernel(
    const float* __restrict__ Q, const float* __restrict__ K,
    const float* __restrict__ V, float* __restrict__ O)
{
    extern __shared__ float sm[];
    float* sQ = sm;
    float* sK = sQ + FBM * QP;
    float* sV = sK + FBN * KP;
    float* sP = sV + FBN * VP;

    const int qb = blockIdx.x;
    const int bh = blockIdx.y;
    const int b = bh / H_, h = bh % H_;
    const int kvh = h / (H_ / HKV_);
    const int tid = threadIdx.x;
    const int tr = tid >> 3;   // 0..31
    const int tc = tid & 7;    // 0..7
    const int q0 = qb * FBM;

    const float* Qg = Q + (((size_t)b * H_ + h) * S_ + q0) * HD_;
    const float* Kg = K + ((size_t)b * HKV_ + kvh) * S_ * HD_;
    const float* Vg = V + ((size_t)b * HKV_ + kvh) * S_ * HD_;

    // load Q tile (128 x 128)
    for (int idx = tid; idx < FBM * (HD_ / 4); idx += 256) {
        int row = idx >> 5;
        int c4  = (idx & 31) << 2;
        *(float4*)(sQ + row * QP + c4) = *(const float4*)(Qg + (size_t)row * HD_ + c4);
    }

    float m[4], l[4], acc[4][16];
#pragma unroll
    for (int i = 0; i < 4; i++) {
        m[i] = -1e30f; l[i] = 0.f;
#pragma unroll
        for (int j = 0; j < 16; j++) acc[i][j] = 0.f;
    }

    const int nkb = 2 * qb + 2;          // causal: keys up to q0+127
    const float sc = 0.08838834764831845f; // 1/sqrt(128)

    for (int kb = 0; kb < nkb; kb++) {
        __syncthreads();   // previous iteration done with sK/sV
        for (int idx = tid; idx < FBN * (HD_ / 4); idx += 256) {
            int row = idx >> 5;
            int c4  = (idx & 31) << 2;
            *(float4*)(sK + row * KP + c4) =
                *(const float4*)(Kg + (size_t)(kb * FBN + row) * HD_ + c4);
            *(float4*)(sV + row * VP + c4) =
                *(const float4*)(Vg + (size_t)(kb * FBN + row) * HD_ + c4);
        }
        __syncthreads();

        // ---- scores: 4x8 per thread ----
        float s[4][8];
#pragma unroll
        for (int i = 0; i < 4; i++)
#pragma unroll
            for (int j = 0; j < 8; j++) s[i][j] = 0.f;

        for (int kk = 0; kk < HD_; kk += 4) {
            float4 qv[4], kv[8];
#pragma unroll
            for (int i = 0; i < 4; i++)
                qv[i] = *(const float4*)(sQ + (tr * 4 + i) * QP + kk);
#pragma unroll
            for (int j = 0; j < 8; j++)
                kv[j] = *(const float4*)(sK + (tc * 8 + j) * KP + kk);
#pragma unroll
            for (int i = 0; i < 4; i++)
#pragma unroll
                for (int j = 0; j < 8; j++)
                    s[i][j] += qv[i].x * kv[j].x + qv[i].y * kv[j].y +
                               qv[i].z * kv[j].z + qv[i].w * kv[j].w;
        }

        // ---- scale + causal mask ----
#pragma unroll
        for (int i = 0; i < 4; i++) {
            int qi = q0 + tr * 4 + i;
#pragma unroll
            for (int j = 0; j < 8; j++) {
                int ki = kb * FBN + tc * 8 + j;
                float val = s[i][j] * sc;
                s[i][j] = (ki > qi) ? -1e30f : val;
            }
        }

        // ---- online softmax (row owned by 8 consecutive lanes) ----
#pragma unroll
        for (int i = 0; i < 4; i++) {
            float rm = s[i][0];
#pragma unroll
            for (int j = 1; j < 8; j++) rm = fmaxf(rm, s[i][j]);
#pragma unroll
            for (int o = 1; o < 8; o <<= 1)
                rm = fmaxf(rm, __shfl_xor_sync(0xffffffffu, rm, o));
            float mn = fmaxf(m[i], rm);
            float corr = __expf(m[i] - mn);
            m[i] = mn;
            float rs = 0.f;
#pragma unroll
            for (int j = 0; j < 8; j++) {
                s[i][j] = __expf(s[i][j] - mn);
                rs += s[i][j];
            }
#pragma unroll
            for (int o = 1; o < 8; o <<= 1)
                rs += __shfl_xor_sync(0xffffffffu, rs, o);
            l[i] = l[i] * corr + rs;
#pragma unroll
            for (int j = 0; j < 16; j++) acc[i][j] *= corr;
            float* prow = sP + (tr * 4 + i) * PP + tc * 8;
            *(float4*)(prow)     = make_float4(s[i][0], s[i][1], s[i][2], s[i][3]);
            *(float4*)(prow + 4) = make_float4(s[i][4], s[i][5], s[i][6], s[i][7]);
        }
        __syncwarp();   // P rows are produced/consumed within one warp

        // ---- PV: acc[4][16] += P[4][64] @ V[64][16] ----
        for (int kk = 0; kk < FBN; kk++) {
            float pv[4];
#pragma unroll
            for (int i = 0; i < 4; i++) pv[i] = sP[(tr * 4 + i) * PP + kk];
            const float* vr = sV + kk * VP + tc * 16;
            float4 v0 = *(const float4*)(vr);
            float4 v1 = *(const float4*)(vr + 4);
            float4 v2 = *(const float4*)(vr + 8);
            float4 v3 = *(const float4*)(vr + 12);
#pragma unroll
            for (int i = 0; i < 4; i++) {
                acc[i][0]  += pv[i] * v0.x;  acc[i][1]  += pv[i] * v0.y;
                acc[i][2]  += pv[i] * v0.z;  acc[i][3]  += pv[i] * v0.w;
                acc[i][4]  += pv[i] * v1.x;  acc[i][5]  += pv[i] * v1.y;
                acc[i][6]  += pv[i] * v1.z;  acc[i][7]  += pv[i] * v1.w;
                acc[i][8]  += pv[i] * v2.x;  acc[i][9]  += pv[i] * v2.y;
                acc[i][10] += pv[i] * v2.z;  acc[i][11] += pv[i] * v2.w;
                acc[i][12] += pv[i] * v3.x;  acc[i][13] += pv[i] * v3.y;
                acc[i][14] += pv[i] * v3.z;  acc[i][15] += pv[i] * v3.w;
            }
        }
    }

    // ---- epilogue: O[b, q, h, d] = acc / l ----
#pragma unroll
    for (int i = 0; i < 4; i++) {
        float rl = 1.f / l[i];
        int qi = q0 + tr * 4 + i;
        float* op = O + (((size_t)b * S_ + qi) * H_ + h) * HD_ + tc * 16;
        *(float4*)(op)      = make_float4(acc[i][0]*rl,  acc[i][1]*rl,  acc[i][2]*rl,  acc[i][3]*rl);
        *(float4*)(op + 4)  = make_float4(acc[i][4]*rl,  acc[i][5]*rl,  acc[i][6]*rl,  acc[i][7]*rl);
        *(float4*)(op + 8)  = make_float4(acc[i][8]*rl,  acc[i][9]*rl,  acc[i][10]*rl, acc[i][11]*rl);
        *(float4*)(op + 12) = make_float4(acc[i][12]*rl, acc[i][13]*rl, acc[i][14]*rl, acc[i][15]*rl);
    }
}

// ---------------------------------------------------------------------------
extern "C" void kernel_launch(void* const* d_in, const int* in_sizes, int n_in,
                              void* d_out, int out_size)
{
    const float* hidden = (const float*)d_in[0];
    const float* wq     = (const float*)d_in[1];
    const float* wk     = (const float*)d_in[2];
    const float* wv     = (const float*)d_in[3];
    const float* wo     = (const float*)d_in[4];
    const float* qw     = (const float*)d_in[5];
    const float* kw     = (const float*)d_in[6];
    const int*   pos    = (const int*)d_in[7];
    float* out = (float*)d_out;

    float *qproj, *kproj, *vproj, *q, *k, *v, *attn;
    cudaGetSymbolAddress((void**)&qproj, g_qproj);
    cudaGetSymbolAddress((void**)&kproj, g_kproj);
    cudaGetSymbolAddress((void**)&vproj, g_vproj);
    cudaGetSymbolAddress((void**)&q,     g_q);
    cudaGetSymbolAddress((void**)&k,     g_k);
    cudaGetSymbolAddress((void**)&v,     g_v);
    cudaGetSymbolAddress((void**)&attn,  g_attn);

    cudaFuncSetAttribute(flash_kernel,
                         cudaFuncAttributeMaxDynamicSharedMemorySize,
                         (int)FLASH_SMEM);

    // QKV projections
    sgemm128<<<dim3((H_*HD_)/128,   NT/128), 256>>>(hidden, wq, qproj, NT, H_*HD_,   D_);
    sgemm128<<<dim3((HKV_*HD_)/128, NT/128), 256>>>(hidden, wk, kproj, NT, HKV_*HD_, D_);
    sgemm128<<<dim3((HKV_*HD_)/128, NT/128), 256>>>(hidden, wv, vproj, NT, HKV_*HD_, D_);

    // RMSNorm + RoPE + transpose to [B,H,S,HD]
    norm_rope_kernel<<<dim3(NT, H_ + 2*HKV_), 128>>>(qproj, kproj, vproj,
                                                     qw, kw, pos, q, k, v);

    // causal flash attention -> [b,s,h,d]
    flash_kernel<<<dim3(S_/FBM, B_*H_), 256, FLASH_SMEM>>>(q, k, v, attn);

    // output projection
    sgemm128<<<dim3(D_/128, NT/128), 256>>>(attn, wo, out, NT, D_, D_);
}

// round 2
// speedup vs baseline: 1.0002x; 1.0002x over previous
#include <cuda_runtime.h>
#include <math.h>

#define B_   2
#define S_   2048
#define D_   2048
#define H_   16
#define HKV_ 4
#define HD_  128
#define NT   (B_ * S_)          // 4096 tokens

// ---------------- scratch (device globals; no allocation allowed) ----------
__device__ float g_qproj[NT * H_ * HD_];    // [b,s,H,HD]
__device__ float g_kproj[NT * HKV_ * HD_];  // [b,s,HKV,HD]
__device__ float g_vproj[NT * HKV_ * HD_];
__device__ float g_q[NT * H_ * HD_];        // [B,H,S,HD]
__device__ float g_k[NT * HKV_ * HD_];      // [B,HKV,S,HD]
__device__ float g_v[NT * HKV_ * HD_];
__device__ float g_attn[NT * H_ * HD_];     // [b,s,H,HD]

// ---------------- classic 128x128x8 SGEMM, 256 threads, 8x8 per thread -----
__global__ __launch_bounds__(256) void sgemm128(
    const float* __restrict__ A, const float* __restrict__ B,
    float* __restrict__ C, int M, int N, int K)
{
    const int BM = 128, BN = 128, BK = 8, TM = 8, TN = 8;
    __shared__ float As[BK][BM];
    __shared__ float Bs[BK][BN];

    const int tid = threadIdx.x;
    const int tr = tid / 16;            // 0..15 -> rows tr*8..tr*8+7
    const int tc = tid % 16;            // 0..15 -> cols tc*8..tc*8+7

    // A tile load: 128x8 floats, one float4 per thread
    const int a_row = tid >> 1;         // 0..127
    const int a_col = (tid & 1) << 2;   // 0 or 4
    // B tile load: 8x128 floats, one float4 per thread
    const int b_row = tid >> 5;         // 0..7
    const int b_col = (tid & 31) << 2;  // 0..124

    const float* Ab = A + (size_t)blockIdx.y * BM * K;
    const float* Bb = B + (size_t)blockIdx.x * BN;

    float acc[TM][TN];
#pragma unroll
    for (int i = 0; i < TM; i++)
#pragma unroll
        for (int j = 0; j < TN; j++) acc[i][j] = 0.f;

    for (int k0 = 0; k0 < K; k0 += BK) {
        float4 av = *(const float4*)(Ab + (size_t)a_row * K + k0 + a_col);
        As[a_col + 0][a_row] = av.x;
        As[a_col + 1][a_row] = av.y;
        As[a_col + 2][a_row] = av.z;
        As[a_col + 3][a_row] = av.w;
        *(float4*)(&Bs[b_row][b_col]) =
            *(const float4*)(Bb + (size_t)(k0 + b_row) * N + b_col);
        __syncthreads();

#pragma unroll
        for (int kk = 0; kk < BK; kk++) {
            float4 a0 = *(const float4*)(&As[kk][tr * TM]);
            float4 a1 = *(const float4*)(&As[kk][tr * TM + 4]);
            float4 b0 = *(const float4*)(&Bs[kk][tc * TN]);
            float4 b1 = *(const float4*)(&Bs[kk][tc * TN + 4]);
            float ar[TM] = {a0.x, a0.y, a0.z, a0.w, a1.x, a1.y, a1.z, a1.w};
            float br[TN] = {b0.x, b0.y, b0.z, b0.w, b1.x, b1.y, b1.z, b1.w};
#pragma unroll
            for (int i = 0; i < TM; i++)
#pragma unroll
                for (int j = 0; j < TN; j++)
                    acc[i][j] += ar[i] * br[j];
        }
        __syncthreads();
    }

    float* Cb = C + (size_t)blockIdx.y * BM * N + (size_t)blockIdx.x * BN;
#pragma unroll
    for (int i = 0; i < TM; i++) {
        float* crow = Cb + (size_t)(tr * TM + i) * N + tc * TN;
        *(float4*)(crow)     = make_float4(acc[i][0], acc[i][1], acc[i][2], acc[i][3]);
        *(float4*)(crow + 4) = make_float4(acc[i][4], acc[i][5], acc[i][6], acc[i][7]);
    }
}

// ------------- RMSNorm + RoPE + head-major transpose (Q,K) + V transpose ---
// grid: (NT, H_ + 2*HKV_), block: 128 threads (one per head dim)
__global__ void norm_rope_kernel(
    const float* __restrict__ qp, const float* __restrict__ kp,
    const float* __restrict__ vp, const float* __restrict__ qw,
    const float* __restrict__ kw, const int* __restrict__ pos_ids,
    float* __restrict__ Qt, float* __restrict__ Kt, float* __restrict__ Vt)
{
    const int token = blockIdx.x;
    const int b = token / S_, s = token % S_;
    const int hid = blockIdx.y;
    const int d = threadIdx.x;

    if (hid >= H_ + HKV_) {          // V: pure transpose, whole block here
        int h = hid - H_ - HKV_;
        Vt[(((size_t)b * HKV_ + h) * S_ + s) * HD_ + d] =
            vp[((size_t)token * HKV_ + h) * HD_ + d];
        return;
    }

    const bool isq = hid < H_;
    const int h = isq ? hid : hid - H_;
    const int nh = isq ? H_ : HKV_;
    const float* src = isq ? qp : kp;

    float x = src[((size_t)token * nh + h) * HD_ + d];

    // RMS: mean of squares over 128 dims
    float ss = x * x;
#pragma unroll
    for (int o = 16; o > 0; o >>= 1) ss += __shfl_xor_sync(0xffffffffu, ss, o);
    __shared__ float sbuf[4];
    if ((d & 31) == 0) sbuf[d >> 5] = ss;
    __syncthreads();
    float var = (sbuf[0] + sbuf[1] + sbuf[2] + sbuf[3]) * (1.0f / HD_);
    float r = rsqrtf(var + 1e-6f);
    const float* w = isq ? qw : kw;
    float xn = w[d] * (x * r);

    __shared__ float xs[HD_];
    xs[d] = xn;
    __syncthreads();
    float rot = (d < 64) ? -xs[d + 64] : xs[d - 64];

    int p = pos_ids[token];
    float inv = powf(10000.0f, -(float)(2 * (d & 63)) / 128.0f);
    float ang = (float)p * inv;
    float out = xn * cosf(ang) + rot * sinf(ang);

    float* dst = isq ? Qt : Kt;
    dst[(((size_t)b * nh + h) * S_ + s) * HD_ + d] = out;
}

// ---------------- fp32 causal flash attention, GQA ------------------------
// BM=128 query rows per block, BN=64 key rows per iteration, 256 threads.
// Thread (tr=tid/8, tc=tid%8): scores rows tr*4+[0,4), cols tc*8+[0,8);
// output rows tr*4+[0,4), dims tc*16+[0,16).
#define FBM 128
#define FBN 64
#define QP  132
#define KP  132
#define VP  132
#define PP  68
#define FLASH_SMEM ((FBM*QP + FBN*KP + FBN*VP + FBM*PP) * sizeof(float))

__global__ __launch_bounds__(256) void flash_kernel(
    const float* __restrict__ Q, const float* __restrict__ K,
    const float* __restrict__ V, float* __restrict__ O)
{
    extern __shared__ float sm[];
    float* sQ = sm;
    float* sK = sQ + FBM * QP;
    float* sV = sK + FBN * KP;
    float* sP = sV + FBN * VP;

    const int qb = blockIdx.x;
    const int bh = blockIdx.y;
    const int b = bh / H_, h = bh % H_;
    const int kvh = h / (H_ / HKV_);
    const int tid = threadIdx.x;
    const int tr = tid >> 3;   // 0..31
    const int tc = tid & 7;    // 0..7
    const int q0 = qb * FBM;

    const float* Qg = Q + (((size_t)b * H_ + h) * S_ + q0) * HD_;
    const float* Kg = K + ((size_t)b * HKV_ + kvh) * S_ * HD_;
    const float* Vg = V + ((size_t)b * HKV_ + kvh) * S_ * HD_;

    // load Q tile (128 x 128)
    for (int idx = tid; idx < FBM * (HD_ / 4); idx += 256) {
        int row = idx >> 5;
        int c4  = (idx & 31) << 2;
        *(float4*)(sQ + row * QP + c4) = *(const float4*)(Qg + (size_t)row * HD_ + c4);
    }

    float m[4], l[4], acc[4][16];
#pragma unroll
    for (int i = 0; i < 4; i++) {
        m[i] = -1e30f; l[i] = 0.f;
#pragma unroll
        for (int j = 0; j < 16; j++) acc[i][j] = 0.f;
    }

    const int nkb = 2 * qb + 2;          // causal: keys up to q0+127
    const float sc = 0.08838834764831845f; // 1/sqrt(128)

    for (int kb = 0; kb < nkb; kb++) {
        __syncthreads();   // previous iteration done with sK/sV
        for (int idx = tid; idx < FBN * (HD_ / 4); idx += 256) {
            int row = idx >> 5;
            int c4  = (idx & 31) << 2;
            *(float4*)(sK + row * KP + c4) =
                *(const float4*)(Kg + (size_t)(kb * FBN + row) * HD_ + c4);
            *(float4*)(sV + row * VP + c4) =
                *(const float4*)(Vg + (size_t)(kb * FBN + row) * HD_ + c4);
        }
        __syncthreads();

        // ---- scores: 4x8 per thread ----
        float s[4][8];
#pragma unroll
        for (int i = 0; i < 4; i++)
#pragma unroll
            for (int j = 0; j < 8; j++) s[i][j] = 0.f;

        for (int kk = 0; kk < HD_; kk += 4) {
            float4 qv[4], kv[8];
#pragma unroll
            for (int i = 0; i < 4; i++)
                qv[i] = *(const float4*)(sQ + (tr * 4 + i) * QP + kk);
#pragma unroll
            for (int j = 0; j < 8; j++)
                kv[j] = *(const float4*)(sK + (tc * 8 + j) * KP + kk);
#pragma unroll
            for (int i = 0; i < 4; i++)
#pragma unroll
                for (int j = 0; j < 8; j++)
                    s[i][j] += qv[i].x * kv[j].x + qv[i].y * kv[j].y +
                               qv[i].z * kv[j].z + qv[i].w * kv[j].w;
        }

        // ---- scale + causal mask ----
#pragma unroll
        for (int i = 0; i < 4; i++) {
            int qi = q0 + tr * 4 + i;
#pragma unroll
            for (int j = 0; j < 8; j++) {
                int ki = kb * FBN + tc * 8 + j;
                float val = s[i][j] * sc;
                s[i][j] = (ki > qi) ? -1e30f : val;
            }
        }

        // ---- online softmax (row owned by 8 consecutive lanes) ----
#pragma unroll
        for (int i = 0; i < 4; i++) {
            float rm = s[i][0];
#pragma unroll
            for (int j = 1; j < 8; j++) rm = fmaxf(rm, s[i][j]);
#pragma unroll
            for (int o = 1; o < 8; o <<= 1)
                rm = fmaxf(rm, __shfl_xor_sync(0xffffffffu, rm, o));
            float mn = fmaxf(m[i], rm);
            float corr = __expf(m[i] - mn);
            m[i] = mn;
            float rs = 0.f;
#pragma unroll
            for (int j = 0; j < 8; j++) {
                s[i][j] = __expf(s[i][j] - mn);
                rs += s[i][j];
            }
#pragma unroll
            for (int o = 1; o < 8; o <<= 1)
                rs += __shfl_xor_sync(0xffffffffu, rs, o);
            l[i] = l[i] * corr + rs;
#pragma unroll
            for (int j = 0; j < 16; j++) acc[i][j] *= corr;
            float* prow = sP + (tr * 4 + i) * PP + tc * 8;
            *(float4*)(prow)     = make_float4(s[i][0], s[i][1], s[i][2], s[i][3]);
            *(float4*)(prow + 4) = make_float4(s[i][4], s[i][5], s[i][6], s[i][7]);
        }
        __syncwarp();   // P rows are produced/consumed within one warp

        // ---- PV: acc[4][16] += P[4][64] @ V[64][16] ----
        for (int kk = 0; kk < FBN; kk++) {
            float pv[4];
#pragma unroll
            for (int i = 0; i < 4; i++) pv[i] = sP[(tr * 4 + i) * PP + kk];
            const float* vr = sV + kk * VP + tc * 16;
            float4 v0 = *(const float4*)(vr);
            float4 v1 = *(const float4*)(vr + 4);
            float4 v2 = *(const float4*)(vr + 8);
            float4 v3 = *(const float4*)(vr + 12);
#pragma unroll
            for (int i = 0; i < 4; i++) {
                acc[i][0]  += pv[i] * v0.x;  acc[i][1]  += pv[i] * v0.y;
                acc[i][2]  += pv[i] * v0.z;  acc[i][3]  += pv[i] * v0.w;
                acc[i][4]  += pv[i] * v1.x;  acc[i][5]  += pv[i] * v1.y;
                acc[i][6]  += pv[i] * v1.z;  acc[i][7]  += pv[i] * v1.w;
                acc[i][8]  += pv[i] * v2.x;  acc[i][9]  += pv[i] * v2.y;
                acc[i][10] += pv[i] * v2.z;  acc[i][11] += pv[i] * v2.w;
                acc[i][12] += pv[i] * v3.x;  acc[i][13] += pv[i] * v3.y;
                acc[i][14] += pv[i] * v3.z;  acc[i][15] += pv[i] * v3.w;
            }
        }
    }

    // ---- epilogue: O[b, q, h, d] = acc / l ----
#pragma unroll
    for (int i = 0; i < 4; i++) {
        float rl = 1.f / l[i];
        int qi = q0 + tr * 4 + i;
        float* op = O + (((size_t)b * S_ + qi) * H_ + h) * HD_ + tc * 16;
        *(float4*)(op)      = make_float4(acc[i][0]*rl,  acc[i][1]*rl,  acc[i][2]*rl,  acc[i][3]*rl);
        *(float4*)(op + 4)  = make_float4(acc[i][4]*rl,  acc[i][5]*rl,  acc[i][6]*rl,  acc[i][7]*rl);
        *(float4*)(op + 8)  = make_float4(acc[i][8]*rl,  acc[i][9]*rl,  acc[i][10]*rl, acc[i][11]*rl);
        *(float4*)(op + 12) = make_float4(acc[i][12]*rl, acc[i][13]*rl, acc[i][14]*rl, acc[i][15]*rl);
    }
}

// ---------------------------------------------------------------------------
extern "C" void kernel_launch(void* const* d_in, const int* in_sizes, int n_in,
                              void* d_out, int out_size)
{
    const float* hidden = (const float*)d_in[0];
    const float* wq     = (const float*)d_in[1];
    const float* wk     = (const float*)d_in[2];
    const float* wv     = (const float*)d_in[3];
    const float* wo     = (const float*)d_in[4];
    const float* qw     = (const float*)d_in[5];
    const float* kw     = (const float*)d_in[6];
    const int*   pos    = (const int*)d_in[7];
    float* out = (float*)d_out;

    float *qproj, *kproj, *vproj, *q, *k, *v, *attn;
    cudaGetSymbolAddress((void**)&qproj, g_qproj);
    cudaGetSymbolAddress((void**)&kproj, g_kproj);
    cudaGetSymbolAddress((void**)&vproj, g_vproj);
    cudaGetSymbolAddress((void**)&q,     g_q);
    cudaGetSymbolAddress((void**)&k,     g_k);
    cudaGetSymbolAddress((void**)&v,     g_v);
    cudaGetSymbolAddress((void**)&attn,  g_attn);

    cudaFuncSetAttribute(flash_kernel,
                         cudaFuncAttributeMaxDynamicSharedMemorySize,
                         (int)FLASH_SMEM);

    // QKV projections
    sgemm128<<<dim3((H_*HD_)/128,   NT/128), 256>>>(hidden, wq, qproj, NT, H_*HD_,   D_);
    sgemm128<<<dim3((HKV_*HD_)/128, NT/128), 256>>>(hidden, wk, kproj, NT, HKV_*HD_, D_);
    sgemm128<<<dim3((HKV_*HD_)/128, NT/128), 256>>>(hidden, wv, vproj, NT, HKV_*HD_, D_);

    // RMSNorm + RoPE + transpose to [B,H,S,HD]
    norm_rope_kernel<<<dim3(NT, H_ + 2*HKV_), 128>>>(qproj, kproj, vproj,
                                                     qw, kw, pos, q, k, v);

    // causal flash attention -> [b,s,h,d]
    flash_kernel<<<dim3(S_/FBM, B_*H_), 256, FLASH_SMEM>>>(q, k, v, attn);

    // output projection
    sgemm128<<<dim3(D_/128, NT/128), 256>>>(attn, wo, out, NT, D_, D_);
}

// round 4
// speedup vs baseline: 1.2966x; 1.2964x over previous
#include <cuda_runtime.h>
#include <cuda_bf16.h>
#include <math.h>
#include <stdint.h>

#define B_   2
#define S_   2048
#define D_   2048
#define H_   16
#define HKV_ 4
#define HD_  128
#define NT   (B_ * S_)

// ---------------- scratch ---------------------------------------------------
__device__ float g_qproj[NT * H_ * HD_];
__device__ float g_kproj[NT * HKV_ * HD_];
__device__ float g_vproj[NT * HKV_ * HD_];
__device__ float g_q[NT * H_ * HD_];
__device__ float g_k[NT * HKV_ * HD_];
__device__ float g_v[NT * HKV_ * HD_];
__device__ float g_attn[NT * H_ * HD_];

__device__ __nv_bfloat16 g_hid_hi[NT * D_];
__device__ __nv_bfloat16 g_hid_lo[NT * D_];
__device__ __nv_bfloat16 g_wqT_hi[D_ * (H_*HD_)];
__device__ __nv_bfloat16 g_wqT_lo[D_ * (H_*HD_)];
__device__ __nv_bfloat16 g_wkT_hi[D_ * (HKV_*HD_)];
__device__ __nv_bfloat16 g_wkT_lo[D_ * (HKV_*HD_)];
__device__ __nv_bfloat16 g_wvT_hi[D_ * (HKV_*HD_)];
__device__ __nv_bfloat16 g_wvT_lo[D_ * (HKV_*HD_)];
__device__ __nv_bfloat16 g_woT_hi[(H_*HD_) * D_];
__device__ __nv_bfloat16 g_woT_lo[(H_*HD_) * D_];
__device__ __nv_bfloat16 g_at_hi[NT * (H_*HD_)];
__device__ __nv_bfloat16 g_at_lo[NT * (H_*HD_)];

// ---------------- helpers ---------------------------------------------------
__device__ __forceinline__ uint32_t s2u(const void* p) {
    return (uint32_t)__cvta_generic_to_shared(p);
}
__device__ __forceinline__ void cpasync16(uint32_t dst, const void* src) {
    asm volatile("cp.async.cg.shared.global [%0], [%1], 16;" :: "r"(dst), "l"(src));
}
#define CP_COMMIT() asm volatile("cp.async.commit_group;")
#define CP_WAIT(N)  asm volatile("cp.async.wait_group %0;" :: "n"(N))

__device__ __forceinline__ void mma16816(float* d, const uint32_t* a, const uint32_t* b) {
    asm volatile(
        "mma.sync.aligned.m16n8k16.row.col.f32.bf16.bf16.f32 "
        "{%0,%1,%2,%3}, {%4,%5,%6,%7}, {%8,%9}, {%0,%1,%2,%3};"
        : "+f"(d[0]), "+f"(d[1]), "+f"(d[2]), "+f"(d[3])
        : "r"(a[0]), "r"(a[1]), "r"(a[2]), "r"(a[3]), "r"(b[0]), "r"(b[1]));
}

// ---------------- fp32 -> bf16 hi/lo split ----------------------------------
__global__ __launch_bounds__(256) void split_kernel(
    const float4* __restrict__ src, uint2* __restrict__ hi,
    uint2* __restrict__ lo, int n4)
{
    int i = blockIdx.x * 256 + threadIdx.x;
    if (i >= n4) return;
    float4 v = src[i];
    __nv_bfloat162 h0 = __floats2bfloat162_rn(v.x, v.y);
    __nv_bfloat162 h1 = __floats2bfloat162_rn(v.z, v.w);
    __nv_bfloat162 l0 = __floats2bfloat162_rn(v.x - __bfloat162float(h0.x),
                                              v.y - __bfloat162float(h0.y));
    __nv_bfloat162 l1 = __floats2bfloat162_rn(v.z - __bfloat162float(h1.x),
                                              v.w - __bfloat162float(h1.y));
    uint2 H, L;
    H.x = *(uint32_t*)&h0; H.y = *(uint32_t*)&h1;
    L.x = *(uint32_t*)&l0; L.y = *(uint32_t*)&l1;
    hi[i] = H; lo[i] = L;
}

// ---------------- W[K,N] -> WT hi/lo [N,K] ----------------------------------
__global__ void transpose_split(const float* __restrict__ W,
                                __nv_bfloat16* __restrict__ hiT,
                                __nv_bfloat16* __restrict__ loT, int K, int N)
{
    __shared__ float t[32][33];
    int n0 = blockIdx.x * 32, k0 = blockIdx.y * 32;
    int tx = threadIdx.x, ty = threadIdx.y;
    for (int j = ty; j < 32; j += 8)
        t[j][tx] = W[(size_t)(k0 + j) * N + n0 + tx];
    __syncthreads();
    for (int j = ty; j < 32; j += 8) {
        float x = t[tx][j];
        __nv_bfloat16 h = __float2bfloat16(x);
        __nv_bfloat16 l = __float2bfloat16(x - __bfloat162float(h));
        size_t o = (size_t)(n0 + j) * K + k0 + tx;
        hiT[o] = h; loT[o] = l;
    }
}

// ---------------- mma.sync bf16x3 split GEMM --------------------------------
// C[M,N] = (Ah+Al)[M,K] @ (Bh+Bl)[N,K]^T, 3 terms, fp32 accum.
// CTA tile 128x256, 8 warps of 64x64. K chunk = 64 bf16, double buffered.
// smem row stride 144B (128B data + 16B pad) -> conflict-free frag loads.
#define KC      64
#define RSTRIDE 144
#define OFF_AL  18432               // 128*144
#define OFF_BH  36864
#define OFF_BL  (36864 + 36864)
#define STAGE   110592              // A hi/lo + B hi/lo
#define G_SMEM  (2 * STAGE)

__global__ __launch_bounds__(256, 1) void gemm_mma(
    const __nv_bfloat16* __restrict__ Ah, const __nv_bfloat16* __restrict__ Al,
    const __nv_bfloat16* __restrict__ Bh, const __nv_bfloat16* __restrict__ Bl,
    float* __restrict__ C, int M, int N, int K)
{
    extern __shared__ char sm[];
    const uint32_t smb = s2u(sm);
    const int tid  = threadIdx.x;
    const int wid  = tid >> 5, lane = tid & 31;
    const int wm   = wid & 1, wn = wid >> 1;      // 2 x 4 warp grid
    const int g    = lane >> 2, tg = lane & 3;
    const int m0   = blockIdx.y * 128, n0 = blockIdx.x * 256;

    float acc[4][8][4];
#pragma unroll
    for (int a = 0; a < 4; a++)
#pragma unroll
        for (int b = 0; b < 8; b++)
#pragma unroll
            for (int c = 0; c < 4; c++) acc[a][b][c] = 0.f;

    const int nchunks = K / KC;

    auto load_chunk = [&](int kc, int st) {
        uint32_t base = smb + st * STAGE;
        int k0 = kc * KC;
#pragma unroll
        for (int i = 0; i < 4; i++) {               // A: 128 rows x 8 segs
            int lin = tid + i * 256;
            int r = lin >> 3, sg = lin & 7;
            uint32_t off = r * RSTRIDE + sg * 16;
            size_t gidx = (size_t)(m0 + r) * K + k0 + sg * 8;
            cpasync16(base + off,          Ah + gidx);
            cpasync16(base + OFF_AL + off, Al + gidx);
        }
#pragma unroll
        for (int i = 0; i < 8; i++) {               // B: 256 rows x 8 segs
            int lin = tid + i * 256;
            int r = lin >> 3, sg = lin & 7;
            uint32_t off = r * RSTRIDE + sg * 16;
            size_t gidx = (size_t)(n0 + r) * K + k0 + sg * 8;
            cpasync16(base + OFF_BH + off, Bh + gidx);
            cpasync16(base + OFF_BL + off, Bl + gidx);
        }
        CP_COMMIT();
    };

    auto compute = [&](int st) {
        const char* base = sm + st * STAGE;
        const char* pa = base + (wm * 64 + g) * RSTRIDE + tg * 4;
        const char* pb = base + OFF_BH + (wn * 64 + g) * RSTRIDE + tg * 4;
#pragma unroll
        for (int ks = 0; ks < 4; ks++) {
            int ko = ks * 32;                        // 16 bf16 = 32 bytes
            uint32_t ah[4][4], al[4][4];
#pragma unroll
            for (int mt = 0; mt < 4; mt++) {
                const char* p = pa + mt * 16 * RSTRIDE + ko;
                ah[mt][0] = *(const uint32_t*)(p);
                ah[mt][1] = *(const uint32_t*)(p + 8 * RSTRIDE);
                ah[mt][2] = *(const uint32_t*)(p + 16);
                ah[mt][3] = *(const uint32_t*)(p + 8 * RSTRIDE + 16);
                const char* q = p + OFF_AL;
                al[mt][0] = *(const uint32_t*)(q);
                al[mt][1] = *(const uint32_t*)(q + 8 * RSTRIDE);
                al[mt][2] = *(const uint32_t*)(q + 16);
                al[mt][3] = *(const uint32_t*)(q + 8 * RSTRIDE + 16);
            }
#pragma unroll
            for (int ng = 0; ng < 2; ng++) {
                uint32_t bh[4][2], bl[4][2];
#pragma unroll
                for (int nt = 0; nt < 4; nt++) {
                    const char* p = pb + (ng * 4 + nt) * 8 * RSTRIDE + ko;
                    bh[nt][0] = *(const uint32_t*)(p);
                    bh[nt][1] = *(const uint32_t*)(p + 16);
                    const char* q = p + 36864;       // OFF_BL - OFF_BH
                    bl[nt][0] = *(const uint32_t*)(q);
                    bl[nt][1] = *(const uint32_t*)(q + 16);
                }
#pragma unroll
                for (int mt = 0; mt < 4; mt++)
#pragma unroll
                    for (int nt = 0; nt < 4; nt++) {
                        float* d = acc[mt][ng * 4 + nt];
                        mma16816(d, ah[mt], bh[nt]);
                        mma16816(d, ah[mt], bl[nt]);
                        mma16816(d, al[mt], bh[nt]);
                    }
            }
        }
    };

    load_chunk(0, 0);
    for (int kc = 0; kc < nchunks; kc++) {
        int st = kc & 1;
        if (kc + 1 < nchunks) load_chunk(kc + 1, st ^ 1);
        if (kc + 1 < nchunks) { CP_WAIT(1); } else { CP_WAIT(0); }
        __syncthreads();
        compute(st);
        __syncthreads();
    }

    // epilogue
#pragma unroll
    for (int mt = 0; mt < 4; mt++)
#pragma unroll
        for (int nt = 0; nt < 8; nt++) {
            int r = m0 + wm * 64 + mt * 16 + g;
            int c = n0 + wn * 64 + nt * 8 + tg * 2;
            float2 v0 = make_float2(acc[mt][nt][0], acc[mt][nt][1]);
            float2 v1 = make_float2(acc[mt][nt][2], acc[mt][nt][3]);
            *(float2*)&C[(size_t)r * N + c]       = v0;
            *(float2*)&C[(size_t)(r + 8) * N + c] = v1;
        }
}

// ---------------- RMSNorm + RoPE + transpose --------------------------------
__global__ void norm_rope_kernel(
    const float* __restrict__ qp, const float* __restrict__ kp,
    const float* __restrict__ vp, const float* __restrict__ qw,
    const float* __restrict__ kw, const int* __restrict__ pos_ids,
    float* __restrict__ Qt, float* __restrict__ Kt, float* __restrict__ Vt)
{
    const int token = blockIdx.x;
    const int b = token / S_, s = token % S_;
    const int hid = blockIdx.y;
    const int d = threadIdx.x;

    if (hid >= H_ + HKV_) {
        int h = hid - H_ - HKV_;
        Vt[(((size_t)b * HKV_ + h) * S_ + s) * HD_ + d] =
            vp[((size_t)token * HKV_ + h) * HD_ + d];
        return;
    }
    const bool isq = hid < H_;
    const int h = isq ? hid : hid - H_;
    const int nh = isq ? H_ : HKV_;
    const float* src = isq ? qp : kp;

    float x = src[((size_t)token * nh + h) * HD_ + d];
    float ss = x * x;
#pragma unroll
    for (int o = 16; o > 0; o >>= 1) ss += __shfl_xor_sync(0xffffffffu, ss, o);
    __shared__ float sbuf[4];
    if ((d & 31) == 0) sbuf[d >> 5] = ss;
    __syncthreads();
    float var = (sbuf[0] + sbuf[1] + sbuf[2] + sbuf[3]) * (1.0f / HD_);
    float r = rsqrtf(var + 1e-6f);
    const float* w = isq ? qw : kw;
    float xn = w[d] * (x * r);

    __shared__ float xs[HD_];
    xs[d] = xn;
    __syncthreads();
    float rot = (d < 64) ? -xs[d + 64] : xs[d - 64];

    int p = pos_ids[token];
    float inv = exp2f(-13.287712379549449f * (float)(2 * (d & 63)) * (1.0f / 128.0f));
    float ang = (float)p * inv;
    float cs, sn;
    sincosf(ang, &sn, &cs);
    float out = xn * cs + rot * sn;

    float* dst = isq ? Qt : Kt;
    dst[(((size_t)b * nh + h) * S_ + s) * HD_ + d] = out;
}

// ---------------- fp32 causal flash attention -------------------------------
#define FBM 128
#define FBN 64
#define QP  132
#define KP  132
#define VP  132
#define PP  68
#define FLASH_SMEM ((FBM*QP + FBN*KP + FBN*VP + FBM*PP) * sizeof(float))

__global__ __launch_bounds__(256) void flash_kernel(
    const float* __restrict__ Q, const float* __restrict__ K,
    const float* __restrict__ V, float* __restrict__ O)
{
    extern __shared__ float smf[];
    float* sQ = smf;
    float* sK = sQ + FBM * QP;
    float* sV = sK + FBN * KP;
    float* sP = sV + FBN * VP;

    const int qb = blockIdx.x;
    const int bh = blockIdx.y;
    const int b = bh / H_, h = bh % H_;
    const int kvh = h / (H_ / HKV_);
    const int tid = threadIdx.x;
    const int tr = tid >> 3;
    const int tc = tid & 7;
    const int q0 = qb * FBM;

    const float* Qg = Q + (((size_t)b * H_ + h) * S_ + q0) * HD_;
    const float* Kg = K + ((size_t)b * HKV_ + kvh) * S_ * HD_;
    const float* Vg = V + ((size_t)b * HKV_ + kvh) * S_ * HD_;

    for (int idx = tid; idx < FBM * (HD_ / 4); idx += 256) {
        int row = idx >> 5;
        int c4  = (idx & 31) << 2;
        *(float4*)(sQ + row * QP + c4) = *(const float4*)(Qg + (size_t)row * HD_ + c4);
    }

    float m[4], l[4], acc[4][16];
#pragma unroll
    for (int i = 0; i < 4; i++) {
        m[i] = -1e30f; l[i] = 0.f;
#pragma unroll
        for (int j = 0; j < 16; j++) acc[i][j] = 0.f;
    }

    const int nkb = 2 * qb + 2;
    const float sc = 0.08838834764831845f;

    for (int kb = 0; kb < nkb; kb++) {
        __syncthreads();
        for (int idx = tid; idx < FBN * (HD_ / 4); idx += 256) {
            int row = idx >> 5;
            int c4  = (idx & 31) << 2;
            *(float4*)(sK + row * KP + c4) =
                *(const float4*)(Kg + (size_t)(kb * FBN + row) * HD_ + c4);
            *(float4*)(sV + row * VP + c4) =
                *(const float4*)(Vg + (size_t)(kb * FBN + row) * HD_ + c4);
        }
        __syncthreads();

        float s[4][8];
#pragma unroll
        for (int i = 0; i < 4; i++)
#pragma unroll
            for (int j = 0; j < 8; j++) s[i][j] = 0.f;

        for (int kk = 0; kk < HD_; kk += 4) {
            float4 qv[4], kv[8];
#pragma unroll
            for (int i = 0; i < 4; i++)
                qv[i] = *(const float4*)(sQ + (tr * 4 + i) * QP + kk);
#pragma unroll
            for (int j = 0; j < 8; j++)
                kv[j] = *(const float4*)(sK + (tc * 8 + j) * KP + kk);
#pragma unroll
            for (int i = 0; i < 4; i++)
#pragma unroll
                for (int j = 0; j < 8; j++)
                    s[i][j] += qv[i].x * kv[j].x + qv[i].y * kv[j].y +
                               qv[i].z * kv[j].z + qv[i].w * kv[j].w;
        }

#pragma unroll
        for (int i = 0; i < 4; i++) {
            int qi = q0 + tr * 4 + i;
#pragma unroll
            for (int j = 0; j < 8; j++) {
                int ki = kb * FBN + tc * 8 + j;
                float val = s[i][j] * sc;
                s[i][j] = (ki > qi) ? -1e30f : val;
            }
        }

#pragma unroll
        for (int i = 0; i < 4; i++) {
            float rm = s[i][0];
#pragma unroll
            for (int j = 1; j < 8; j++) rm = fmaxf(rm, s[i][j]);
#pragma unroll
            for (int o = 1; o < 8; o <<= 1)
                rm = fmaxf(rm, __shfl_xor_sync(0xffffffffu, rm, o));
            float mn = fmaxf(m[i], rm);
            float corr = __expf(m[i] - mn);
            m[i] = mn;
            float rs = 0.f;
#pragma unroll
            for (int j = 0; j < 8; j++) {
                s[i][j] = __expf(s[i][j] - mn);
                rs += s[i][j];
            }
#pragma unroll
            for (int o = 1; o < 8; o <<= 1)
                rs += __shfl_xor_sync(0xffffffffu, rs, o);
            l[i] = l[i] * corr + rs;
#pragma unroll
            for (int j = 0; j < 16; j++) acc[i][j] *= corr;
            float* prow = sP + (tr * 4 + i) * PP + tc * 8;
            *(float4*)(prow)     = make_float4(s[i][0], s[i][1], s[i][2], s[i][3]);
            *(float4*)(prow + 4) = make_float4(s[i][4], s[i][5], s[i][6], s[i][7]);
        }
        __syncwarp();

        for (int kk = 0; kk < FBN; kk++) {
            float pv[4];
#pragma unroll
            for (int i = 0; i < 4; i++) pv[i] = sP[(tr * 4 + i) * PP + kk];
            const float* vr = sV + kk * VP + tc * 16;
            float4 v0 = *(const float4*)(vr);
            float4 v1 = *(const float4*)(vr + 4);
            float4 v2 = *(const float4*)(vr + 8);
            float4 v3 = *(const float4*)(vr + 12);
#pragma unroll
            for (int i = 0; i < 4; i++) {
                acc[i][0]  += pv[i] * v0.x;  acc[i][1]  += pv[i] * v0.y;
                acc[i][2]  += pv[i] * v0.z;  acc[i][3]  += pv[i] * v0.w;
                acc[i][4]  += pv[i] * v1.x;  acc[i][5]  += pv[i] * v1.y;
                acc[i][6]  += pv[i] * v1.z;  acc[i][7]  += pv[i] * v1.w;
                acc[i][8]  += pv[i] * v2.x;  acc[i][9]  += pv[i] * v2.y;
                acc[i][10] += pv[i] * v2.z;  acc[i][11] += pv[i] * v2.w;
                acc[i][12] += pv[i] * v3.x;  acc[i][13] += pv[i] * v3.y;
                acc[i][14] += pv[i] * v3.z;  acc[i][15] += pv[i] * v3.w;
            }
        }
    }

#pragma unroll
    for (int i = 0; i < 4; i++) {
        float rl = 1.f / l[i];
        int qi = q0 + tr * 4 + i;
        float* op = O + (((size_t)b * S_ + qi) * H_ + h) * HD_ + tc * 16;
        *(float4*)(op)      = make_float4(acc[i][0]*rl,  acc[i][1]*rl,  acc[i][2]*rl,  acc[i][3]*rl);
        *(float4*)(op + 4)  = make_float4(acc[i][4]*rl,  acc[i][5]*rl,  acc[i][6]*rl,  acc[i][7]*rl);
        *(float4*)(op + 8)  = make_float4(acc[i][8]*rl,  acc[i][9]*rl,  acc[i][10]*rl, acc[i][11]*rl);
        *(float4*)(op + 12) = make_float4(acc[i][12]*rl, acc[i][13]*rl, acc[i][14]*rl, acc[i][15]*rl);
    }
}

// ---------------------------------------------------------------------------
extern "C" void kernel_launch(void* const* d_in, const int* in_sizes, int n_in,
                              void* d_out, int out_size)
{
    const float* hidden = (const float*)d_in[0];
    const float* wq     = (const float*)d_in[1];
    const float* wk     = (const float*)d_in[2];
    const float* wv     = (const float*)d_in[3];
    const float* wo     = (const float*)d_in[4];
    const float* qw     = (const float*)d_in[5];
    const float* kw     = (const float*)d_in[6];
    const int*   pos    = (const int*)d_in[7];
    float* out = (float*)d_out;

    float *qproj, *kproj, *vproj, *q, *k, *v, *attn;
    cudaGetSymbolAddress((void**)&qproj, g_qproj);
    cudaGetSymbolAddress((void**)&kproj, g_kproj);
    cudaGetSymbolAddress((void**)&vproj, g_vproj);
    cudaGetSymbolAddress((void**)&q,     g_q);
    cudaGetSymbolAddress((void**)&k,     g_k);
    cudaGetSymbolAddress((void**)&v,     g_v);
    cudaGetSymbolAddress((void**)&attn,  g_attn);

    __nv_bfloat16 *hh, *hl, *wqh, *wql, *wkh, *wkl, *wvh, *wvl, *woh, *wol, *ath, *atl;
    cudaGetSymbolAddress((void**)&hh,  g_hid_hi);
    cudaGetSymbolAddress((void**)&hl,  g_hid_lo);
    cudaGetSymbolAddress((void**)&wqh, g_wqT_hi);
    cudaGetSymbolAddress((void**)&wql, g_wqT_lo);
    cudaGetSymbolAddress((void**)&wkh, g_wkT_hi);
    cudaGetSymbolAddress((void**)&wkl, g_wkT_lo);
    cudaGetSymbolAddress((void**)&wvh, g_wvT_hi);
    cudaGetSymbolAddress((void**)&wvl, g_wvT_lo);
    cudaGetSymbolAddress((void**)&woh, g_woT_hi);
    cudaGetSymbolAddress((void**)&wol, g_woT_lo);
    cudaGetSymbolAddress((void**)&ath, g_at_hi);
    cudaGetSymbolAddress((void**)&atl, g_at_lo);

    cudaFuncSetAttribute(flash_kernel, cudaFuncAttributeMaxDynamicSharedMemorySize,
                         (int)FLASH_SMEM);
    cudaFuncSetAttribute(gemm_mma, cudaFuncAttributeMaxDynamicSharedMemorySize,
                         (int)G_SMEM);

    // split hidden into hi/lo bf16
    int n4 = NT * D_ / 4;
    split_kernel<<<(n4 + 255) / 256, 256>>>((const float4*)hidden, (uint2*)hh, (uint2*)hl, n4);

    // transpose+split weights: W[K,N] -> WT[N,K]
    transpose_split<<<dim3((H_*HD_)/32, D_/32), dim3(32, 8)>>>(wq, wqh, wql, D_, H_*HD_);
    transpose_split<<<dim3((HKV_*HD_)/32, D_/32), dim3(32, 8)>>>(wk, wkh, wkl, D_, HKV_*HD_);
    transpose_split<<<dim3((HKV_*HD_)/32, D_/32), dim3(32, 8)>>>(wv, wvh, wvl, D_, HKV_*HD_);
    transpose_split<<<dim3(D_/32, (H_*HD_)/32), dim3(32, 8)>>>(wo, woh, wol, H_*HD_, D_);

    // QKV projections (mma.sync bf16x3)
    gemm_mma<<<dim3((H_*HD_)/256,   NT/128), 256, G_SMEM>>>(hh, hl, wqh, wql, qproj, NT, H_*HD_,   D_);
    gemm_mma<<<dim3((HKV_*HD_)/256, NT/128), 256, G_SMEM>>>(hh, hl, wkh, wkl, kproj, NT, HKV_*HD_, D_);
    gemm_mma<<<dim3((HKV_*HD_)/256, NT/128), 256, G_SMEM>>>(hh, hl, wvh, wvl, vproj, NT, HKV_*HD_, D_);

    // RMSNorm + RoPE + transpose
    norm_rope_kernel<<<dim3(NT, H_ + 2*HKV_), 128>>>(qproj, kproj, vproj, qw, kw, pos, q, k, v);

    // causal flash attention -> [token, H*HD]
    flash_kernel<<<dim3(S_/FBM, B_*H_), 256, FLASH_SMEM>>>(q, k, v, attn);

    // split attention output, then output projection (mma.sync bf16x3)
    int a4 = NT * (H_*HD_) / 4;
    split_kernel<<<(a4 + 255) / 256, 256>>>((const float4*)attn, (uint2*)ath, (uint2*)atl, a4);
    gemm_mma<<<dim3(D_/256, NT/128), 256, G_SMEM>>>(ath, atl, woh, wol, out, NT, D_, D_);
}

// round 5
// speedup vs baseline: 4.7988x; 3.7012x over previous
#include <cuda_runtime.h>
#include <cuda_bf16.h>
#include <math.h>
#include <stdint.h>

#define B_   2
#define S_   2048
#define D_   2048
#define H_   16
#define HKV_ 4
#define HD_  128
#define NT   (B_ * S_)

// ---------------- scratch ---------------------------------------------------
__device__ float g_qproj[NT * H_ * HD_];
__device__ float g_kproj[NT * HKV_ * HD_];
__device__ float g_vproj[NT * HKV_ * HD_];

__device__ __nv_bfloat16 g_hid_hi[NT * D_];
__device__ __nv_bfloat16 g_hid_lo[NT * D_];
__device__ __nv_bfloat16 g_wqT_hi[D_ * (H_*HD_)];
__device__ __nv_bfloat16 g_wqT_lo[D_ * (H_*HD_)];
__device__ __nv_bfloat16 g_wkT_hi[D_ * (HKV_*HD_)];
__device__ __nv_bfloat16 g_wkT_lo[D_ * (HKV_*HD_)];
__device__ __nv_bfloat16 g_wvT_hi[D_ * (HKV_*HD_)];
__device__ __nv_bfloat16 g_wvT_lo[D_ * (HKV_*HD_)];
__device__ __nv_bfloat16 g_woT_hi[(H_*HD_) * D_];
__device__ __nv_bfloat16 g_woT_lo[(H_*HD_) * D_];
__device__ __nv_bfloat16 g_at_hi[NT * (H_*HD_)];
__device__ __nv_bfloat16 g_at_lo[NT * (H_*HD_)];

// bf16 hi/lo Q,K ([b,h,s,d]) and V^T ([b,kvh,d,s])
__device__ __nv_bfloat16 g_qh[NT * H_ * HD_];
__device__ __nv_bfloat16 g_ql[NT * H_ * HD_];
__device__ __nv_bfloat16 g_kh[NT * HKV_ * HD_];
__device__ __nv_bfloat16 g_kl[NT * HKV_ * HD_];
__device__ __nv_bfloat16 g_vth[NT * HKV_ * HD_];
__device__ __nv_bfloat16 g_vtl[NT * HKV_ * HD_];

// ---------------- helpers ---------------------------------------------------
__device__ __forceinline__ uint32_t s2u(const void* p) {
    return (uint32_t)__cvta_generic_to_shared(p);
}
__device__ __forceinline__ void cpasync16(uint32_t dst, const void* src) {
    asm volatile("cp.async.cg.shared.global [%0], [%1], 16;" :: "r"(dst), "l"(src));
}
#define CP_COMMIT() asm volatile("cp.async.commit_group;")
#define CP_WAIT(N)  asm volatile("cp.async.wait_group %0;" :: "n"(N))

__device__ __forceinline__ void mma16816(float* d, const uint32_t* a, const uint32_t* b) {
    asm volatile(
        "mma.sync.aligned.m16n8k16.row.col.f32.bf16.bf16.f32 "
        "{%0,%1,%2,%3}, {%4,%5,%6,%7}, {%8,%9}, {%0,%1,%2,%3};"
        : "+f"(d[0]), "+f"(d[1]), "+f"(d[2]), "+f"(d[3])
        : "r"(a[0]), "r"(a[1]), "r"(a[2]), "r"(a[3]), "r"(b[0]), "r"(b[1]));
}
__device__ __forceinline__ uint32_t pack_hi(float x, float y) {
    __nv_bfloat162 h = __floats2bfloat162_rn(x, y);
    return *(uint32_t*)&h;
}
__device__ __forceinline__ uint32_t pack_lo(float x, float y, uint32_t hi) {
    __nv_bfloat162 h = *(__nv_bfloat162*)&hi;
    __nv_bfloat162 l = __floats2bfloat162_rn(x - __bfloat162float(h.x),
                                             y - __bfloat162float(h.y));
    return *(uint32_t*)&l;
}

// ---------------- fp32 -> bf16 hi/lo split ----------------------------------
__global__ __launch_bounds__(256) void split_kernel(
    const float4* __restrict__ src, uint2* __restrict__ hi,
    uint2* __restrict__ lo, int n4)
{
    int i = blockIdx.x * 256 + threadIdx.x;
    if (i >= n4) return;
    float4 v = src[i];
    __nv_bfloat162 h0 = __floats2bfloat162_rn(v.x, v.y);
    __nv_bfloat162 h1 = __floats2bfloat162_rn(v.z, v.w);
    __nv_bfloat162 l0 = __floats2bfloat162_rn(v.x - __bfloat162float(h0.x),
                                              v.y - __bfloat162float(h0.y));
    __nv_bfloat162 l1 = __floats2bfloat162_rn(v.z - __bfloat162float(h1.x),
                                              v.w - __bfloat162float(h1.y));
    uint2 H, L;
    H.x = *(uint32_t*)&h0; H.y = *(uint32_t*)&h1;
    L.x = *(uint32_t*)&l0; L.y = *(uint32_t*)&l1;
    hi[i] = H; lo[i] = L;
}

// ---------------- W[K,N] -> WT hi/lo [N,K] ----------------------------------
__global__ void transpose_split(const float* __restrict__ W,
                                __nv_bfloat16* __restrict__ hiT,
                                __nv_bfloat16* __restrict__ loT, int K, int N)
{
    __shared__ float t[32][33];
    int n0 = blockIdx.x * 32, k0 = blockIdx.y * 32;
    int tx = threadIdx.x, ty = threadIdx.y;
    for (int j = ty; j < 32; j += 8)
        t[j][tx] = W[(size_t)(k0 + j) * N + n0 + tx];
    __syncthreads();
    for (int j = ty; j < 32; j += 8) {
        float x = t[tx][j];
        __nv_bfloat16 h = __float2bfloat16(x);
        __nv_bfloat16 l = __float2bfloat16(x - __bfloat162float(h));
        size_t o = (size_t)(n0 + j) * K + k0 + tx;
        hiT[o] = h; loT[o] = l;
    }
}

// ---------------- mma.sync bf16x3 split GEMM (unchanged from R4) ------------
#define KC      64
#define RSTRIDE 144
#define OFF_AL  18432
#define OFF_BH  36864
#define OFF_BL  (36864 + 36864)
#define STAGE   110592
#define G_SMEM  (2 * STAGE)

__global__ __launch_bounds__(256, 1) void gemm_mma(
    const __nv_bfloat16* __restrict__ Ah, const __nv_bfloat16* __restrict__ Al,
    const __nv_bfloat16* __restrict__ Bh, const __nv_bfloat16* __restrict__ Bl,
    float* __restrict__ C, int M, int N, int K)
{
    extern __shared__ char sm[];
    const uint32_t smb = s2u(sm);
    const int tid  = threadIdx.x;
    const int wid  = tid >> 5, lane = tid & 31;
    const int wm   = wid & 1, wn = wid >> 1;
    const int g    = lane >> 2, tg = lane & 3;
    const int m0   = blockIdx.y * 128, n0 = blockIdx.x * 256;

    float acc[4][8][4];
#pragma unroll
    for (int a = 0; a < 4; a++)
#pragma unroll
        for (int b = 0; b < 8; b++)
#pragma unroll
            for (int c = 0; c < 4; c++) acc[a][b][c] = 0.f;

    const int nchunks = K / KC;

    auto load_chunk = [&](int kc, int st) {
        uint32_t base = smb + st * STAGE;
        int k0 = kc * KC;
#pragma unroll
        for (int i = 0; i < 4; i++) {
            int lin = tid + i * 256;
            int r = lin >> 3, sg = lin & 7;
            uint32_t off = r * RSTRIDE + sg * 16;
            size_t gidx = (size_t)(m0 + r) * K + k0 + sg * 8;
            cpasync16(base + off,          Ah + gidx);
            cpasync16(base + OFF_AL + off, Al + gidx);
        }
#pragma unroll
        for (int i = 0; i < 8; i++) {
            int lin = tid + i * 256;
            int r = lin >> 3, sg = lin & 7;
            uint32_t off = r * RSTRIDE + sg * 16;
            size_t gidx = (size_t)(n0 + r) * K + k0 + sg * 8;
            cpasync16(base + OFF_BH + off, Bh + gidx);
            cpasync16(base + OFF_BL + off, Bl + gidx);
        }
        CP_COMMIT();
    };

    auto compute = [&](int st) {
        const char* base = sm + st * STAGE;
        const char* pa = base + (wm * 64 + g) * RSTRIDE + tg * 4;
        const char* pb = base + OFF_BH + (wn * 64 + g) * RSTRIDE + tg * 4;
#pragma unroll
        for (int ks = 0; ks < 4; ks++) {
            int ko = ks * 32;
            uint32_t ah[4][4], al[4][4];
#pragma unroll
            for (int mt = 0; mt < 4; mt++) {
                const char* p = pa + mt * 16 * RSTRIDE + ko;
                ah[mt][0] = *(const uint32_t*)(p);
                ah[mt][1] = *(const uint32_t*)(p + 8 * RSTRIDE);
                ah[mt][2] = *(const uint32_t*)(p + 16);
                ah[mt][3] = *(const uint32_t*)(p + 8 * RSTRIDE + 16);
                const char* q = p + OFF_AL;
                al[mt][0] = *(const uint32_t*)(q);
                al[mt][1] = *(const uint32_t*)(q + 8 * RSTRIDE);
                al[mt][2] = *(const uint32_t*)(q + 16);
                al[mt][3] = *(const uint32_t*)(q + 8 * RSTRIDE + 16);
            }
#pragma unroll
            for (int ng = 0; ng < 2; ng++) {
                uint32_t bh[4][2], bl[4][2];
#pragma unroll
                for (int nt = 0; nt < 4; nt++) {
                    const char* p = pb + (ng * 4 + nt) * 8 * RSTRIDE + ko;
                    bh[nt][0] = *(const uint32_t*)(p);
                    bh[nt][1] = *(const uint32_t*)(p + 16);
                    const char* q = p + 36864;
                    bl[nt][0] = *(const uint32_t*)(q);
                    bl[nt][1] = *(const uint32_t*)(q + 16);
                }
#pragma unroll
                for (int mt = 0; mt < 4; mt++)
#pragma unroll
                    for (int nt = 0; nt < 4; nt++) {
                        float* d = acc[mt][ng * 4 + nt];
                        mma16816(d, ah[mt], bh[nt]);
                        mma16816(d, ah[mt], bl[nt]);
                        mma16816(d, al[mt], bh[nt]);
                    }
            }
        }
    };

    load_chunk(0, 0);
    for (int kc = 0; kc < nchunks; kc++) {
        int st = kc & 1;
        if (kc + 1 < nchunks) load_chunk(kc + 1, st ^ 1);
        if (kc + 1 < nchunks) { CP_WAIT(1); } else { CP_WAIT(0); }
        __syncthreads();
        compute(st);
        __syncthreads();
    }

#pragma unroll
    for (int mt = 0; mt < 4; mt++)
#pragma unroll
        for (int nt = 0; nt < 8; nt++) {
            int r = m0 + wm * 64 + mt * 16 + g;
            int c = n0 + wn * 64 + nt * 8 + tg * 2;
            float2 v0 = make_float2(acc[mt][nt][0], acc[mt][nt][1]);
            float2 v1 = make_float2(acc[mt][nt][2], acc[mt][nt][3]);
            *(float2*)&C[(size_t)r * N + c]       = v0;
            *(float2*)&C[(size_t)(r + 8) * N + c] = v1;
        }
}

// ---------------- RMSNorm + RoPE -> bf16 hi/lo, V^T -------------------------
__global__ void norm_rope_kernel(
    const float* __restrict__ qp, const float* __restrict__ kp,
    const float* __restrict__ vp, const float* __restrict__ qw,
    const float* __restrict__ kw, const int* __restrict__ pos_ids,
    __nv_bfloat16* __restrict__ Qhh, __nv_bfloat16* __restrict__ Qll,
    __nv_bfloat16* __restrict__ Khh, __nv_bfloat16* __restrict__ Kll,
    __nv_bfloat16* __restrict__ Vth, __nv_bfloat16* __restrict__ Vtl)
{
    const int token = blockIdx.x;
    const int b = token / S_, s = token % S_;
    const int hid = blockIdx.y;
    const int d = threadIdx.x;

    if (hid >= H_ + HKV_) {          // V: hi/lo split + transpose to [d][s]
        int h = hid - H_ - HKV_;
        float x = vp[((size_t)token * HKV_ + h) * HD_ + d];
        __nv_bfloat16 hi = __float2bfloat16(x);
        __nv_bfloat16 lo = __float2bfloat16(x - __bfloat162float(hi));
        size_t o = (((size_t)b * HKV_ + h) * HD_ + d) * S_ + s;
        Vth[o] = hi; Vtl[o] = lo;
        return;
    }
    const bool isq = hid < H_;
    const int h = isq ? hid : hid - H_;
    const int nh = isq ? H_ : HKV_;
    const float* src = isq ? qp : kp;

    float x = src[((size_t)token * nh + h) * HD_ + d];
    float ss = x * x;
#pragma unroll
    for (int o = 16; o > 0; o >>= 1) ss += __shfl_xor_sync(0xffffffffu, ss, o);
    __shared__ float sbuf[4];
    if ((d & 31) == 0) sbuf[d >> 5] = ss;
    __syncthreads();
    float var = (sbuf[0] + sbuf[1] + sbuf[2] + sbuf[3]) * (1.0f / HD_);
    float r = rsqrtf(var + 1e-6f);
    const float* w = isq ? qw : kw;
    float xn = w[d] * (x * r);

    __shared__ float xs[HD_];
    xs[d] = xn;
    __syncthreads();
    float rot = (d < 64) ? -xs[d + 64] : xs[d - 64];

    int p = pos_ids[token];
    float inv = exp2f(-13.287712379549449f * (float)(2 * (d & 63)) * (1.0f / 128.0f));
    float ang = (float)p * inv;
    float cs, sn;
    sincosf(ang, &sn, &cs);
    float out = xn * cs + rot * sn;

    __nv_bfloat16 hi = __float2bfloat16(out);
    __nv_bfloat16 lo = __float2bfloat16(out - __bfloat162float(hi));
    size_t o = (((size_t)b * nh + h) * S_ + s) * HD_ + d;
    if (isq) { Qhh[o] = hi; Qll[o] = lo; }
    else     { Khh[o] = hi; Kll[o] = lo; }
}

// ---------------- mma.sync bf16x3 causal flash attention --------------------
// CTA = 128 q-rows, iterate 64-key blocks. 8 warps x (16 rows x full keys).
#define FQSTR 272
#define FKSTR 272
#define FVSTR 144
#define QBYTES (128 * FQSTR)                 // 34816
#define KSTAGE (64 * FKSTR * 2)              // 34816
#define VSTAGE (128 * FVSTR * 2)             // 36864
#define OFF_Q  0
#define OFF_K  (2 * QBYTES)                  // 69632
#define OFF_V  (OFF_K + 2 * KSTAGE)          // 139264
#define FLASH_SMEM (OFF_V + 2 * VSTAGE)      // 212992

__global__ __launch_bounds__(256, 1) void flash_mma(
    const __nv_bfloat16* __restrict__ Qh, const __nv_bfloat16* __restrict__ Ql,
    const __nv_bfloat16* __restrict__ Kh, const __nv_bfloat16* __restrict__ Kl,
    const __nv_bfloat16* __restrict__ Vth, const __nv_bfloat16* __restrict__ Vtl,
    __nv_bfloat16* __restrict__ Oh, __nv_bfloat16* __restrict__ Ol)
{
    extern __shared__ char sm[];
    const uint32_t smb = s2u(sm);
    const int tid = threadIdx.x, wid = tid >> 5, lane = tid & 31;
    const int g = lane >> 2, tg = lane & 3;
    const int qb = blockIdx.x, bh = blockIdx.y;
    const int b = bh / H_, h = bh % H_;
    const int kvh = h / (H_ / HKV_);
    const int q0 = qb * 128;
    const int nkb = 2 * qb + 2;

    const __nv_bfloat16* Qhg = Qh + (((size_t)b * H_ + h) * S_ + q0) * HD_;
    const __nv_bfloat16* Qlg = Ql + (((size_t)b * H_ + h) * S_ + q0) * HD_;
    const __nv_bfloat16* Khg = Kh + ((size_t)b * HKV_ + kvh) * S_ * HD_;
    const __nv_bfloat16* Klg = Kl + ((size_t)b * HKV_ + kvh) * S_ * HD_;
    const __nv_bfloat16* Vhg = Vth + ((size_t)b * HKV_ + kvh) * (size_t)HD_ * S_;
    const __nv_bfloat16* Vlg = Vtl + ((size_t)b * HKV_ + kvh) * (size_t)HD_ * S_;

    // Q tile (128 x 128 hi+lo)
    for (int i = tid; i < 2048; i += 256) {
        int r = i >> 4, c = i & 15;
        cpasync16(smb + OFF_Q + r * FQSTR + c * 16,          Qhg + (size_t)r * HD_ + c * 8);
        cpasync16(smb + OFF_Q + QBYTES + r * FQSTR + c * 16, Qlg + (size_t)r * HD_ + c * 8);
    }
    CP_COMMIT();

    auto load_kv = [&](int kb, int st) {
        uint32_t kbase = smb + OFF_K + st * KSTAGE;
        const __nv_bfloat16* kh = Khg + (size_t)kb * 64 * HD_;
        const __nv_bfloat16* kl = Klg + (size_t)kb * 64 * HD_;
        for (int i = tid; i < 1024; i += 256) {
            int r = i >> 4, c = i & 15;
            cpasync16(kbase + r * FKSTR + c * 16,         kh + (size_t)r * HD_ + c * 8);
            cpasync16(kbase + 17408 + r * FKSTR + c * 16, kl + (size_t)r * HD_ + c * 8);
        }
        uint32_t vbase = smb + OFF_V + st * VSTAGE;
        const __nv_bfloat16* vh = Vhg + kb * 64;
        const __nv_bfloat16* vl = Vlg + kb * 64;
        for (int i = tid; i < 1024; i += 256) {
            int r = i >> 3, c = i & 7;
            cpasync16(vbase + r * FVSTR + c * 16,         vh + (size_t)r * S_ + c * 8);
            cpasync16(vbase + 18432 + r * FVSTR + c * 16, vl + (size_t)r * S_ + c * 8);
        }
        CP_COMMIT();
    };

    load_kv(0, 0);
    if (nkb > 1) load_kv(1, 1);

    float m0 = -1e30f, m1 = -1e30f, l0 = 0.f, l1 = 0.f;
    float acc[16][4];
#pragma unroll
    for (int i = 0; i < 16; i++)
#pragma unroll
        for (int j = 0; j < 4; j++) acc[i][j] = 0.f;

    const int qi0 = q0 + wid * 16 + g;
    const int qi1 = qi0 + 8;
    const float sc = 0.08838834764831845f;

    for (int kb = 0; kb < nkb; kb++) {
        int st = kb & 1;
        if (kb + 1 < nkb) { CP_WAIT(1); } else { CP_WAIT(0); }
        __syncthreads();

        // ---- scores: warp rows [wid*16, +16), keys [kb*64, +64) ----
        float c[8][4];
#pragma unroll
        for (int i = 0; i < 8; i++)
#pragma unroll
            for (int j = 0; j < 4; j++) c[i][j] = 0.f;

        const char* paq = sm + OFF_Q + (wid * 16 + g) * FQSTR + tg * 4;
        const char* pkb = sm + OFF_K + st * KSTAGE + g * FKSTR + tg * 4;
#pragma unroll
        for (int ks = 0; ks < 8; ks++) {
            int ko = ks * 32;
            uint32_t ah[4], al[4];
            const char* p = paq + ko;
            ah[0] = *(const uint32_t*)(p);
            ah[1] = *(const uint32_t*)(p + 8 * FQSTR);
            ah[2] = *(const uint32_t*)(p + 16);
            ah[3] = *(const uint32_t*)(p + 8 * FQSTR + 16);
            const char* q = p + QBYTES;
            al[0] = *(const uint32_t*)(q);
            al[1] = *(const uint32_t*)(q + 8 * FQSTR);
            al[2] = *(const uint32_t*)(q + 16);
            al[3] = *(const uint32_t*)(q + 8 * FQSTR + 16);
#pragma unroll
            for (int nt = 0; nt < 8; nt++) {
                const char* pk = pkb + nt * 8 * FKSTR + ko;
                uint32_t bh2[2], bl2[2];
                bh2[0] = *(const uint32_t*)(pk);
                bh2[1] = *(const uint32_t*)(pk + 16);
                bl2[0] = *(const uint32_t*)(pk + 17408);
                bl2[1] = *(const uint32_t*)(pk + 17408 + 16);
                mma16816(c[nt], ah, bh2);
                mma16816(c[nt], ah, bl2);
                mma16816(c[nt], al, bh2);
            }
        }

        // ---- scale + causal mask ----
#pragma unroll
        for (int nt = 0; nt < 8; nt++) {
            int k0c = kb * 64 + nt * 8 + tg * 2;
            c[nt][0] = (k0c     <= qi0) ? c[nt][0] * sc : -1e30f;
            c[nt][1] = (k0c + 1 <= qi0) ? c[nt][1] * sc : -1e30f;
            c[nt][2] = (k0c     <= qi1) ? c[nt][2] * sc : -1e30f;
            c[nt][3] = (k0c + 1 <= qi1) ? c[nt][3] * sc : -1e30f;
        }

        // ---- online softmax (rows g, g+8; reduce over 4 tg lanes) ----
        float rm0 = -1e30f, rm1 = -1e30f;
#pragma unroll
        for (int nt = 0; nt < 8; nt++) {
            rm0 = fmaxf(rm0, fmaxf(c[nt][0], c[nt][1]));
            rm1 = fmaxf(rm1, fmaxf(c[nt][2], c[nt][3]));
        }
        rm0 = fmaxf(rm0, __shfl_xor_sync(0xffffffffu, rm0, 1));
        rm0 = fmaxf(rm0, __shfl_xor_sync(0xffffffffu, rm0, 2));
        rm1 = fmaxf(rm1, __shfl_xor_sync(0xffffffffu, rm1, 1));
        rm1 = fmaxf(rm1, __shfl_xor_sync(0xffffffffu, rm1, 2));
        float mn0 = fmaxf(m0, rm0), mn1 = fmaxf(m1, rm1);
        float cr0 = __expf(m0 - mn0), cr1 = __expf(m1 - mn1);
        m0 = mn0; m1 = mn1;
        float rs0 = 0.f, rs1 = 0.f;
#pragma unroll
        for (int nt = 0; nt < 8; nt++) {
            c[nt][0] = __expf(c[nt][0] - mn0);
            c[nt][1] = __expf(c[nt][1] - mn0);
            c[nt][2] = __expf(c[nt][2] - mn1);
            c[nt][3] = __expf(c[nt][3] - mn1);
            rs0 += c[nt][0] + c[nt][1];
            rs1 += c[nt][2] + c[nt][3];
        }
        rs0 += __shfl_xor_sync(0xffffffffu, rs0, 1);
        rs0 += __shfl_xor_sync(0xffffffffu, rs0, 2);
        rs1 += __shfl_xor_sync(0xffffffffu, rs1, 1);
        rs1 += __shfl_xor_sync(0xffffffffu, rs1, 2);
        l0 = l0 * cr0 + rs0;
        l1 = l1 * cr1 + rs1;
#pragma unroll
        for (int nt = 0; nt < 16; nt++) {
            acc[nt][0] *= cr0; acc[nt][1] *= cr0;
            acc[nt][2] *= cr1; acc[nt][3] *= cr1;
        }

        // ---- P hi/lo A-fragments (register-only repack) ----
        uint32_t ph[4][4], pl[4][4];
#pragma unroll
        for (int s = 0; s < 4; s++) {
            ph[s][0] = pack_hi(c[2*s][0],   c[2*s][1]);
            ph[s][1] = pack_hi(c[2*s][2],   c[2*s][3]);
            ph[s][2] = pack_hi(c[2*s+1][0], c[2*s+1][1]);
            ph[s][3] = pack_hi(c[2*s+1][2], c[2*s+1][3]);
            pl[s][0] = pack_lo(c[2*s][0],   c[2*s][1],   ph[s][0]);
            pl[s][1] = pack_lo(c[2*s][2],   c[2*s][3],   ph[s][1]);
            pl[s][2] = pack_lo(c[2*s+1][0], c[2*s+1][1], ph[s][2]);
            pl[s][3] = pack_lo(c[2*s+1][2], c[2*s+1][3], ph[s][3]);
        }

        // ---- PV: acc[16 d-tiles] += P[16x64] @ V[64x128] ----
        const char* pvb = sm + OFF_V + st * VSTAGE + g * FVSTR + tg * 4;
#pragma unroll
        for (int s = 0; s < 4; s++) {
#pragma unroll
            for (int nt = 0; nt < 16; nt++) {
                const char* pv = pvb + nt * 8 * FVSTR + s * 32;
                uint32_t bh2[2], bl2[2];
                bh2[0] = *(const uint32_t*)(pv);
                bh2[1] = *(const uint32_t*)(pv + 16);
                bl2[0] = *(const uint32_t*)(pv + 18432);
                bl2[1] = *(const uint32_t*)(pv + 18432 + 16);
                mma16816(acc[nt], ph[s], bh2);
                mma16816(acc[nt], ph[s], bl2);
                mma16816(acc[nt], pl[s], bh2);
            }
        }

        __syncthreads();                       // stage reuse safety
        if (kb + 2 < nkb) load_kv(kb + 2, st);
    }

    // ---- epilogue: O = acc / l -> bf16 hi/lo [token][h*128+d] ----
    float rl0 = 1.f / l0, rl1 = 1.f / l1;
    int t0 = b * S_ + q0 + wid * 16 + g;
    size_t o0 = (size_t)t0 * (H_ * HD_) + h * HD_;
    size_t o1 = (size_t)(t0 + 8) * (H_ * HD_) + h * HD_;
#pragma unroll
    for (int nt = 0; nt < 16; nt++) {
        int d = nt * 8 + tg * 2;
        float x0 = acc[nt][0] * rl0, x1 = acc[nt][1] * rl0;
        float y0 = acc[nt][2] * rl1, y1 = acc[nt][3] * rl1;
        uint32_t h0 = pack_hi(x0, x1);
        uint32_t l0w = pack_lo(x0, x1, h0);
        uint32_t h1 = pack_hi(y0, y1);
        uint32_t l1w = pack_lo(y0, y1, h1);
        *(uint32_t*)(Oh + o0 + d) = h0;
        *(uint32_t*)(Ol + o0 + d) = l0w;
        *(uint32_t*)(Oh + o1 + d) = h1;
        *(uint32_t*)(Ol + o1 + d) = l1w;
    }
}

// ---------------------------------------------------------------------------
extern "C" void kernel_launch(void* const* d_in, const int* in_sizes, int n_in,
                              void* d_out, int out_size)
{
    const float* hidden = (const float*)d_in[0];
    const float* wq     = (const float*)d_in[1];
    const float* wk     = (const float*)d_in[2];
    const float* wv     = (const float*)d_in[3];
    const float* wo     = (const float*)d_in[4];
    const float* qw     = (const float*)d_in[5];
    const float* kw     = (const float*)d_in[6];
    const int*   pos    = (const int*)d_in[7];
    float* out = (float*)d_out;

    float *qproj, *kproj, *vproj;
    cudaGetSymbolAddress((void**)&qproj, g_qproj);
    cudaGetSymbolAddress((void**)&kproj, g_kproj);
    cudaGetSymbolAddress((void**)&vproj, g_vproj);

    __nv_bfloat16 *hh, *hl, *wqh, *wql, *wkh, *wkl, *wvh, *wvl, *woh, *wol, *ath, *atl;
    __nv_bfloat16 *qh, *ql, *kh, *kl, *vth, *vtl;
    cudaGetSymbolAddress((void**)&hh,  g_hid_hi);
    cudaGetSymbolAddress((void**)&hl,  g_hid_lo);
    cudaGetSymbolAddress((void**)&wqh, g_wqT_hi);
    cudaGetSymbolAddress((void**)&wql, g_wqT_lo);
    cudaGetSymbolAddress((void**)&wkh, g_wkT_hi);
    cudaGetSymbolAddress((void**)&wkl, g_wkT_lo);
    cudaGetSymbolAddress((void**)&wvh, g_wvT_hi);
    cudaGetSymbolAddress((void**)&wvl, g_wvT_lo);
    cudaGetSymbolAddress((void**)&woh, g_woT_hi);
    cudaGetSymbolAddress((void**)&wol, g_woT_lo);
    cudaGetSymbolAddress((void**)&ath, g_at_hi);
    cudaGetSymbolAddress((void**)&atl, g_at_lo);
    cudaGetSymbolAddress((void**)&qh,  g_qh);
    cudaGetSymbolAddress((void**)&ql,  g_ql);
    cudaGetSymbolAddress((void**)&kh,  g_kh);
    cudaGetSymbolAddress((void**)&kl,  g_kl);
    cudaGetSymbolAddress((void**)&vth, g_vth);
    cudaGetSymbolAddress((void**)&vtl, g_vtl);

    cudaFuncSetAttribute(gemm_mma, cudaFuncAttributeMaxDynamicSharedMemorySize,
                         (int)G_SMEM);
    cudaFuncSetAttribute(flash_mma, cudaFuncAttributeMaxDynamicSharedMemorySize,
                         (int)FLASH_SMEM);

    // split hidden into hi/lo bf16
    int n4 = NT * D_ / 4;
    split_kernel<<<(n4 + 255) / 256, 256>>>((const float4*)hidden, (uint2*)hh, (uint2*)hl, n4);

    // transpose+split weights
    transpose_split<<<dim3((H_*HD_)/32, D_/32), dim3(32, 8)>>>(wq, wqh, wql, D_, H_*HD_);
    transpose_split<<<dim3((HKV_*HD_)/32, D_/32), dim3(32, 8)>>>(wk, wkh, wkl, D_, HKV_*HD_);
    transpose_split<<<dim3((HKV_*HD_)/32, D_/32), dim3(32, 8)>>>(wv, wvh, wvl, D_, HKV_*HD_);
    transpose_split<<<dim3(D_/32, (H_*HD_)/32), dim3(32, 8)>>>(wo, woh, wol, H_*HD_, D_);

    // QKV projections
    gemm_mma<<<dim3((H_*HD_)/256,   NT/128), 256, G_SMEM>>>(hh, hl, wqh, wql, qproj, NT, H_*HD_,   D_);
    gemm_mma<<<dim3((HKV_*HD_)/256, NT/128), 256, G_SMEM>>>(hh, hl, wkh, wkl, kproj, NT, HKV_*HD_, D_);
    gemm_mma<<<dim3((HKV_*HD_)/256, NT/128), 256, G_SMEM>>>(hh, hl, wvh, wvl, vproj, NT, HKV_*HD_, D_);

    // RMSNorm + RoPE -> bf16 hi/lo (Q,K) and V^T hi/lo
    norm_rope_kernel<<<dim3(NT, H_ + 2*HKV_), 128>>>(qproj, kproj, vproj, qw, kw, pos,
                                                     qh, ql, kh, kl, vth, vtl);

    // tensor-core causal flash attention -> attention out bf16 hi/lo
    flash_mma<<<dim3(S_/128, B_*H_), 256, FLASH_SMEM>>>(qh, ql, kh, kl, vth, vtl, ath, atl);

    // output projection
    gemm_mma<<<dim3(D_/256, NT/128), 256, G_SMEM>>>(ath, atl, woh, wol, out, NT, D_, D_);
}

// round 6
// speedup vs baseline: 5.4793x; 1.1418x over previous
#include <cuda_runtime.h>
#include <cuda_bf16.h>
#include <math.h>
#include <stdint.h>

#define B_   2
#define S_   2048
#define D_   2048
#define H_   16
#define HKV_ 4
#define HD_  128
#define NT   (B_ * S_)
#define NQKV 3072

// ---------------- scratch ---------------------------------------------------
__device__ float g_qkvproj[NT * NQKV];

__device__ __nv_bfloat16 g_hid_hi[NT * D_];
__device__ __nv_bfloat16 g_hid_lo[NT * D_];
__device__ __nv_bfloat16 g_wqkvT_hi[NQKV * D_];
__device__ __nv_bfloat16 g_wqkvT_lo[NQKV * D_];
__device__ __nv_bfloat16 g_woT_hi[(H_*HD_) * D_];
__device__ __nv_bfloat16 g_woT_lo[(H_*HD_) * D_];
__device__ __nv_bfloat16 g_at_hi[NT * (H_*HD_)];
__device__ __nv_bfloat16 g_at_lo[NT * (H_*HD_)];

__device__ __nv_bfloat16 g_qh[NT * H_ * HD_];
__device__ __nv_bfloat16 g_ql[NT * H_ * HD_];
__device__ __nv_bfloat16 g_kh[NT * HKV_ * HD_];
__device__ __nv_bfloat16 g_kl[NT * HKV_ * HD_];
__device__ __nv_bfloat16 g_vth[NT * HKV_ * HD_];
__device__ __nv_bfloat16 g_vtl[NT * HKV_ * HD_];

// ---------------- helpers ---------------------------------------------------
__device__ __forceinline__ uint32_t s2u(const void* p) {
    return (uint32_t)__cvta_generic_to_shared(p);
}
__device__ __forceinline__ void cpasync16(uint32_t dst, const void* src) {
    asm volatile("cp.async.cg.shared.global [%0], [%1], 16;" :: "r"(dst), "l"(src));
}
#define CP_COMMIT() asm volatile("cp.async.commit_group;")
#define CP_WAIT(N)  asm volatile("cp.async.wait_group %0;" :: "n"(N))

__device__ __forceinline__ void mma16816(float* d, const uint32_t* a, const uint32_t* b) {
    asm volatile(
        "mma.sync.aligned.m16n8k16.row.col.f32.bf16.bf16.f32 "
        "{%0,%1,%2,%3}, {%4,%5,%6,%7}, {%8,%9}, {%0,%1,%2,%3};"
        : "+f"(d[0]), "+f"(d[1]), "+f"(d[2]), "+f"(d[3])
        : "r"(a[0]), "r"(a[1]), "r"(a[2]), "r"(a[3]), "r"(b[0]), "r"(b[1]));
}
__device__ __forceinline__ void ldm_x4(uint32_t* r, uint32_t addr) {
    asm volatile("ldmatrix.sync.aligned.m8n8.x4.shared.b16 {%0,%1,%2,%3}, [%4];"
                 : "=r"(r[0]), "=r"(r[1]), "=r"(r[2]), "=r"(r[3]) : "r"(addr));
}
__device__ __forceinline__ uint32_t pack_hi(float x, float y) {
    __nv_bfloat162 h = __floats2bfloat162_rn(x, y);
    return *(uint32_t*)&h;
}
__device__ __forceinline__ uint32_t pack_lo(float x, float y, uint32_t hi) {
    __nv_bfloat162 h = *(__nv_bfloat162*)&hi;
    __nv_bfloat162 l = __floats2bfloat162_rn(x - __bfloat162float(h.x),
                                             y - __bfloat162float(h.y));
    return *(uint32_t*)&l;
}

// ---------------- fp32 -> bf16 hi/lo split ----------------------------------
__global__ __launch_bounds__(256) void split_kernel(
    const float4* __restrict__ src, uint2* __restrict__ hi,
    uint2* __restrict__ lo, int n4)
{
    int i = blockIdx.x * 256 + threadIdx.x;
    if (i >= n4) return;
    float4 v = src[i];
    __nv_bfloat162 h0 = __floats2bfloat162_rn(v.x, v.y);
    __nv_bfloat162 h1 = __floats2bfloat162_rn(v.z, v.w);
    __nv_bfloat162 l0 = __floats2bfloat162_rn(v.x - __bfloat162float(h0.x),
                                              v.y - __bfloat162float(h0.y));
    __nv_bfloat162 l1 = __floats2bfloat162_rn(v.z - __bfloat162float(h1.x),
                                              v.w - __bfloat162float(h1.y));
    uint2 H, L;
    H.x = *(uint32_t*)&h0; H.y = *(uint32_t*)&h1;
    L.x = *(uint32_t*)&l0; L.y = *(uint32_t*)&l1;
    hi[i] = H; lo[i] = L;
}

// ---------------- W[K,N] -> WT hi/lo [N,K] ----------------------------------
__global__ void transpose_split(const float* __restrict__ W,
                                __nv_bfloat16* __restrict__ hiT,
                                __nv_bfloat16* __restrict__ loT, int K, int N)
{
    __shared__ float t[32][33];
    int n0 = blockIdx.x * 32, k0 = blockIdx.y * 32;
    int tx = threadIdx.x, ty = threadIdx.y;
    for (int j = ty; j < 32; j += 8)
        t[j][tx] = W[(size_t)(k0 + j) * N + n0 + tx];
    __syncthreads();
    for (int j = ty; j < 32; j += 8) {
        float x = t[tx][j];
        __nv_bfloat16 h = __float2bfloat16(x);
        __nv_bfloat16 l = __float2bfloat16(x - __bfloat162float(h));
        size_t o = (size_t)(n0 + j) * K + k0 + tx;
        hiT[o] = h; loT[o] = l;
    }
}

// ---------------- mma.sync bf16x3 split GEMM (ldmatrix) ---------------------
#define KC      64
#define RSTRIDE 144
#define OFF_AL  18432
#define OFF_BH  36864
#define OFF_BL  (36864 + 36864)
#define STAGE   110592
#define G_SMEM  (2 * STAGE)

__global__ __launch_bounds__(256, 1) void gemm_mma(
    const __nv_bfloat16* __restrict__ Ah, const __nv_bfloat16* __restrict__ Al,
    const __nv_bfloat16* __restrict__ Bh, const __nv_bfloat16* __restrict__ Bl,
    float* __restrict__ C, int M, int N, int K)
{
    extern __shared__ char sm[];
    const uint32_t smb = s2u(sm);
    const int tid  = threadIdx.x;
    const int wid  = tid >> 5, lane = tid & 31;
    const int wm   = wid & 1, wn = wid >> 1;
    const int g    = lane >> 2, tg = lane & 3;
    const int lm   = lane >> 3, lr = lane & 7;   // ldmatrix lane split
    const int m0   = blockIdx.y * 128, n0 = blockIdx.x * 256;

    float acc[4][8][4];
#pragma unroll
    for (int a = 0; a < 4; a++)
#pragma unroll
        for (int b = 0; b < 8; b++)
#pragma unroll
            for (int c = 0; c < 4; c++) acc[a][b][c] = 0.f;

    const int nchunks = K / KC;

    auto load_chunk = [&](int kc, int st) {
        uint32_t base = smb + st * STAGE;
        int k0 = kc * KC;
#pragma unroll
        for (int i = 0; i < 4; i++) {
            int lin = tid + i * 256;
            int r = lin >> 3, sg = lin & 7;
            uint32_t off = r * RSTRIDE + sg * 16;
            size_t gidx = (size_t)(m0 + r) * K + k0 + sg * 8;
            cpasync16(base + off,          Ah + gidx);
            cpasync16(base + OFF_AL + off, Al + gidx);
        }
#pragma unroll
        for (int i = 0; i < 8; i++) {
            int lin = tid + i * 256;
            int r = lin >> 3, sg = lin & 7;
            uint32_t off = r * RSTRIDE + sg * 16;
            size_t gidx = (size_t)(n0 + r) * K + k0 + sg * 8;
            cpasync16(base + OFF_BH + off, Bh + gidx);
            cpasync16(base + OFF_BL + off, Bl + gidx);
        }
        CP_COMMIT();
    };

    auto compute = [&](int st) {
        uint32_t base = smb + st * STAGE;
        // A lane addr: matrices [rows0-7,k0][rows8-15,k0][rows0-7,k8][rows8-15,k8]
        uint32_t aaddr = base + (wm * 64 + (lm & 1) * 8 + lr) * RSTRIDE + (lm >> 1) * 16;
        // B lane addr: matrices [n0-7,k0][n0-7,k8][n8-15,k0][n8-15,k8]
        uint32_t baddr = base + OFF_BH + (wn * 64 + (lm >> 1) * 8 + lr) * RSTRIDE + (lm & 1) * 16;
#pragma unroll
        for (int ks = 0; ks < 4; ks++) {
            int ko = ks * 32;
            uint32_t ah[4][4], al[4][4];
#pragma unroll
            for (int mt = 0; mt < 4; mt++) {
                ldm_x4(ah[mt], aaddr + mt * 16 * RSTRIDE + ko);
                ldm_x4(al[mt], aaddr + OFF_AL + mt * 16 * RSTRIDE + ko);
            }
#pragma unroll
            for (int p = 0; p < 4; p++) {
                uint32_t bh[4], bl[4];
                ldm_x4(bh, baddr + p * 16 * RSTRIDE + ko);
                ldm_x4(bl, baddr + 36864 + p * 16 * RSTRIDE + ko);
#pragma unroll
                for (int mt = 0; mt < 4; mt++) {
                    float* d0 = acc[mt][2 * p];
                    float* d1 = acc[mt][2 * p + 1];
                    mma16816(d0, ah[mt], bh);     mma16816(d0, ah[mt], bl);
                    mma16816(d0, al[mt], bh);
                    mma16816(d1, ah[mt], bh + 2); mma16816(d1, ah[mt], bl + 2);
                    mma16816(d1, al[mt], bh + 2);
                }
            }
        }
    };

    load_chunk(0, 0);
    for (int kc = 0; kc < nchunks; kc++) {
        int st = kc & 1;
        if (kc + 1 < nchunks) load_chunk(kc + 1, st ^ 1);
        if (kc + 1 < nchunks) { CP_WAIT(1); } else { CP_WAIT(0); }
        __syncthreads();
        compute(st);
        __syncthreads();
    }

#pragma unroll
    for (int mt = 0; mt < 4; mt++)
#pragma unroll
        for (int nt = 0; nt < 8; nt++) {
            int r = m0 + wm * 64 + mt * 16 + g;
            int c = n0 + wn * 64 + nt * 8 + tg * 2;
            float2 v0 = make_float2(acc[mt][nt][0], acc[mt][nt][1]);
            float2 v1 = make_float2(acc[mt][nt][2], acc[mt][nt][3]);
            *(float2*)&C[(size_t)r * N + c]       = v0;
            *(float2*)&C[(size_t)(r + 8) * N + c] = v1;
        }
}

// ---------------- RMSNorm + RoPE -> bf16 hi/lo, V^T -------------------------
__global__ void norm_rope_kernel(
    const float* __restrict__ qkv, const float* __restrict__ qw,
    const float* __restrict__ kw, const int* __restrict__ pos_ids,
    __nv_bfloat16* __restrict__ Qhh, __nv_bfloat16* __restrict__ Qll,
    __nv_bfloat16* __restrict__ Khh, __nv_bfloat16* __restrict__ Kll,
    __nv_bfloat16* __restrict__ Vth, __nv_bfloat16* __restrict__ Vtl)
{
    const int token = blockIdx.x;
    const int b = token / S_, s = token % S_;
    const int hid = blockIdx.y;
    const int d = threadIdx.x;

    if (hid >= H_ + HKV_) {
        int h = hid - H_ - HKV_;
        float x = qkv[(size_t)token * NQKV + 2560 + h * HD_ + d];
        __nv_bfloat16 hi = __float2bfloat16(x);
        __nv_bfloat16 lo = __float2bfloat16(x - __bfloat162float(hi));
        size_t o = (((size_t)b * HKV_ + h) * HD_ + d) * S_ + s;
        Vth[o] = hi; Vtl[o] = lo;
        return;
    }
    const bool isq = hid < H_;
    const int h = isq ? hid : hid - H_;
    const int nh = isq ? H_ : HKV_;
    const int coff = isq ? h * HD_ : 2048 + h * HD_;

    float x = qkv[(size_t)token * NQKV + coff + d];
    float ss = x * x;
#pragma unroll
    for (int o = 16; o > 0; o >>= 1) ss += __shfl_xor_sync(0xffffffffu, ss, o);
    __shared__ float sbuf[4];
    if ((d & 31) == 0) sbuf[d >> 5] = ss;
    __syncthreads();
    float var = (sbuf[0] + sbuf[1] + sbuf[2] + sbuf[3]) * (1.0f / HD_);
    float r = rsqrtf(var + 1e-6f);
    const float* w = isq ? qw : kw;
    float xn = w[d] * (x * r);

    __shared__ float xs[HD_];
    xs[d] = xn;
    __syncthreads();
    float rot = (d < 64) ? -xs[d + 64] : xs[d - 64];

    int p = pos_ids[token];
    float inv = exp2f(-13.287712379549449f * (float)(2 * (d & 63)) * (1.0f / 128.0f));
    float ang = (float)p * inv;
    float cs, sn;
    sincosf(ang, &sn, &cs);
    float out = xn * cs + rot * sn;

    __nv_bfloat16 hi = __float2bfloat16(out);
    __nv_bfloat16 lo = __float2bfloat16(out - __bfloat162float(hi));
    size_t o = (((size_t)b * nh + h) * S_ + s) * HD_ + d;
    if (isq) { Qhh[o] = hi; Qll[o] = lo; }
    else     { Khh[o] = hi; Kll[o] = lo; }
}

// ---------------- mma.sync bf16x3 causal flash attention (ldmatrix) ---------
#define FQSTR 272
#define FKSTR 272
#define FVSTR 144
#define QBYTES (128 * FQSTR)
#define KSTAGE (64 * FKSTR * 2)
#define VSTAGE (128 * FVSTR * 2)
#define OFF_Q  0
#define OFF_K  (2 * QBYTES)
#define OFF_V  (OFF_K + 2 * KSTAGE)
#define FLASH_SMEM (OFF_V + 2 * VSTAGE)

__global__ __launch_bounds__(256, 1) void flash_mma(
    const __nv_bfloat16* __restrict__ Qh, const __nv_bfloat16* __restrict__ Ql,
    const __nv_bfloat16* __restrict__ Kh, const __nv_bfloat16* __restrict__ Kl,
    const __nv_bfloat16* __restrict__ Vth, const __nv_bfloat16* __restrict__ Vtl,
    __nv_bfloat16* __restrict__ Oh, __nv_bfloat16* __restrict__ Ol)
{
    extern __shared__ char sm[];
    const uint32_t smb = s2u(sm);
    const int tid = threadIdx.x, wid = tid >> 5, lane = tid & 31;
    const int g = lane >> 2, tg = lane & 3;
    const int lm = lane >> 3, lr = lane & 7;
    const int qb = blockIdx.x, bh = blockIdx.y;
    const int b = bh / H_, h = bh % H_;
    const int kvh = h / (H_ / HKV_);
    const int q0 = qb * 128;
    const int nkb = 2 * qb + 2;

    const __nv_bfloat16* Qhg = Qh + (((size_t)b * H_ + h) * S_ + q0) * HD_;
    const __nv_bfloat16* Qlg = Ql + (((size_t)b * H_ + h) * S_ + q0) * HD_;
    const __nv_bfloat16* Khg = Kh + ((size_t)b * HKV_ + kvh) * S_ * HD_;
    const __nv_bfloat16* Klg = Kl + ((size_t)b * HKV_ + kvh) * S_ * HD_;
    const __nv_bfloat16* Vhg = Vth + ((size_t)b * HKV_ + kvh) * (size_t)HD_ * S_;
    const __nv_bfloat16* Vlg = Vtl + ((size_t)b * HKV_ + kvh) * (size_t)HD_ * S_;

    for (int i = tid; i < 2048; i += 256) {
        int r = i >> 4, c = i & 15;
        cpasync16(smb + OFF_Q + r * FQSTR + c * 16,          Qhg + (size_t)r * HD_ + c * 8);
        cpasync16(smb + OFF_Q + QBYTES + r * FQSTR + c * 16, Qlg + (size_t)r * HD_ + c * 8);
    }
    CP_COMMIT();

    auto load_kv = [&](int kb, int st) {
        uint32_t kbase = smb + OFF_K + st * KSTAGE;
        const __nv_bfloat16* kh = Khg + (size_t)kb * 64 * HD_;
        const __nv_bfloat16* kl = Klg + (size_t)kb * 64 * HD_;
        for (int i = tid; i < 1024; i += 256) {
            int r = i >> 4, c = i & 15;
            cpasync16(kbase + r * FKSTR + c * 16,         kh + (size_t)r * HD_ + c * 8);
            cpasync16(kbase + 17408 + r * FKSTR + c * 16, kl + (size_t)r * HD_ + c * 8);
        }
        uint32_t vbase = smb + OFF_V + st * VSTAGE;
        const __nv_bfloat16* vh = Vhg + kb * 64;
        const __nv_bfloat16* vl = Vlg + kb * 64;
        for (int i = tid; i < 1024; i += 256) {
            int r = i >> 3, c = i & 7;
            cpasync16(vbase + r * FVSTR + c * 16,         vh + (size_t)r * S_ + c * 8);
            cpasync16(vbase + 18432 + r * FVSTR + c * 16, vl + (size_t)r * S_ + c * 8);
        }
        CP_COMMIT();
    };

    load_kv(0, 0);
    if (nkb > 1) load_kv(1, 1);

    float m0 = -1e30f, m1 = -1e30f, l0 = 0.f, l1 = 0.f;
    float acc[16][4];
#pragma unroll
    for (int i = 0; i < 16; i++)
#pragma unroll
        for (int j = 0; j < 4; j++) acc[i][j] = 0.f;

    const int qi0 = q0 + wid * 16 + g;
    const int qi1 = qi0 + 8;
    const float sc = 0.08838834764831845f;

    // ldmatrix lane addresses
    const uint32_t aaddr = smb + OFF_Q + (wid * 16 + (lm & 1) * 8 + lr) * FQSTR + (lm >> 1) * 16;
    const uint32_t brow_off = ((lm >> 1) * 8 + lr);
    const uint32_t bcol_off = (lm & 1) * 16;

    for (int kb = 0; kb < nkb; kb++) {
        int st = kb & 1;
        if (kb + 1 < nkb) { CP_WAIT(1); } else { CP_WAIT(0); }
        __syncthreads();

        float c[8][4];
#pragma unroll
        for (int i = 0; i < 8; i++)
#pragma unroll
            for (int j = 0; j < 4; j++) c[i][j] = 0.f;

        uint32_t kaddr = smb + OFF_K + st * KSTAGE + brow_off * FKSTR + bcol_off;
#pragma unroll
        for (int ks = 0; ks < 8; ks++) {
            int ko = ks * 32;
            uint32_t ah[4], al[4];
            ldm_x4(ah, aaddr + ko);
            ldm_x4(al, aaddr + QBYTES + ko);
#pragma unroll
            for (int p = 0; p < 4; p++) {
                uint32_t bh2[4], bl2[4];
                ldm_x4(bh2, kaddr + p * 16 * FKSTR + ko);
                ldm_x4(bl2, kaddr + 17408 + p * 16 * FKSTR + ko);
                float* d0 = c[2 * p];
                float* d1 = c[2 * p + 1];
                mma16816(d0, ah, bh2);     mma16816(d0, ah, bl2);
                mma16816(d0, al, bh2);
                mma16816(d1, ah, bh2 + 2); mma16816(d1, ah, bl2 + 2);
                mma16816(d1, al, bh2 + 2);
            }
        }

#pragma unroll
        for (int nt = 0; nt < 8; nt++) {
            int k0c = kb * 64 + nt * 8 + tg * 2;
            c[nt][0] = (k0c     <= qi0) ? c[nt][0] * sc : -1e30f;
            c[nt][1] = (k0c + 1 <= qi0) ? c[nt][1] * sc : -1e30f;
            c[nt][2] = (k0c     <= qi1) ? c[nt][2] * sc : -1e30f;
            c[nt][3] = (k0c + 1 <= qi1) ? c[nt][3] * sc : -1e30f;
        }

        float rm0 = -1e30f, rm1 = -1e30f;
#pragma unroll
        for (int nt = 0; nt < 8; nt++) {
            rm0 = fmaxf(rm0, fmaxf(c[nt][0], c[nt][1]));
            rm1 = fmaxf(rm1, fmaxf(c[nt][2], c[nt][3]));
        }
        rm0 = fmaxf(rm0, __shfl_xor_sync(0xffffffffu, rm0, 1));
        rm0 = fmaxf(rm0, __shfl_xor_sync(0xffffffffu, rm0, 2));
        rm1 = fmaxf(rm1, __shfl_xor_sync(0xffffffffu, rm1, 1));
        rm1 = fmaxf(rm1, __shfl_xor_sync(0xffffffffu, rm1, 2));
        float mn0 = fmaxf(m0, rm0), mn1 = fmaxf(m1, rm1);
        float cr0 = __expf(m0 - mn0), cr1 = __expf(m1 - mn1);
        m0 = mn0; m1 = mn1;
        float rs0 = 0.f, rs1 = 0.f;
#pragma unroll
        for (int nt = 0; nt < 8; nt++) {
            c[nt][0] = __expf(c[nt][0] - mn0);
            c[nt][1] = __expf(c[nt][1] - mn0);
            c[nt][2] = __expf(c[nt][2] - mn1);
            c[nt][3] = __expf(c[nt][3] - mn1);
            rs0 += c[nt][0] + c[nt][1];
            rs1 += c[nt][2] + c[nt][3];
        }
        rs0 += __shfl_xor_sync(0xffffffffu, rs0, 1);
        rs0 += __shfl_xor_sync(0xffffffffu, rs0, 2);
        rs1 += __shfl_xor_sync(0xffffffffu, rs1, 1);
        rs1 += __shfl_xor_sync(0xffffffffu, rs1, 2);
        l0 = l0 * cr0 + rs0;
        l1 = l1 * cr1 + rs1;
#pragma unroll
        for (int nt = 0; nt < 16; nt++) {
            acc[nt][0] *= cr0; acc[nt][1] *= cr0;
            acc[nt][2] *= cr1; acc[nt][3] *= cr1;
        }

        uint32_t ph[4][4], pl[4][4];
#pragma unroll
        for (int s = 0; s < 4; s++) {
            ph[s][0] = pack_hi(c[2*s][0],   c[2*s][1]);
            ph[s][1] = pack_hi(c[2*s][2],   c[2*s][3]);
            ph[s][2] = pack_hi(c[2*s+1][0], c[2*s+1][1]);
            ph[s][3] = pack_hi(c[2*s+1][2], c[2*s+1][3]);
            pl[s][0] = pack_lo(c[2*s][0],   c[2*s][1],   ph[s][0]);
            pl[s][1] = pack_lo(c[2*s][2],   c[2*s][3],   ph[s][1]);
            pl[s][2] = pack_lo(c[2*s+1][0], c[2*s+1][1], ph[s][2]);
            pl[s][3] = pack_lo(c[2*s+1][2], c[2*s+1][3], ph[s][3]);
        }

        uint32_t vaddr = smb + OFF_V + st * VSTAGE + brow_off * FVSTR + bcol_off;
#pragma unroll
        for (int s = 0; s < 4; s++) {
#pragma unroll
            for (int p = 0; p < 8; p++) {
                uint32_t bh2[4], bl2[4];
                ldm_x4(bh2, vaddr + p * 16 * FVSTR + s * 32);
                ldm_x4(bl2, vaddr + 18432 + p * 16 * FVSTR + s * 32);
                float* d0 = acc[2 * p];
                float* d1 = acc[2 * p + 1];
                mma16816(d0, ph[s], bh2);     mma16816(d0, ph[s], bl2);
                mma16816(d0, pl[s], bh2);
                mma16816(d1, ph[s], bh2 + 2); mma16816(d1, ph[s], bl2 + 2);
                mma16816(d1, pl[s], bh2 + 2);
            }
        }

        __syncthreads();
        if (kb + 2 < nkb) load_kv(kb + 2, st);
    }

    float rl0 = 1.f / l0, rl1 = 1.f / l1;
    int t0 = b * S_ + q0 + wid * 16 + g;
    size_t o0 = (size_t)t0 * (H_ * HD_) + h * HD_;
    size_t o1 = (size_t)(t0 + 8) * (H_ * HD_) + h * HD_;
#pragma unroll
    for (int nt = 0; nt < 16; nt++) {
        int d = nt * 8 + tg * 2;
        float x0 = acc[nt][0] * rl0, x1 = acc[nt][1] * rl0;
        float y0 = acc[nt][2] * rl1, y1 = acc[nt][3] * rl1;
        uint32_t h0 = pack_hi(x0, x1);
        uint32_t l0w = pack_lo(x0, x1, h0);
        uint32_t h1 = pack_hi(y0, y1);
        uint32_t l1w = pack_lo(y0, y1, h1);
        *(uint32_t*)(Oh + o0 + d) = h0;
        *(uint32_t*)(Ol + o0 + d) = l0w;
        *(uint32_t*)(Oh + o1 + d) = h1;
        *(uint32_t*)(Ol + o1 + d) = l1w;
    }
}

// ---------------------------------------------------------------------------
extern "C" void kernel_launch(void* const* d_in, const int* in_sizes, int n_in,
                              void* d_out, int out_size)
{
    const float* hidden = (const float*)d_in[0];
    const float* wq     = (const float*)d_in[1];
    const float* wk     = (const float*)d_in[2];
    const float* wv     = (const float*)d_in[3];
    const float* wo     = (const float*)d_in[4];
    const float* qw     = (const float*)d_in[5];
    const float* kw     = (const float*)d_in[6];
    const int*   pos    = (const int*)d_in[7];
    float* out = (float*)d_out;

    float *qkvproj;
    cudaGetSymbolAddress((void**)&qkvproj, g_qkvproj);

    __nv_bfloat16 *hh, *hl, *wqkvh, *wqkvl, *woh, *wol, *ath, *atl;
    __nv_bfloat16 *qh, *ql, *kh, *kl, *vth, *vtl;
    cudaGetSymbolAddress((void**)&hh,    g_hid_hi);
    cudaGetSymbolAddress((void**)&hl,    g_hid_lo);
    cudaGetSymbolAddress((void**)&wqkvh, g_wqkvT_hi);
    cudaGetSymbolAddress((void**)&wqkvl, g_wqkvT_lo);
    cudaGetSymbolAddress((void**)&woh,   g_woT_hi);
    cudaGetSymbolAddress((void**)&wol,   g_woT_lo);
    cudaGetSymbolAddress((void**)&ath,   g_at_hi);
    cudaGetSymbolAddress((void**)&atl,   g_at_lo);
    cudaGetSymbolAddress((void**)&qh,    g_qh);
    cudaGetSymbolAddress((void**)&ql,    g_ql);
    cudaGetSymbolAddress((void**)&kh,    g_kh);
    cudaGetSymbolAddress((void**)&kl,    g_kl);
    cudaGetSymbolAddress((void**)&vth,   g_vth);
    cudaGetSymbolAddress((void**)&vtl,   g_vtl);

    cudaFuncSetAttribute(gemm_mma, cudaFuncAttributeMaxDynamicSharedMemorySize,
                         (int)G_SMEM);
    cudaFuncSetAttribute(flash_mma, cudaFuncAttributeMaxDynamicSharedMemorySize,
                         (int)FLASH_SMEM);

    // split hidden into hi/lo bf16
    int n4 = NT * D_ / 4;
    split_kernel<<<(n4 + 255) / 256, 256>>>((const float4*)hidden, (uint2*)hh, (uint2*)hl, n4);

    // transpose+split weights into concatenated QKV buffer + WO
    transpose_split<<<dim3((H_*HD_)/32, D_/32), dim3(32, 8)>>>(wq, wqkvh, wqkvl, D_, H_*HD_);
    transpose_split<<<dim3((HKV_*HD_)/32, D_/32), dim3(32, 8)>>>(
        wk, wqkvh + (size_t)2048 * D_, wqkvl + (size_t)2048 * D_, D_, HKV_*HD_);
    transpose_split<<<dim3((HKV_*HD_)/32, D_/32), dim3(32, 8)>>>(
        wv, wqkvh + (size_t)2560 * D_, wqkvl + (size_t)2560 * D_, D_, HKV_*HD_);
    transpose_split<<<dim3(D_/32, (H_*HD_)/32), dim3(32, 8)>>>(wo, woh, wol, H_*HD_, D_);

    // fused QKV projection
    gemm_mma<<<dim3(NQKV/256, NT/128), 256, G_SMEM>>>(hh, hl, wqkvh, wqkvl, qkvproj,
                                                      NT, NQKV, D_);

    // RMSNorm + RoPE -> bf16 hi/lo (Q,K) and V^T hi/lo
    norm_rope_kernel<<<dim3(NT, H_ + 2*HKV_), 128>>>(qkvproj, qw, kw, pos,
                                                     qh, ql, kh, kl, vth, vtl);

    // tensor-core causal flash attention -> attention out bf16 hi/lo
    flash_mma<<<dim3(S_/128, B_*H_), 256, FLASH_SMEM>>>(qh, ql, kh, kl, vth, vtl, ath, atl);

    // output projection
    gemm_mma<<<dim3(D_/256, NT/128), 256, G_SMEM>>>(ath, atl, woh, wol, out, NT, D_, D_);
}

// round 7
// speedup vs baseline: 6.7357x; 1.2293x over previous
#include <cuda_runtime.h>
#include <cuda_bf16.h>
#include <cuda_fp16.h>
#include <math.h>
#include <stdint.h>

#define B_   2
#define S_   2048
#define D_   2048
#define H_   16
#define HKV_ 4
#define HD_  128
#define NT   (B_ * S_)
#define NQKV 3072

// ---------------- scratch ---------------------------------------------------
__device__ float g_qkvproj[NT * NQKV];

__device__ __half g_hid_hi[NT * D_];
__device__ __half g_hid_lo[NT * D_];
__device__ __half g_wqkvT[NQKV * D_];
__device__ __half g_woT[(H_*HD_) * D_];
__device__ __half g_at_hi[NT * (H_*HD_)];
__device__ __half g_at_lo[NT * (H_*HD_)];

__device__ __nv_bfloat16 g_qh[NT * H_ * HD_];
__device__ __nv_bfloat16 g_ql[NT * H_ * HD_];
__device__ __nv_bfloat16 g_kh[NT * HKV_ * HD_];
__device__ __nv_bfloat16 g_kl[NT * HKV_ * HD_];
__device__ __nv_bfloat16 g_vth[NT * HKV_ * HD_];
__device__ __nv_bfloat16 g_vtl[NT * HKV_ * HD_];

// ---------------- helpers ---------------------------------------------------
__device__ __forceinline__ uint32_t s2u(const void* p) {
    return (uint32_t)__cvta_generic_to_shared(p);
}
__device__ __forceinline__ void cpasync16(uint32_t dst, const void* src) {
    asm volatile("cp.async.cg.shared.global [%0], [%1], 16;" :: "r"(dst), "l"(src));
}
#define CP_COMMIT() asm volatile("cp.async.commit_group;")
#define CP_WAIT(N)  asm volatile("cp.async.wait_group %0;" :: "n"(N))

__device__ __forceinline__ void mma_bf16(float* d, const uint32_t* a, const uint32_t* b) {
    asm volatile(
        "mma.sync.aligned.m16n8k16.row.col.f32.bf16.bf16.f32 "
        "{%0,%1,%2,%3}, {%4,%5,%6,%7}, {%8,%9}, {%0,%1,%2,%3};"
        : "+f"(d[0]), "+f"(d[1]), "+f"(d[2]), "+f"(d[3])
        : "r"(a[0]), "r"(a[1]), "r"(a[2]), "r"(a[3]), "r"(b[0]), "r"(b[1]));
}
__device__ __forceinline__ void mma_f16(float* d, const uint32_t* a, const uint32_t* b) {
    asm volatile(
        "mma.sync.aligned.m16n8k16.row.col.f32.f16.f16.f32 "
        "{%0,%1,%2,%3}, {%4,%5,%6,%7}, {%8,%9}, {%0,%1,%2,%3};"
        : "+f"(d[0]), "+f"(d[1]), "+f"(d[2]), "+f"(d[3])
        : "r"(a[0]), "r"(a[1]), "r"(a[2]), "r"(a[3]), "r"(b[0]), "r"(b[1]));
}
__device__ __forceinline__ void ldm_x4(uint32_t* r, uint32_t addr) {
    asm volatile("ldmatrix.sync.aligned.m8n8.x4.shared.b16 {%0,%1,%2,%3}, [%4];"
                 : "=r"(r[0]), "=r"(r[1]), "=r"(r[2]), "=r"(r[3]) : "r"(addr));
}
__device__ __forceinline__ uint32_t pack_hi(float x, float y) {
    __nv_bfloat162 h = __floats2bfloat162_rn(x, y);
    return *(uint32_t*)&h;
}
__device__ __forceinline__ uint32_t pack_lo(float x, float y, uint32_t hi) {
    __nv_bfloat162 h = *(__nv_bfloat162*)&hi;
    __nv_bfloat162 l = __floats2bfloat162_rn(x - __bfloat162float(h.x),
                                             y - __bfloat162float(h.y));
    return *(uint32_t*)&l;
}
__device__ __forceinline__ uint32_t packh_hi(float x, float y) {
    __half2 h = __floats2half2_rn(x, y);
    return *(uint32_t*)&h;
}
__device__ __forceinline__ uint32_t packh_lo(float x, float y, uint32_t hi) {
    __half2 h = *(__half2*)&hi;
    __half2 l = __floats2half2_rn(x - __half2float(h.x), y - __half2float(h.y));
    return *(uint32_t*)&l;
}

// ---------------- fp32 -> fp16 hi/lo split ----------------------------------
__global__ __launch_bounds__(256) void split_f16(
    const float4* __restrict__ src, uint2* __restrict__ hi,
    uint2* __restrict__ lo, int n4)
{
    int i = blockIdx.x * 256 + threadIdx.x;
    if (i >= n4) return;
    float4 v = src[i];
    __half2 h0 = __floats2half2_rn(v.x, v.y);
    __half2 h1 = __floats2half2_rn(v.z, v.w);
    __half2 l0 = __floats2half2_rn(v.x - __half2float(h0.x),
                                   v.y - __half2float(h0.y));
    __half2 l1 = __floats2half2_rn(v.z - __half2float(h1.x),
                                   v.w - __half2float(h1.y));
    uint2 H, L;
    H.x = *(uint32_t*)&h0; H.y = *(uint32_t*)&h1;
    L.x = *(uint32_t*)&l0; L.y = *(uint32_t*)&l1;
    hi[i] = H; lo[i] = L;
}

// ---------------- W[K,N] -> WT[N,K] single fp16 -----------------------------
__global__ void transpose_f16(const float* __restrict__ W,
                              __half* __restrict__ T, int K, int N)
{
    __shared__ float t[32][33];
    int n0 = blockIdx.x * 32, k0 = blockIdx.y * 32;
    int tx = threadIdx.x, ty = threadIdx.y;
    for (int j = ty; j < 32; j += 8)
        t[j][tx] = W[(size_t)(k0 + j) * N + n0 + tx];
    __syncthreads();
    for (int j = ty; j < 32; j += 8)
        T[(size_t)(n0 + j) * K + k0 + tx] = __float2half(t[tx][j]);
}

// ---------------- mma.sync fp16 2-term GEMM ---------------------------------
// C[M,N] = (Ah+Al)[M,K] @ B[N,K]^T, A fp16 hi/lo, B single fp16, fp32 accum.
#define KC      64
#define RSTRIDE 144
#define OFF_AL  18432
#define OFF_B   36864
#define STAGE   73728
#define G_SMEM  (2 * STAGE)

__global__ __launch_bounds__(256, 1) void gemm_mma(
    const __half* __restrict__ Ah, const __half* __restrict__ Al,
    const __half* __restrict__ B, float* __restrict__ C, int M, int N, int K)
{
    extern __shared__ char sm[];
    const uint32_t smb = s2u(sm);
    const int tid  = threadIdx.x;
    const int wid  = tid >> 5, lane = tid & 31;
    const int wm   = wid & 1, wn = wid >> 1;
    const int g    = lane >> 2, tg = lane & 3;
    const int lm   = lane >> 3, lr = lane & 7;
    const int m0   = blockIdx.y * 128, n0 = blockIdx.x * 256;

    float acc[4][8][4];
#pragma unroll
    for (int a = 0; a < 4; a++)
#pragma unroll
        for (int b = 0; b < 8; b++)
#pragma unroll
            for (int c = 0; c < 4; c++) acc[a][b][c] = 0.f;

    const int nchunks = K / KC;

    auto load_chunk = [&](int kc, int st) {
        uint32_t base = smb + st * STAGE;
        int k0 = kc * KC;
#pragma unroll
        for (int i = 0; i < 4; i++) {
            int lin = tid + i * 256;
            int r = lin >> 3, sg = lin & 7;
            uint32_t off = r * RSTRIDE + sg * 16;
            size_t gidx = (size_t)(m0 + r) * K + k0 + sg * 8;
            cpasync16(base + off,          Ah + gidx);
            cpasync16(base + OFF_AL + off, Al + gidx);
        }
#pragma unroll
        for (int i = 0; i < 8; i++) {
            int lin = tid + i * 256;
            int r = lin >> 3, sg = lin & 7;
            uint32_t off = r * RSTRIDE + sg * 16;
            size_t gidx = (size_t)(n0 + r) * K + k0 + sg * 8;
            cpasync16(base + OFF_B + off, B + gidx);
        }
        CP_COMMIT();
    };

    auto compute = [&](int st) {
        uint32_t base = smb + st * STAGE;
        uint32_t aaddr = base + (wm * 64 + (lm & 1) * 8 + lr) * RSTRIDE + (lm >> 1) * 16;
        uint32_t baddr = base + OFF_B + (wn * 64 + (lm >> 1) * 8 + lr) * RSTRIDE + (lm & 1) * 16;
#pragma unroll
        for (int ks = 0; ks < 4; ks++) {
            int ko = ks * 32;
            uint32_t ah[4][4], al[4][4];
#pragma unroll
            for (int mt = 0; mt < 4; mt++) {
                ldm_x4(ah[mt], aaddr + mt * 16 * RSTRIDE + ko);
                ldm_x4(al[mt], aaddr + OFF_AL + mt * 16 * RSTRIDE + ko);
            }
#pragma unroll
            for (int p = 0; p < 4; p++) {
                uint32_t bq[4];
                ldm_x4(bq, baddr + p * 16 * RSTRIDE + ko);
#pragma unroll
                for (int mt = 0; mt < 4; mt++) {
                    float* d0 = acc[mt][2 * p];
                    float* d1 = acc[mt][2 * p + 1];
                    mma_f16(d0, ah[mt], bq);
                    mma_f16(d0, al[mt], bq);
                    mma_f16(d1, ah[mt], bq + 2);
                    mma_f16(d1, al[mt], bq + 2);
                }
            }
        }
    };

    load_chunk(0, 0);
    for (int kc = 0; kc < nchunks; kc++) {
        int st = kc & 1;
        if (kc + 1 < nchunks) load_chunk(kc + 1, st ^ 1);
        if (kc + 1 < nchunks) { CP_WAIT(1); } else { CP_WAIT(0); }
        __syncthreads();
        compute(st);
        __syncthreads();
    }

#pragma unroll
    for (int mt = 0; mt < 4; mt++)
#pragma unroll
        for (int nt = 0; nt < 8; nt++) {
            int r = m0 + wm * 64 + mt * 16 + g;
            int c = n0 + wn * 64 + nt * 8 + tg * 2;
            float2 v0 = make_float2(acc[mt][nt][0], acc[mt][nt][1]);
            float2 v1 = make_float2(acc[mt][nt][2], acc[mt][nt][3]);
            *(float2*)&C[(size_t)r * N + c]       = v0;
            *(float2*)&C[(size_t)(r + 8) * N + c] = v1;
        }
}

// ---------------- RMSNorm + RoPE -> bf16 hi/lo, V^T -------------------------
__global__ void norm_rope_kernel(
    const float* __restrict__ qkv, const float* __restrict__ qw,
    const float* __restrict__ kw, const int* __restrict__ pos_ids,
    __nv_bfloat16* __restrict__ Qhh, __nv_bfloat16* __restrict__ Qll,
    __nv_bfloat16* __restrict__ Khh, __nv_bfloat16* __restrict__ Kll,
    __nv_bfloat16* __restrict__ Vth, __nv_bfloat16* __restrict__ Vtl)
{
    const int token = blockIdx.x;
    const int b = token / S_, s = token % S_;
    const int hid = blockIdx.y;
    const int d = threadIdx.x;

    if (hid >= H_ + HKV_) {
        int h = hid - H_ - HKV_;
        float x = qkv[(size_t)token * NQKV + 2560 + h * HD_ + d];
        __nv_bfloat16 hi = __float2bfloat16(x);
        __nv_bfloat16 lo = __float2bfloat16(x - __bfloat162float(hi));
        size_t o = (((size_t)b * HKV_ + h) * HD_ + d) * S_ + s;
        Vth[o] = hi; Vtl[o] = lo;
        return;
    }
    const bool isq = hid < H_;
    const int h = isq ? hid : hid - H_;
    const int nh = isq ? H_ : HKV_;
    const int coff = isq ? h * HD_ : 2048 + h * HD_;

    float x = qkv[(size_t)token * NQKV + coff + d];
    float ss = x * x;
#pragma unroll
    for (int o = 16; o > 0; o >>= 1) ss += __shfl_xor_sync(0xffffffffu, ss, o);
    __shared__ float sbuf[4];
    if ((d & 31) == 0) sbuf[d >> 5] = ss;
    __syncthreads();
    float var = (sbuf[0] + sbuf[1] + sbuf[2] + sbuf[3]) * (1.0f / HD_);
    float r = rsqrtf(var + 1e-6f);
    const float* w = isq ? qw : kw;
    float xn = w[d] * (x * r);

    __shared__ float xs[HD_];
    xs[d] = xn;
    __syncthreads();
    float rot = (d < 64) ? -xs[d + 64] : xs[d - 64];

    int p = pos_ids[token];
    float inv = exp2f(-13.287712379549449f * (float)(2 * (d & 63)) * (1.0f / 128.0f));
    float ang = (float)p * inv;
    float cs, sn;
    sincosf(ang, &sn, &cs);
    float out = xn * cs + rot * sn;

    __nv_bfloat16 hi = __float2bfloat16(out);
    __nv_bfloat16 lo = __float2bfloat16(out - __bfloat162float(hi));
    size_t o = (((size_t)b * nh + h) * S_ + s) * HD_ + d;
    if (isq) { Qhh[o] = hi; Qll[o] = lo; }
    else     { Khh[o] = hi; Kll[o] = lo; }
}

// ---------------- mma.sync bf16x3 causal flash attention (ldmatrix) ---------
#define FQSTR 272
#define FKSTR 272
#define FVSTR 144
#define QBYTES (128 * FQSTR)
#define KSTAGE (64 * FKSTR * 2)
#define VSTAGE (128 * FVSTR * 2)
#define OFF_Q  0
#define OFF_K  (2 * QBYTES)
#define OFF_V  (OFF_K + 2 * KSTAGE)
#define FLASH_SMEM (OFF_V + 2 * VSTAGE)

__global__ __launch_bounds__(256, 1) void flash_mma(
    const __nv_bfloat16* __restrict__ Qh, const __nv_bfloat16* __restrict__ Ql,
    const __nv_bfloat16* __restrict__ Kh, const __nv_bfloat16* __restrict__ Kl,
    const __nv_bfloat16* __restrict__ Vth, const __nv_bfloat16* __restrict__ Vtl,
    __half* __restrict__ Oh, __half* __restrict__ Ol)
{
    extern __shared__ char sm[];
    const uint32_t smb = s2u(sm);
    const int tid = threadIdx.x, wid = tid >> 5, lane = tid & 31;
    const int g = lane >> 2, tg = lane & 3;
    const int lm = lane >> 3, lr = lane & 7;
    const int qb = gridDim.x - 1 - blockIdx.x;   // longest tiles first
    const int bh = blockIdx.y;
    const int b = bh / H_, h = bh % H_;
    const int kvh = h / (H_ / HKV_);
    const int q0 = qb * 128;
    const int nkb = 2 * qb + 2;

    const __nv_bfloat16* Qhg = Qh + (((size_t)b * H_ + h) * S_ + q0) * HD_;
    const __nv_bfloat16* Qlg = Ql + (((size_t)b * H_ + h) * S_ + q0) * HD_;
    const __nv_bfloat16* Khg = Kh + ((size_t)b * HKV_ + kvh) * S_ * HD_;
    const __nv_bfloat16* Klg = Kl + ((size_t)b * HKV_ + kvh) * S_ * HD_;
    const __nv_bfloat16* Vhg = Vth + ((size_t)b * HKV_ + kvh) * (size_t)HD_ * S_;
    const __nv_bfloat16* Vlg = Vtl + ((size_t)b * HKV_ + kvh) * (size_t)HD_ * S_;

    for (int i = tid; i < 2048; i += 256) {
        int r = i >> 4, c = i & 15;
        cpasync16(smb + OFF_Q + r * FQSTR + c * 16,          Qhg + (size_t)r * HD_ + c * 8);
        cpasync16(smb + OFF_Q + QBYTES + r * FQSTR + c * 16, Qlg + (size_t)r * HD_ + c * 8);
    }
    CP_COMMIT();

    auto load_kv = [&](int kb, int st) {
        uint32_t kbase = smb + OFF_K + st * KSTAGE;
        const __nv_bfloat16* kh = Khg + (size_t)kb * 64 * HD_;
        const __nv_bfloat16* kl = Klg + (size_t)kb * 64 * HD_;
        for (int i = tid; i < 1024; i += 256) {
            int r = i >> 4, c = i & 15;
            cpasync16(kbase + r * FKSTR + c * 16,         kh + (size_t)r * HD_ + c * 8);
            cpasync16(kbase + 17408 + r * FKSTR + c * 16, kl + (size_t)r * HD_ + c * 8);
        }
        uint32_t vbase = smb + OFF_V + st * VSTAGE;
        const __nv_bfloat16* vh = Vhg + kb * 64;
        const __nv_bfloat16* vl = Vlg + kb * 64;
        for (int i = tid; i < 1024; i += 256) {
            int r = i >> 3, c = i & 7;
            cpasync16(vbase + r * FVSTR + c * 16,         vh + (size_t)r * S_ + c * 8);
            cpasync16(vbase + 18432 + r * FVSTR + c * 16, vl + (size_t)r * S_ + c * 8);
        }
        CP_COMMIT();
    };

    load_kv(0, 0);
    if (nkb > 1) load_kv(1, 1);

    float m0 = -1e30f, m1 = -1e30f, l0 = 0.f, l1 = 0.f;
    float acc[16][4];
#pragma unroll
    for (int i = 0; i < 16; i++)
#pragma unroll
        for (int j = 0; j < 4; j++) acc[i][j] = 0.f;

    const int qi0 = q0 + wid * 16 + g;
    const int qi1 = qi0 + 8;
    const float sc = 0.08838834764831845f;

    const uint32_t aaddr = smb + OFF_Q + (wid * 16 + (lm & 1) * 8 + lr) * FQSTR + (lm >> 1) * 16;
    const uint32_t brow_off = ((lm >> 1) * 8 + lr);
    const uint32_t bcol_off = (lm & 1) * 16;

    for (int kb = 0; kb < nkb; kb++) {
        int st = kb & 1;
        if (kb + 1 < nkb) { CP_WAIT(1); } else { CP_WAIT(0); }
        __syncthreads();

        float c[8][4];
#pragma unroll
        for (int i = 0; i < 8; i++)
#pragma unroll
            for (int j = 0; j < 4; j++) c[i][j] = 0.f;

        uint32_t kaddr = smb + OFF_K + st * KSTAGE + brow_off * FKSTR + bcol_off;
#pragma unroll
        for (int ks = 0; ks < 8; ks++) {
            int ko = ks * 32;
            uint32_t ah[4], al[4];
            ldm_x4(ah, aaddr + ko);
            ldm_x4(al, aaddr + QBYTES + ko);
#pragma unroll
            for (int p = 0; p < 4; p++) {
                uint32_t bh2[4], bl2[4];
                ldm_x4(bh2, kaddr + p * 16 * FKSTR + ko);
                ldm_x4(bl2, kaddr + 17408 + p * 16 * FKSTR + ko);
                float* d0 = c[2 * p];
                float* d1 = c[2 * p + 1];
                mma_bf16(d0, ah, bh2);     mma_bf16(d0, ah, bl2);
                mma_bf16(d0, al, bh2);
                mma_bf16(d1, ah, bh2 + 2); mma_bf16(d1, ah, bl2 + 2);
                mma_bf16(d1, al, bh2 + 2);
            }
        }

#pragma unroll
        for (int nt = 0; nt < 8; nt++) {
            int k0c = kb * 64 + nt * 8 + tg * 2;
            c[nt][0] = (k0c     <= qi0) ? c[nt][0] * sc : -1e30f;
            c[nt][1] = (k0c + 1 <= qi0) ? c[nt][1] * sc : -1e30f;
            c[nt][2] = (k0c     <= qi1) ? c[nt][2] * sc : -1e30f;
            c[nt][3] = (k0c + 1 <= qi1) ? c[nt][3] * sc : -1e30f;
        }

        float rm0 = -1e30f, rm1 = -1e30f;
#pragma unroll
        for (int nt = 0; nt < 8; nt++) {
            rm0 = fmaxf(rm0, fmaxf(c[nt][0], c[nt][1]));
            rm1 = fmaxf(rm1, fmaxf(c[nt][2], c[nt][3]));
        }
        rm0 = fmaxf(rm0, __shfl_xor_sync(0xffffffffu, rm0, 1));
        rm0 = fmaxf(rm0, __shfl_xor_sync(0xffffffffu, rm0, 2));
        rm1 = fmaxf(rm1, __shfl_xor_sync(0xffffffffu, rm1, 1));
        rm1 = fmaxf(rm1, __shfl_xor_sync(0xffffffffu, rm1, 2));
        float mn0 = fmaxf(m0, rm0), mn1 = fmaxf(m1, rm1);
        float cr0 = __expf(m0 - mn0), cr1 = __expf(m1 - mn1);
        m0 = mn0; m1 = mn1;
        float rs0 = 0.f, rs1 = 0.f;
#pragma unroll
        for (int nt = 0; nt < 8; nt++) {
            c[nt][0] = __expf(c[nt][0] - mn0);
            c[nt][1] = __expf(c[nt][1] - mn0);
            c[nt][2] = __expf(c[nt][2] - mn1);
            c[nt][3] = __expf(c[nt][3] - mn1);
            rs0 += c[nt][0] + c[nt][1];
            rs1 += c[nt][2] + c[nt][3];
        }
        rs0 += __shfl_xor_sync(0xffffffffu, rs0, 1);
        rs0 += __shfl_xor_sync(0xffffffffu, rs0, 2);
        rs1 += __shfl_xor_sync(0xffffffffu, rs1, 1);
        rs1 += __shfl_xor_sync(0xffffffffu, rs1, 2);
        l0 = l0 * cr0 + rs0;
        l1 = l1 * cr1 + rs1;
#pragma unroll
        for (int nt = 0; nt < 16; nt++) {
            acc[nt][0] *= cr0; acc[nt][1] *= cr0;
            acc[nt][2] *= cr1; acc[nt][3] *= cr1;
        }

        uint32_t ph[4][4], pl[4][4];
#pragma unroll
        for (int s = 0; s < 4; s++) {
            ph[s][0] = pack_hi(c[2*s][0],   c[2*s][1]);
            ph[s][1] = pack_hi(c[2*s][2],   c[2*s][3]);
            ph[s][2] = pack_hi(c[2*s+1][0], c[2*s+1][1]);
            ph[s][3] = pack_hi(c[2*s+1][2], c[2*s+1][3]);
            pl[s][0] = pack_lo(c[2*s][0],   c[2*s][1],   ph[s][0]);
            pl[s][1] = pack_lo(c[2*s][2],   c[2*s][3],   ph[s][1]);
            pl[s][2] = pack_lo(c[2*s+1][0], c[2*s+1][1], ph[s][2]);
            pl[s][3] = pack_lo(c[2*s+1][2], c[2*s+1][3], ph[s][3]);
        }

        uint32_t vaddr = smb + OFF_V + st * VSTAGE + brow_off * FVSTR + bcol_off;
#pragma unroll
        for (int s = 0; s < 4; s++) {
#pragma unroll
            for (int p = 0; p < 8; p++) {
                uint32_t bh2[4], bl2[4];
                ldm_x4(bh2, vaddr + p * 16 * FVSTR + s * 32);
                ldm_x4(bl2, vaddr + 18432 + p * 16 * FVSTR + s * 32);
                float* d0 = acc[2 * p];
                float* d1 = acc[2 * p + 1];
                mma_bf16(d0, ph[s], bh2);     mma_bf16(d0, ph[s], bl2);
                mma_bf16(d0, pl[s], bh2);
                mma_bf16(d1, ph[s], bh2 + 2); mma_bf16(d1, ph[s], bl2 + 2);
                mma_bf16(d1, pl[s], bh2 + 2);
            }
        }

        __syncthreads();
        if (kb + 2 < nkb) load_kv(kb + 2, st);
    }

    float rl0 = 1.f / l0, rl1 = 1.f / l1;
    int t0 = b * S_ + q0 + wid * 16 + g;
    size_t o0 = (size_t)t0 * (H_ * HD_) + h * HD_;
    size_t o1 = (size_t)(t0 + 8) * (H_ * HD_) + h * HD_;
#pragma unroll
    for (int nt = 0; nt < 16; nt++) {
        int d = nt * 8 + tg * 2;
        float x0 = acc[nt][0] * rl0, x1 = acc[nt][1] * rl0;
        float y0 = acc[nt][2] * rl1, y1 = acc[nt][3] * rl1;
        uint32_t h0 = packh_hi(x0, x1);
        uint32_t l0w = packh_lo(x0, x1, h0);
        uint32_t h1 = packh_hi(y0, y1);
        uint32_t l1w = packh_lo(y0, y1, h1);
        *(uint32_t*)(Oh + o0 + d) = h0;
        *(uint32_t*)(Ol + o0 + d) = l0w;
        *(uint32_t*)(Oh + o1 + d) = h1;
        *(uint32_t*)(Ol + o1 + d) = l1w;
    }
}

// ---------------------------------------------------------------------------
extern "C" void kernel_launch(void* const* d_in, const int* in_sizes, int n_in,
                              void* d_out, int out_size)
{
    const float* hidden = (const float*)d_in[0];
    const float* wq     = (const float*)d_in[1];
    const float* wk     = (const float*)d_in[2];
    const float* wv     = (const float*)d_in[3];
    const float* wo     = (const float*)d_in[4];
    const float* qw     = (const float*)d_in[5];
    const float* kw     = (const float*)d_in[6];
    const int*   pos    = (const int*)d_in[7];
    float* out = (float*)d_out;

    float *qkvproj;
    cudaGetSymbolAddress((void**)&qkvproj, g_qkvproj);

    __half *hh, *hl, *wqkvT, *woT, *ath, *atl;
    __nv_bfloat16 *qh, *ql, *kh, *kl, *vth, *vtl;
    cudaGetSymbolAddress((void**)&hh,    g_hid_hi);
    cudaGetSymbolAddress((void**)&hl,    g_hid_lo);
    cudaGetSymbolAddress((void**)&wqkvT, g_wqkvT);
    cudaGetSymbolAddress((void**)&woT,   g_woT);
    cudaGetSymbolAddress((void**)&ath,   g_at_hi);
    cudaGetSymbolAddress((void**)&atl,   g_at_lo);
    cudaGetSymbolAddress((void**)&qh,    g_qh);
    cudaGetSymbolAddress((void**)&ql,    g_ql);
    cudaGetSymbolAddress((void**)&kh,    g_kh);
    cudaGetSymbolAddress((void**)&kl,    g_kl);
    cudaGetSymbolAddress((void**)&vth,   g_vth);
    cudaGetSymbolAddress((void**)&vtl,   g_vtl);

    cudaFuncSetAttribute(gemm_mma, cudaFuncAttributeMaxDynamicSharedMemorySize,
                         (int)G_SMEM);
    cudaFuncSetAttribute(flash_mma, cudaFuncAttributeMaxDynamicSharedMemorySize,
                         (int)FLASH_SMEM);

    // split hidden into hi/lo fp16
    int n4 = NT * D_ / 4;
    split_f16<<<(n4 + 255) / 256, 256>>>((const float4*)hidden, (uint2*)hh, (uint2*)hl, n4);

    // transpose weights to single fp16 (concatenated QKV + WO)
    transpose_f16<<<dim3((H_*HD_)/32, D_/32), dim3(32, 8)>>>(wq, wqkvT, D_, H_*HD_);
    transpose_f16<<<dim3((HKV_*HD_)/32, D_/32), dim3(32, 8)>>>(
        wk, wqkvT + (size_t)2048 * D_, D_, HKV_*HD_);
    transpose_f16<<<dim3((HKV_*HD_)/32, D_/32), dim3(32, 8)>>>(
        wv, wqkvT + (size_t)2560 * D_, D_, HKV_*HD_);
    transpose_f16<<<dim3(D_/32, (H_*HD_)/32), dim3(32, 8)>>>(wo, woT, H_*HD_, D_);

    // fused QKV projection (fp16 2-term)
    gemm_mma<<<dim3(NQKV/256, NT/128), 256, G_SMEM>>>(hh, hl, wqkvT, qkvproj,
                                                      NT, NQKV, D_);

    // RMSNorm + RoPE -> bf16 hi/lo (Q,K) and V^T hi/lo
    norm_rope_kernel<<<dim3(NT, H_ + 2*HKV_), 128>>>(qkvproj, qw, kw, pos,
                                                     qh, ql, kh, kl, vth, vtl);

    // tensor-core causal flash attention (bf16 3-term) -> attn fp16 hi/lo
    flash_mma<<<dim3(S_/128, B_*H_), 256, FLASH_SMEM>>>(qh, ql, kh, kl, vth, vtl, ath, atl);

    // output projection (fp16 2-term)
    gemm_mma<<<dim3(D_/256, NT/128), 256, G_SMEM>>>(ath, atl, woT, out, NT, D_, D_);
}

// round 8
// speedup vs baseline: 7.8166x; 1.1605x over previous
#include <cuda_runtime.h>
#include <cuda_bf16.h>
#include <cuda_fp16.h>
#include <math.h>
#include <stdint.h>

#define B_   2
#define S_   2048
#define D_   2048
#define H_   16
#define HKV_ 4
#define HD_  128
#define NT   (B_ * S_)
#define NQKV 3072

// ---------------- scratch ---------------------------------------------------
__device__ float g_qkvproj[NT * NQKV];

__device__ __half g_hid_hi[NT * D_];
__device__ __half g_hid_lo[NT * D_];
__device__ __half g_wqkvT[NQKV * D_];
__device__ __half g_woT[(H_*HD_) * D_];
__device__ __half g_at_hi[NT * (H_*HD_)];
__device__ __half g_at_lo[NT * (H_*HD_)];

__device__ __half g_qh[NT * H_ * HD_];     // Q hi (fp16)
__device__ __half g_ql[NT * H_ * HD_];     // Q lo (fp16)
__device__ __half g_kh[NT * HKV_ * HD_];   // K single fp16
__device__ __half g_vth[NT * HKV_ * HD_];  // V^T single fp16 [b,kvh,d,s]

// ---------------- helpers ---------------------------------------------------
__device__ __forceinline__ uint32_t s2u(const void* p) {
    return (uint32_t)__cvta_generic_to_shared(p);
}
__device__ __forceinline__ void cpasync16(uint32_t dst, const void* src) {
    asm volatile("cp.async.cg.shared.global [%0], [%1], 16;" :: "r"(dst), "l"(src));
}
#define CP_COMMIT() asm volatile("cp.async.commit_group;")
#define CP_WAIT(N)  asm volatile("cp.async.wait_group %0;" :: "n"(N))

__device__ __forceinline__ void mma_f16(float* d, const uint32_t* a, const uint32_t* b) {
    asm volatile(
        "mma.sync.aligned.m16n8k16.row.col.f32.f16.f16.f32 "
        "{%0,%1,%2,%3}, {%4,%5,%6,%7}, {%8,%9}, {%0,%1,%2,%3};"
        : "+f"(d[0]), "+f"(d[1]), "+f"(d[2]), "+f"(d[3])
        : "r"(a[0]), "r"(a[1]), "r"(a[2]), "r"(a[3]), "r"(b[0]), "r"(b[1]));
}
__device__ __forceinline__ void ldm_x4(uint32_t* r, uint32_t addr) {
    asm volatile("ldmatrix.sync.aligned.m8n8.x4.shared.b16 {%0,%1,%2,%3}, [%4];"
                 : "=r"(r[0]), "=r"(r[1]), "=r"(r[2]), "=r"(r[3]) : "r"(addr));
}
__device__ __forceinline__ uint32_t packh_hi(float x, float y) {
    __half2 h = __floats2half2_rn(x, y);
    return *(uint32_t*)&h;
}
__device__ __forceinline__ uint32_t packh_lo(float x, float y, uint32_t hi) {
    __half2 h = *(__half2*)&hi;
    __half2 l = __floats2half2_rn(x - __half2float(h.x), y - __half2float(h.y));
    return *(uint32_t*)&l;
}

// ---------------- fp32 -> fp16 hi/lo split ----------------------------------
__global__ __launch_bounds__(256) void split_f16(
    const float4* __restrict__ src, uint2* __restrict__ hi,
    uint2* __restrict__ lo, int n4)
{
    int i = blockIdx.x * 256 + threadIdx.x;
    if (i >= n4) return;
    float4 v = src[i];
    __half2 h0 = __floats2half2_rn(v.x, v.y);
    __half2 h1 = __floats2half2_rn(v.z, v.w);
    __half2 l0 = __floats2half2_rn(v.x - __half2float(h0.x),
                                   v.y - __half2float(h0.y));
    __half2 l1 = __floats2half2_rn(v.z - __half2float(h1.x),
                                   v.w - __half2float(h1.y));
    uint2 H, L;
    H.x = *(uint32_t*)&h0; H.y = *(uint32_t*)&h1;
    L.x = *(uint32_t*)&l0; L.y = *(uint32_t*)&l1;
    hi[i] = H; lo[i] = L;
}

// ---------------- W[K,N] -> WT[N,K] single fp16 -----------------------------
__global__ void transpose_f16(const float* __restrict__ W,
                              __half* __restrict__ T, int K, int N)
{
    __shared__ float t[32][33];
    int n0 = blockIdx.x * 32, k0 = blockIdx.y * 32;
    int tx = threadIdx.x, ty = threadIdx.y;
    for (int j = ty; j < 32; j += 8)
        t[j][tx] = W[(size_t)(k0 + j) * N + n0 + tx];
    __syncthreads();
    for (int j = ty; j < 32; j += 8)
        T[(size_t)(n0 + j) * K + k0 + tx] = __float2half(t[tx][j]);
}

// ---------------- mma.sync fp16 2-term GEMM ---------------------------------
#define KC      64
#define RSTRIDE 144
#define OFF_AL  18432
#define OFF_B   36864
#define STAGE   73728
#define G_SMEM  (2 * STAGE)

__global__ __launch_bounds__(256, 1) void gemm_mma(
    const __half* __restrict__ Ah, const __half* __restrict__ Al,
    const __half* __restrict__ B, float* __restrict__ C, int M, int N, int K)
{
    extern __shared__ char sm[];
    const uint32_t smb = s2u(sm);
    const int tid  = threadIdx.x;
    const int wid  = tid >> 5, lane = tid & 31;
    const int wm   = wid & 1, wn = wid >> 1;
    const int g    = lane >> 2, tg = lane & 3;
    const int lm   = lane >> 3, lr = lane & 7;
    const int m0   = blockIdx.y * 128, n0 = blockIdx.x * 256;

    float acc[4][8][4];
#pragma unroll
    for (int a = 0; a < 4; a++)
#pragma unroll
        for (int b = 0; b < 8; b++)
#pragma unroll
            for (int c = 0; c < 4; c++) acc[a][b][c] = 0.f;

    const int nchunks = K / KC;

    auto load_chunk = [&](int kc, int st) {
        uint32_t base = smb + st * STAGE;
        int k0 = kc * KC;
#pragma unroll
        for (int i = 0; i < 4; i++) {
            int lin = tid + i * 256;
            int r = lin >> 3, sg = lin & 7;
            uint32_t off = r * RSTRIDE + sg * 16;
            size_t gidx = (size_t)(m0 + r) * K + k0 + sg * 8;
            cpasync16(base + off,          Ah + gidx);
            cpasync16(base + OFF_AL + off, Al + gidx);
        }
#pragma unroll
        for (int i = 0; i < 8; i++) {
            int lin = tid + i * 256;
            int r = lin >> 3, sg = lin & 7;
            uint32_t off = r * RSTRIDE + sg * 16;
            size_t gidx = (size_t)(n0 + r) * K + k0 + sg * 8;
            cpasync16(base + OFF_B + off, B + gidx);
        }
        CP_COMMIT();
    };

    auto compute = [&](int st) {
        uint32_t base = smb + st * STAGE;
        uint32_t aaddr = base + (wm * 64 + (lm & 1) * 8 + lr) * RSTRIDE + (lm >> 1) * 16;
        uint32_t baddr = base + OFF_B + (wn * 64 + (lm >> 1) * 8 + lr) * RSTRIDE + (lm & 1) * 16;
#pragma unroll
        for (int ks = 0; ks < 4; ks++) {
            int ko = ks * 32;
            uint32_t ah[4][4], al[4][4];
#pragma unroll
            for (int mt = 0; mt < 4; mt++) {
                ldm_x4(ah[mt], aaddr + mt * 16 * RSTRIDE + ko);
                ldm_x4(al[mt], aaddr + OFF_AL + mt * 16 * RSTRIDE + ko);
            }
#pragma unroll
            for (int p = 0; p < 4; p++) {
                uint32_t bq[4];
                ldm_x4(bq, baddr + p * 16 * RSTRIDE + ko);
#pragma unroll
                for (int mt = 0; mt < 4; mt++) {
                    float* d0 = acc[mt][2 * p];
                    float* d1 = acc[mt][2 * p + 1];
                    mma_f16(d0, ah[mt], bq);
                    mma_f16(d0, al[mt], bq);
                    mma_f16(d1, ah[mt], bq + 2);
                    mma_f16(d1, al[mt], bq + 2);
                }
            }
        }
    };

    load_chunk(0, 0);
    for (int kc = 0; kc < nchunks; kc++) {
        int st = kc & 1;
        if (kc + 1 < nchunks) load_chunk(kc + 1, st ^ 1);
        if (kc + 1 < nchunks) { CP_WAIT(1); } else { CP_WAIT(0); }
        __syncthreads();
        compute(st);
        __syncthreads();
    }

#pragma unroll
    for (int mt = 0; mt < 4; mt++)
#pragma unroll
        for (int nt = 0; nt < 8; nt++) {
            int r = m0 + wm * 64 + mt * 16 + g;
            int c = n0 + wn * 64 + nt * 8 + tg * 2;
            float2 v0 = make_float2(acc[mt][nt][0], acc[mt][nt][1]);
            float2 v1 = make_float2(acc[mt][nt][2], acc[mt][nt][3]);
            *(float2*)&C[(size_t)r * N + c]       = v0;
            *(float2*)&C[(size_t)(r + 8) * N + c] = v1;
        }
}

// ---------------- RMSNorm + RoPE -> Q fp16 hi/lo, K fp16, V^T fp16 ----------
__global__ void norm_rope_kernel(
    const float* __restrict__ qkv, const float* __restrict__ qw,
    const float* __restrict__ kw, const int* __restrict__ pos_ids,
    __half* __restrict__ Qhh, __half* __restrict__ Qll,
    __half* __restrict__ Khh, __half* __restrict__ Vth)
{
    const int token = blockIdx.x;
    const int b = token / S_, s = token % S_;
    const int hid = blockIdx.y;
    const int d = threadIdx.x;

    if (hid >= H_ + HKV_) {
        int h = hid - H_ - HKV_;
        float x = qkv[(size_t)token * NQKV + 2560 + h * HD_ + d];
        Vth[(((size_t)b * HKV_ + h) * HD_ + d) * S_ + s] = __float2half(x);
        return;
    }
    const bool isq = hid < H_;
    const int h = isq ? hid : hid - H_;
    const int nh = isq ? H_ : HKV_;
    const int coff = isq ? h * HD_ : 2048 + h * HD_;

    float x = qkv[(size_t)token * NQKV + coff + d];
    float ss = x * x;
#pragma unroll
    for (int o = 16; o > 0; o >>= 1) ss += __shfl_xor_sync(0xffffffffu, ss, o);
    __shared__ float sbuf[4];
    if ((d & 31) == 0) sbuf[d >> 5] = ss;
    __syncthreads();
    float var = (sbuf[0] + sbuf[1] + sbuf[2] + sbuf[3]) * (1.0f / HD_);
    float r = rsqrtf(var + 1e-6f);
    const float* w = isq ? qw : kw;
    float xn = w[d] * (x * r);

    __shared__ float xs[HD_];
    xs[d] = xn;
    __syncthreads();
    float rot = (d < 64) ? -xs[d + 64] : xs[d - 64];

    int p = pos_ids[token];
    float inv = exp2f(-13.287712379549449f * (float)(2 * (d & 63)) * (1.0f / 128.0f));
    float ang = (float)p * inv;
    float cs, sn;
    sincosf(ang, &sn, &cs);
    float out = xn * cs + rot * sn;

    size_t o = (((size_t)b * nh + h) * S_ + s) * HD_ + d;
    if (isq) {
        __half hi = __float2half(out);
        Qhh[o] = hi;
        Qll[o] = __float2half(out - __half2float(hi));
    } else {
        Khh[o] = __float2half(out);
    }
}

// ---------------- mma.sync fp16 2-term causal flash attention ---------------
#define FQSTR 272
#define FKSTR 272
#define FVSTR 144
#define QBYTES (128 * FQSTR)                 // 34816 per plane
#define KSTAGE (64 * FKSTR)                  // 17408 (single plane)
#define VSTAGE (128 * FVSTR)                 // 18432 (single plane)
#define OFF_Q  0
#define OFF_K  (2 * QBYTES)                  // 69632
#define OFF_V  (OFF_K + 2 * KSTAGE)          // 104448
#define FLASH_SMEM (OFF_V + 2 * VSTAGE)      // 141312

__global__ __launch_bounds__(256, 1) void flash_mma(
    const __half* __restrict__ Qh, const __half* __restrict__ Ql,
    const __half* __restrict__ Kh, const __half* __restrict__ Vth,
    __half* __restrict__ Oh, __half* __restrict__ Ol)
{
    extern __shared__ char sm[];
    const uint32_t smb = s2u(sm);
    const int tid = threadIdx.x, wid = tid >> 5, lane = tid & 31;
    const int g = lane >> 2, tg = lane & 3;
    const int lm = lane >> 3, lr = lane & 7;
    const int qb = gridDim.x - 1 - blockIdx.x;   // longest tiles first
    const int bh = blockIdx.y;
    const int b = bh / H_, h = bh % H_;
    const int kvh = h / (H_ / HKV_);
    const int q0 = qb * 128;
    const int nkb = 2 * qb + 2;

    const __half* Qhg = Qh + (((size_t)b * H_ + h) * S_ + q0) * HD_;
    const __half* Qlg = Ql + (((size_t)b * H_ + h) * S_ + q0) * HD_;
    const __half* Khg = Kh + ((size_t)b * HKV_ + kvh) * S_ * HD_;
    const __half* Vhg = Vth + ((size_t)b * HKV_ + kvh) * (size_t)HD_ * S_;

    for (int i = tid; i < 2048; i += 256) {
        int r = i >> 4, c = i & 15;
        cpasync16(smb + OFF_Q + r * FQSTR + c * 16,          Qhg + (size_t)r * HD_ + c * 8);
        cpasync16(smb + OFF_Q + QBYTES + r * FQSTR + c * 16, Qlg + (size_t)r * HD_ + c * 8);
    }
    CP_COMMIT();

    auto load_kv = [&](int kb, int st) {
        uint32_t kbase = smb + OFF_K + st * KSTAGE;
        const __half* kh = Khg + (size_t)kb * 64 * HD_;
        for (int i = tid; i < 1024; i += 256) {
            int r = i >> 4, c = i & 15;
            cpasync16(kbase + r * FKSTR + c * 16, kh + (size_t)r * HD_ + c * 8);
        }
        uint32_t vbase = smb + OFF_V + st * VSTAGE;
        const __half* vh = Vhg + kb * 64;
        for (int i = tid; i < 1024; i += 256) {
            int r = i >> 3, c = i & 7;
            cpasync16(vbase + r * FVSTR + c * 16, vh + (size_t)r * S_ + c * 8);
        }
        CP_COMMIT();
    };

    load_kv(0, 0);
    if (nkb > 1) load_kv(1, 1);

    float m0 = -1e30f, m1 = -1e30f, l0 = 0.f, l1 = 0.f;
    float acc[16][4];
#pragma unroll
    for (int i = 0; i < 16; i++)
#pragma unroll
        for (int j = 0; j < 4; j++) acc[i][j] = 0.f;

    const int qi0 = q0 + wid * 16 + g;
    const int qi1 = qi0 + 8;
    const int qimax = q0 + wid * 16 + 15;
    const float sc = 0.08838834764831845f;

    const uint32_t aaddr = smb + OFF_Q + (wid * 16 + (lm & 1) * 8 + lr) * FQSTR + (lm >> 1) * 16;
    const uint32_t brow_off = ((lm >> 1) * 8 + lr);
    const uint32_t bcol_off = (lm & 1) * 16;

    for (int kb = 0; kb < nkb; kb++) {
        int st = kb & 1;
        if (kb + 1 < nkb) { CP_WAIT(1); } else { CP_WAIT(0); }
        __syncthreads();

        if (kb * 64 <= qimax) {        // warp-level skip of fully-masked blocks
            float c[8][4];
#pragma unroll
            for (int i = 0; i < 8; i++)
#pragma unroll
                for (int j = 0; j < 4; j++) c[i][j] = 0.f;

            uint32_t kaddr = smb + OFF_K + st * KSTAGE + brow_off * FKSTR + bcol_off;
#pragma unroll
            for (int ks = 0; ks < 8; ks++) {
                int ko = ks * 32;
                uint32_t ah[4], al[4];
                ldm_x4(ah, aaddr + ko);
                ldm_x4(al, aaddr + QBYTES + ko);
#pragma unroll
                for (int p = 0; p < 4; p++) {
                    uint32_t bq[4];
                    ldm_x4(bq, kaddr + p * 16 * FKSTR + ko);
                    float* d0 = c[2 * p];
                    float* d1 = c[2 * p + 1];
                    mma_f16(d0, ah, bq);
                    mma_f16(d0, al, bq);
                    mma_f16(d1, ah, bq + 2);
                    mma_f16(d1, al, bq + 2);
                }
            }

#pragma unroll
            for (int nt = 0; nt < 8; nt++) {
                int k0c = kb * 64 + nt * 8 + tg * 2;
                c[nt][0] = (k0c     <= qi0) ? c[nt][0] * sc : -1e30f;
                c[nt][1] = (k0c + 1 <= qi0) ? c[nt][1] * sc : -1e30f;
                c[nt][2] = (k0c     <= qi1) ? c[nt][2] * sc : -1e30f;
                c[nt][3] = (k0c + 1 <= qi1) ? c[nt][3] * sc : -1e30f;
            }

            float rm0 = -1e30f, rm1 = -1e30f;
#pragma unroll
            for (int nt = 0; nt < 8; nt++) {
                rm0 = fmaxf(rm0, fmaxf(c[nt][0], c[nt][1]));
                rm1 = fmaxf(rm1, fmaxf(c[nt][2], c[nt][3]));
            }
            rm0 = fmaxf(rm0, __shfl_xor_sync(0xffffffffu, rm0, 1));
            rm0 = fmaxf(rm0, __shfl_xor_sync(0xffffffffu, rm0, 2));
            rm1 = fmaxf(rm1, __shfl_xor_sync(0xffffffffu, rm1, 1));
            rm1 = fmaxf(rm1, __shfl_xor_sync(0xffffffffu, rm1, 2));
            float mn0 = fmaxf(m0, rm0), mn1 = fmaxf(m1, rm1);
            float cr0 = __expf(m0 - mn0), cr1 = __expf(m1 - mn1);
            m0 = mn0; m1 = mn1;
            float rs0 = 0.f, rs1 = 0.f;
#pragma unroll
            for (int nt = 0; nt < 8; nt++) {
                c[nt][0] = __expf(c[nt][0] - mn0);
                c[nt][1] = __expf(c[nt][1] - mn0);
                c[nt][2] = __expf(c[nt][2] - mn1);
                c[nt][3] = __expf(c[nt][3] - mn1);
                rs0 += c[nt][0] + c[nt][1];
                rs1 += c[nt][2] + c[nt][3];
            }
            rs0 += __shfl_xor_sync(0xffffffffu, rs0, 1);
            rs0 += __shfl_xor_sync(0xffffffffu, rs0, 2);
            rs1 += __shfl_xor_sync(0xffffffffu, rs1, 1);
            rs1 += __shfl_xor_sync(0xffffffffu, rs1, 2);
            l0 = l0 * cr0 + rs0;
            l1 = l1 * cr1 + rs1;
#pragma unroll
            for (int nt = 0; nt < 16; nt++) {
                acc[nt][0] *= cr0; acc[nt][1] *= cr0;
                acc[nt][2] *= cr1; acc[nt][3] *= cr1;
            }

            // P fp16 hi/lo A-fragments (register repack)
            uint32_t ph[4][4], pl[4][4];
#pragma unroll
            for (int s = 0; s < 4; s++) {
                ph[s][0] = packh_hi(c[2*s][0],   c[2*s][1]);
                ph[s][1] = packh_hi(c[2*s][2],   c[2*s][3]);
                ph[s][2] = packh_hi(c[2*s+1][0], c[2*s+1][1]);
                ph[s][3] = packh_hi(c[2*s+1][2], c[2*s+1][3]);
                pl[s][0] = packh_lo(c[2*s][0],   c[2*s][1],   ph[s][0]);
                pl[s][1] = packh_lo(c[2*s][2],   c[2*s][3],   ph[s][1]);
                pl[s][2] = packh_lo(c[2*s+1][0], c[2*s+1][1], ph[s][2]);
                pl[s][3] = packh_lo(c[2*s+1][2], c[2*s+1][3], ph[s][3]);
            }

            uint32_t vaddr = smb + OFF_V + st * VSTAGE + brow_off * FVSTR + bcol_off;
#pragma unroll
            for (int s = 0; s < 4; s++) {
#pragma unroll
                for (int p = 0; p < 8; p++) {
                    uint32_t bq[4];
                    ldm_x4(bq, vaddr + p * 16 * FVSTR + s * 32);
                    float* d0 = acc[2 * p];
                    float* d1 = acc[2 * p + 1];
                    mma_f16(d0, ph[s], bq);
                    mma_f16(d0, pl[s], bq);
                    mma_f16(d1, ph[s], bq + 2);
                    mma_f16(d1, pl[s], bq + 2);
                }
            }
        }

        __syncthreads();
        if (kb + 2 < nkb) load_kv(kb + 2, st);
    }

    float rl0 = 1.f / l0, rl1 = 1.f / l1;
    int t0 = b * S_ + q0 + wid * 16 + g;
    size_t o0 = (size_t)t0 * (H_ * HD_) + h * HD_;
    size_t o1 = (size_t)(t0 + 8) * (H_ * HD_) + h * HD_;
#pragma unroll
    for (int nt = 0; nt < 16; nt++) {
        int d = nt * 8 + tg * 2;
        float x0 = acc[nt][0] * rl0, x1 = acc[nt][1] * rl0;
        float y0 = acc[nt][2] * rl1, y1 = acc[nt][3] * rl1;
        uint32_t h0 = packh_hi(x0, x1);
        uint32_t l0w = packh_lo(x0, x1, h0);
        uint32_t h1 = packh_hi(y0, y1);
        uint32_t l1w = packh_lo(y0, y1, h1);
        *(uint32_t*)(Oh + o0 + d) = h0;
        *(uint32_t*)(Ol + o0 + d) = l0w;
        *(uint32_t*)(Oh + o1 + d) = h1;
        *(uint32_t*)(Ol + o1 + d) = l1w;
    }
}

// ---------------------------------------------------------------------------
extern "C" void kernel_launch(void* const* d_in, const int* in_sizes, int n_in,
                              void* d_out, int out_size)
{
    const float* hidden = (const float*)d_in[0];
    const float* wq     = (const float*)d_in[1];
    const float* wk     = (const float*)d_in[2];
    const float* wv     = (const float*)d_in[3];
    const float* wo     = (const float*)d_in[4];
    const float* qw     = (const float*)d_in[5];
    const float* kw     = (const float*)d_in[6];
    const int*   pos    = (const int*)d_in[7];
    float* out = (float*)d_out;

    float *qkvproj;
    cudaGetSymbolAddress((void**)&qkvproj, g_qkvproj);

    __half *hh, *hl, *wqkvT, *woT, *ath, *atl, *qh, *ql, *kh, *vth;
    cudaGetSymbolAddress((void**)&hh,    g_hid_hi);
    cudaGetSymbolAddress((void**)&hl,    g_hid_lo);
    cudaGetSymbolAddress((void**)&wqkvT, g_wqkvT);
    cudaGetSymbolAddress((void**)&woT,   g_woT);
    cudaGetSymbolAddress((void**)&ath,   g_at_hi);
    cudaGetSymbolAddress((void**)&atl,   g_at_lo);
    cudaGetSymbolAddress((void**)&qh,    g_qh);
    cudaGetSymbolAddress((void**)&ql,    g_ql);
    cudaGetSymbolAddress((void**)&kh,    g_kh);
    cudaGetSymbolAddress((void**)&vth,   g_vth);

    cudaFuncSetAttribute(gemm_mma, cudaFuncAttributeMaxDynamicSharedMemorySize,
                         (int)G_SMEM);
    cudaFuncSetAttribute(flash_mma, cudaFuncAttributeMaxDynamicSharedMemorySize,
                         (int)FLASH_SMEM);

    // split hidden into hi/lo fp16
    int n4 = NT * D_ / 4;
    split_f16<<<(n4 + 255) / 256, 256>>>((const float4*)hidden, (uint2*)hh, (uint2*)hl, n4);

    // transpose weights to single fp16 (concatenated QKV + WO)
    transpose_f16<<<dim3((H_*HD_)/32, D_/32), dim3(32, 8)>>>(wq, wqkvT, D_, H_*HD_);
    transpose_f16<<<dim3((HKV_*HD_)/32, D_/32), dim3(32, 8)>>>(
        wk, wqkvT + (size_t)2048 * D_, D_, HKV_*HD_);
    transpose_f16<<<dim3((HKV_*HD_)/32, D_/32), dim3(32, 8)>>>(
        wv, wqkvT + (size_t)2560 * D_, D_, HKV_*HD_);
    transpose_f16<<<dim3(D_/32, (H_*HD_)/32), dim3(32, 8)>>>(wo, woT, H_*HD_, D_);

    // fused QKV projection (fp16 2-term)
    gemm_mma<<<dim3(NQKV/256, NT/128), 256, G_SMEM>>>(hh, hl, wqkvT, qkvproj,
                                                      NT, NQKV, D_);

    // RMSNorm + RoPE -> Q fp16 hi/lo, K fp16, V^T fp16
    norm_rope_kernel<<<dim3(NT, H_ + 2*HKV_), 128>>>(qkvproj, qw, kw, pos,
                                                     qh, ql, kh, vth);

    // tensor-core causal flash attention (fp16 2-term) -> attn fp16 hi/lo
    flash_mma<<<dim3(S_/128, B_*H_), 256, FLASH_SMEM>>>(qh, ql, kh, vth, ath, atl);

    // output projection (fp16 2-term)
    gemm_mma<<<dim3(D_/256, NT/128), 256, G_SMEM>>>(ath, atl, woT, out, NT, D_, D_);
}

// round 9
// speedup vs baseline: 8.5819x; 1.0979x over previous
#include <cuda_runtime.h>
#include <cuda_bf16.h>
#include <cuda_fp16.h>
#include <math.h>
#include <stdint.h>

#define B_   2
#define S_   2048
#define D_   2048
#define H_   16
#define HKV_ 4
#define HD_  128
#define NT   (B_ * S_)
#define NQKV 3072

// ---------------- scratch ---------------------------------------------------
__device__ float g_qkvproj[NT * NQKV];

__device__ __half g_hid_hi[NT * D_];
__device__ __half g_hid_lo[NT * D_];
__device__ __half g_wqkvT[NQKV * D_];
__device__ __half g_woT[(H_*HD_) * D_];
__device__ __half g_at_hi[NT * (H_*HD_)];
__device__ __half g_at_lo[NT * (H_*HD_)];

__device__ __half g_qh[NT * H_ * HD_];     // Q single fp16
__device__ __half g_kh[NT * HKV_ * HD_];   // K single fp16
__device__ __half g_vth[NT * HKV_ * HD_];  // V^T single fp16 [b,kvh,d,s]

// ---------------- helpers ---------------------------------------------------
__device__ __forceinline__ uint32_t s2u(const void* p) {
    return (uint32_t)__cvta_generic_to_shared(p);
}
__device__ __forceinline__ void cpasync16(uint32_t dst, const void* src) {
    asm volatile("cp.async.cg.shared.global [%0], [%1], 16;" :: "r"(dst), "l"(src));
}
#define CP_COMMIT() asm volatile("cp.async.commit_group;")
#define CP_WAIT(N)  asm volatile("cp.async.wait_group %0;" :: "n"(N))

__device__ __forceinline__ void mma_f16(float* d, const uint32_t* a, const uint32_t* b) {
    asm volatile(
        "mma.sync.aligned.m16n8k16.row.col.f32.f16.f16.f32 "
        "{%0,%1,%2,%3}, {%4,%5,%6,%7}, {%8,%9}, {%0,%1,%2,%3};"
        : "+f"(d[0]), "+f"(d[1]), "+f"(d[2]), "+f"(d[3])
        : "r"(a[0]), "r"(a[1]), "r"(a[2]), "r"(a[3]), "r"(b[0]), "r"(b[1]));
}
__device__ __forceinline__ void ldm_x4(uint32_t* r, uint32_t addr) {
    asm volatile("ldmatrix.sync.aligned.m8n8.x4.shared.b16 {%0,%1,%2,%3}, [%4];"
                 : "=r"(r[0]), "=r"(r[1]), "=r"(r[2]), "=r"(r[3]) : "r"(addr));
}
__device__ __forceinline__ uint32_t packh_hi(float x, float y) {
    __half2 h = __floats2half2_rn(x, y);
    return *(uint32_t*)&h;
}
__device__ __forceinline__ uint32_t packh_lo(float x, float y, uint32_t hi) {
    __half2 h = *(__half2*)&hi;
    __half2 l = __floats2half2_rn(x - __half2float(h.x), y - __half2float(h.y));
    return *(uint32_t*)&l;
}

// ---------------- fp32 -> fp16 hi/lo split ----------------------------------
__global__ __launch_bounds__(256) void split_f16(
    const float4* __restrict__ src, uint2* __restrict__ hi,
    uint2* __restrict__ lo, int n4)
{
    int i = blockIdx.x * 256 + threadIdx.x;
    if (i >= n4) return;
    float4 v = src[i];
    __half2 h0 = __floats2half2_rn(v.x, v.y);
    __half2 h1 = __floats2half2_rn(v.z, v.w);
    __half2 l0 = __floats2half2_rn(v.x - __half2float(h0.x),
                                   v.y - __half2float(h0.y));
    __half2 l1 = __floats2half2_rn(v.z - __half2float(h1.x),
                                   v.w - __half2float(h1.y));
    uint2 H, L;
    H.x = *(uint32_t*)&h0; H.y = *(uint32_t*)&h1;
    L.x = *(uint32_t*)&l0; L.y = *(uint32_t*)&l1;
    hi[i] = H; lo[i] = L;
}

// ---------------- W[K,N] -> WT[N,K] single fp16 -----------------------------
__global__ void transpose_f16(const float* __restrict__ W,
                              __half* __restrict__ T, int K, int N)
{
    __shared__ float t[32][33];
    int n0 = blockIdx.x * 32, k0 = blockIdx.y * 32;
    int tx = threadIdx.x, ty = threadIdx.y;
    for (int j = ty; j < 32; j += 8)
        t[j][tx] = W[(size_t)(k0 + j) * N + n0 + tx];
    __syncthreads();
    for (int j = ty; j < 32; j += 8)
        T[(size_t)(n0 + j) * K + k0 + tx] = __float2half(t[tx][j]);
}

// ---------------- mma.sync fp16 2-term GEMM ---------------------------------
#define KC      64
#define RSTRIDE 144
#define OFF_AL  18432
#define OFF_B   36864
#define STAGE   73728
#define G_SMEM  (2 * STAGE)

__global__ __launch_bounds__(256, 1) void gemm_mma(
    const __half* __restrict__ Ah, const __half* __restrict__ Al,
    const __half* __restrict__ B, float* __restrict__ C, int M, int N, int K)
{
    extern __shared__ char sm[];
    const uint32_t smb = s2u(sm);
    const int tid  = threadIdx.x;
    const int wid  = tid >> 5, lane = tid & 31;
    const int wm   = wid & 1, wn = wid >> 1;
    const int g    = lane >> 2, tg = lane & 3;
    const int lm   = lane >> 3, lr = lane & 7;
    const int m0   = blockIdx.y * 128, n0 = blockIdx.x * 256;

    float acc[4][8][4];
#pragma unroll
    for (int a = 0; a < 4; a++)
#pragma unroll
        for (int b = 0; b < 8; b++)
#pragma unroll
            for (int c = 0; c < 4; c++) acc[a][b][c] = 0.f;

    const int nchunks = K / KC;

    auto load_chunk = [&](int kc, int st) {
        uint32_t base = smb + st * STAGE;
        int k0 = kc * KC;
#pragma unroll
        for (int i = 0; i < 4; i++) {
            int lin = tid + i * 256;
            int r = lin >> 3, sg = lin & 7;
            uint32_t off = r * RSTRIDE + sg * 16;
            size_t gidx = (size_t)(m0 + r) * K + k0 + sg * 8;
            cpasync16(base + off,          Ah + gidx);
            cpasync16(base + OFF_AL + off, Al + gidx);
        }
#pragma unroll
        for (int i = 0; i < 8; i++) {
            int lin = tid + i * 256;
            int r = lin >> 3, sg = lin & 7;
            uint32_t off = r * RSTRIDE + sg * 16;
            size_t gidx = (size_t)(n0 + r) * K + k0 + sg * 8;
            cpasync16(base + OFF_B + off, B + gidx);
        }
        CP_COMMIT();
    };

    auto compute = [&](int st) {
        uint32_t base = smb + st * STAGE;
        uint32_t aaddr = base + (wm * 64 + (lm & 1) * 8 + lr) * RSTRIDE + (lm >> 1) * 16;
        uint32_t baddr = base + OFF_B + (wn * 64 + (lm >> 1) * 8 + lr) * RSTRIDE + (lm & 1) * 16;
#pragma unroll
        for (int ks = 0; ks < 4; ks++) {
            int ko = ks * 32;
            uint32_t ah[4][4], al[4][4];
#pragma unroll
            for (int mt = 0; mt < 4; mt++) {
                ldm_x4(ah[mt], aaddr + mt * 16 * RSTRIDE + ko);
                ldm_x4(al[mt], aaddr + OFF_AL + mt * 16 * RSTRIDE + ko);
            }
#pragma unroll
            for (int p = 0; p < 4; p++) {
                uint32_t bq[4];
                ldm_x4(bq, baddr + p * 16 * RSTRIDE + ko);
#pragma unroll
                for (int mt = 0; mt < 4; mt++) {
                    float* d0 = acc[mt][2 * p];
                    float* d1 = acc[mt][2 * p + 1];
                    mma_f16(d0, ah[mt], bq);
                    mma_f16(d0, al[mt], bq);
                    mma_f16(d1, ah[mt], bq + 2);
                    mma_f16(d1, al[mt], bq + 2);
                }
            }
        }
    };

    load_chunk(0, 0);
    for (int kc = 0; kc < nchunks; kc++) {
        int st = kc & 1;
        if (kc + 1 < nchunks) load_chunk(kc + 1, st ^ 1);
        if (kc + 1 < nchunks) { CP_WAIT(1); } else { CP_WAIT(0); }
        __syncthreads();
        compute(st);
        __syncthreads();
    }

#pragma unroll
    for (int mt = 0; mt < 4; mt++)
#pragma unroll
        for (int nt = 0; nt < 8; nt++) {
            int r = m0 + wm * 64 + mt * 16 + g;
            int c = n0 + wn * 64 + nt * 8 + tg * 2;
            float2 v0 = make_float2(acc[mt][nt][0], acc[mt][nt][1]);
            float2 v1 = make_float2(acc[mt][nt][2], acc[mt][nt][3]);
            *(float2*)&C[(size_t)r * N + c]       = v0;
            *(float2*)&C[(size_t)(r + 8) * N + c] = v1;
        }
}

// ---------------- RMSNorm + RoPE -> Q fp16, K fp16, V^T fp16 ----------------
__global__ void norm_rope_kernel(
    const float* __restrict__ qkv, const float* __restrict__ qw,
    const float* __restrict__ kw, const int* __restrict__ pos_ids,
    __half* __restrict__ Qhh, __half* __restrict__ Khh, __half* __restrict__ Vth)
{
    const int token = blockIdx.x;
    const int b = token / S_, s = token % S_;
    const int hid = blockIdx.y;
    const int d = threadIdx.x;

    if (hid >= H_ + HKV_) {
        int h = hid - H_ - HKV_;
        float x = qkv[(size_t)token * NQKV + 2560 + h * HD_ + d];
        Vth[(((size_t)b * HKV_ + h) * HD_ + d) * S_ + s] = __float2half(x);
        return;
    }
    const bool isq = hid < H_;
    const int h = isq ? hid : hid - H_;
    const int nh = isq ? H_ : HKV_;
    const int coff = isq ? h * HD_ : 2048 + h * HD_;

    float x = qkv[(size_t)token * NQKV + coff + d];
    float ss = x * x;
#pragma unroll
    for (int o = 16; o > 0; o >>= 1) ss += __shfl_xor_sync(0xffffffffu, ss, o);
    __shared__ float sbuf[4];
    if ((d & 31) == 0) sbuf[d >> 5] = ss;
    __syncthreads();
    float var = (sbuf[0] + sbuf[1] + sbuf[2] + sbuf[3]) * (1.0f / HD_);
    float r = rsqrtf(var + 1e-6f);
    const float* w = isq ? qw : kw;
    float xn = w[d] * (x * r);

    __shared__ float xs[HD_];
    xs[d] = xn;
    __syncthreads();
    float rot = (d < 64) ? -xs[d + 64] : xs[d - 64];

    int p = pos_ids[token];
    float inv = exp2f(-13.287712379549449f * (float)(2 * (d & 63)) * (1.0f / 128.0f));
    float ang = (float)p * inv;
    float cs, sn;
    sincosf(ang, &sn, &cs);
    float out = xn * cs + rot * sn;

    size_t o = (((size_t)b * nh + h) * S_ + s) * HD_ + d;
    if (isq) Qhh[o] = __float2half(out);
    else     Khh[o] = __float2half(out);
}

// ---------------- mma.sync fp16 single-term causal flash --------------------
#define FQSTR 272
#define FKSTR 272
#define FVSTR 144
#define QBYTES (128 * FQSTR)                 // 34816 (single plane)
#define KSTAGE (64 * FKSTR)                  // 17408
#define VSTAGE (128 * FVSTR)                 // 18432
#define OFF_Q  0
#define OFF_K  QBYTES                        // 34816
#define OFF_V  (OFF_K + 2 * KSTAGE)          // 69632
#define FLASH_SMEM (OFF_V + 2 * VSTAGE)      // 106496

__global__ __launch_bounds__(256, 1) void flash_mma(
    const __half* __restrict__ Qh, const __half* __restrict__ Kh,
    const __half* __restrict__ Vth,
    __half* __restrict__ Oh, __half* __restrict__ Ol)
{
    extern __shared__ char sm[];
    const uint32_t smb = s2u(sm);
    const int tid = threadIdx.x, wid = tid >> 5, lane = tid & 31;
    const int g = lane >> 2, tg = lane & 3;
    const int lm = lane >> 3, lr = lane & 7;
    const int qb = gridDim.x - 1 - blockIdx.x;   // longest tiles first
    const int bh = blockIdx.y;
    const int b = bh / H_, h = bh % H_;
    const int kvh = h / (H_ / HKV_);
    const int q0 = qb * 128;
    const int nkb = 2 * qb + 2;

    const __half* Qhg = Qh + (((size_t)b * H_ + h) * S_ + q0) * HD_;
    const __half* Khg = Kh + ((size_t)b * HKV_ + kvh) * S_ * HD_;
    const __half* Vhg = Vth + ((size_t)b * HKV_ + kvh) * (size_t)HD_ * S_;

    for (int i = tid; i < 2048; i += 256) {
        int r = i >> 4, c = i & 15;
        cpasync16(smb + OFF_Q + r * FQSTR + c * 16, Qhg + (size_t)r * HD_ + c * 8);
    }
    CP_COMMIT();

    auto load_kv = [&](int kb, int st) {
        uint32_t kbase = smb + OFF_K + st * KSTAGE;
        const __half* kh = Khg + (size_t)kb * 64 * HD_;
        for (int i = tid; i < 1024; i += 256) {
            int r = i >> 4, c = i & 15;
            cpasync16(kbase + r * FKSTR + c * 16, kh + (size_t)r * HD_ + c * 8);
        }
        uint32_t vbase = smb + OFF_V + st * VSTAGE;
        const __half* vh = Vhg + kb * 64;
        for (int i = tid; i < 1024; i += 256) {
            int r = i >> 3, c = i & 7;
            cpasync16(vbase + r * FVSTR + c * 16, vh + (size_t)r * S_ + c * 8);
        }
        CP_COMMIT();
    };

    load_kv(0, 0);
    if (nkb > 1) load_kv(1, 1);

    float m0 = -1e30f, m1 = -1e30f, l0 = 0.f, l1 = 0.f;
    float acc[16][4];
#pragma unroll
    for (int i = 0; i < 16; i++)
#pragma unroll
        for (int j = 0; j < 4; j++) acc[i][j] = 0.f;

    const int qi0 = q0 + wid * 16 + g;
    const int qi1 = qi0 + 8;
    const int qimax = q0 + wid * 16 + 15;
    const float sc = 0.08838834764831845f;

    const uint32_t aaddr = smb + OFF_Q + (wid * 16 + (lm & 1) * 8 + lr) * FQSTR + (lm >> 1) * 16;
    const uint32_t brow_off = ((lm >> 1) * 8 + lr);
    const uint32_t bcol_off = (lm & 1) * 16;

    for (int kb = 0; kb < nkb; kb++) {
        int st = kb & 1;
        if (kb + 1 < nkb) { CP_WAIT(1); } else { CP_WAIT(0); }
        __syncthreads();

        if (kb * 64 <= qimax) {        // warp-level skip of fully-masked blocks
            float c[8][4];
#pragma unroll
            for (int i = 0; i < 8; i++)
#pragma unroll
                for (int j = 0; j < 4; j++) c[i][j] = 0.f;

            uint32_t kaddr = smb + OFF_K + st * KSTAGE + brow_off * FKSTR + bcol_off;
#pragma unroll
            for (int ks = 0; ks < 8; ks++) {
                int ko = ks * 32;
                uint32_t ah[4];
                ldm_x4(ah, aaddr + ko);
#pragma unroll
                for (int p = 0; p < 4; p++) {
                    uint32_t bq[4];
                    ldm_x4(bq, kaddr + p * 16 * FKSTR + ko);
                    mma_f16(c[2 * p],     ah, bq);
                    mma_f16(c[2 * p + 1], ah, bq + 2);
                }
            }

#pragma unroll
            for (int nt = 0; nt < 8; nt++) {
                int k0c = kb * 64 + nt * 8 + tg * 2;
                c[nt][0] = (k0c     <= qi0) ? c[nt][0] * sc : -1e30f;
                c[nt][1] = (k0c + 1 <= qi0) ? c[nt][1] * sc : -1e30f;
                c[nt][2] = (k0c     <= qi1) ? c[nt][2] * sc : -1e30f;
                c[nt][3] = (k0c + 1 <= qi1) ? c[nt][3] * sc : -1e30f;
            }

            float rm0 = -1e30f, rm1 = -1e30f;
#pragma unroll
            for (int nt = 0; nt < 8; nt++) {
                rm0 = fmaxf(rm0, fmaxf(c[nt][0], c[nt][1]));
                rm1 = fmaxf(rm1, fmaxf(c[nt][2], c[nt][3]));
            }
            rm0 = fmaxf(rm0, __shfl_xor_sync(0xffffffffu, rm0, 1));
            rm0 = fmaxf(rm0, __shfl_xor_sync(0xffffffffu, rm0, 2));
            rm1 = fmaxf(rm1, __shfl_xor_sync(0xffffffffu, rm1, 1));
            rm1 = fmaxf(rm1, __shfl_xor_sync(0xffffffffu, rm1, 2));
            float mn0 = fmaxf(m0, rm0), mn1 = fmaxf(m1, rm1);
            float cr0 = __expf(m0 - mn0), cr1 = __expf(m1 - mn1);
            m0 = mn0; m1 = mn1;
            float rs0 = 0.f, rs1 = 0.f;
#pragma unroll
            for (int nt = 0; nt < 8; nt++) {
                c[nt][0] = __expf(c[nt][0] - mn0);
                c[nt][1] = __expf(c[nt][1] - mn0);
                c[nt][2] = __expf(c[nt][2] - mn1);
                c[nt][3] = __expf(c[nt][3] - mn1);
                rs0 += c[nt][0] + c[nt][1];
                rs1 += c[nt][2] + c[nt][3];
            }
            rs0 += __shfl_xor_sync(0xffffffffu, rs0, 1);
            rs0 += __shfl_xor_sync(0xffffffffu, rs0, 2);
            rs1 += __shfl_xor_sync(0xffffffffu, rs1, 1);
            rs1 += __shfl_xor_sync(0xffffffffu, rs1, 2);
            l0 = l0 * cr0 + rs0;
            l1 = l1 * cr1 + rs1;
#pragma unroll
            for (int nt = 0; nt < 16; nt++) {
                acc[nt][0] *= cr0; acc[nt][1] *= cr0;
                acc[nt][2] *= cr1; acc[nt][3] *= cr1;
            }

            // P single fp16 A-fragments (register repack)
            uint32_t ph[4][4];
#pragma unroll
            for (int s = 0; s < 4; s++) {
                ph[s][0] = packh_hi(c[2*s][0],   c[2*s][1]);
                ph[s][1] = packh_hi(c[2*s][2],   c[2*s][3]);
                ph[s][2] = packh_hi(c[2*s+1][0], c[2*s+1][1]);
                ph[s][3] = packh_hi(c[2*s+1][2], c[2*s+1][3]);
            }

            uint32_t vaddr = smb + OFF_V + st * VSTAGE + brow_off * FVSTR + bcol_off;
#pragma unroll
            for (int s = 0; s < 4; s++) {
#pragma unroll
                for (int p = 0; p < 8; p++) {
                    uint32_t bq[4];
                    ldm_x4(bq, vaddr + p * 16 * FVSTR + s * 32);
                    mma_f16(acc[2 * p],     ph[s], bq);
                    mma_f16(acc[2 * p + 1], ph[s], bq + 2);
                }
            }
        }

        __syncthreads();
        if (kb + 2 < nkb) load_kv(kb + 2, st);
    }

    float rl0 = 1.f / l0, rl1 = 1.f / l1;
    int t0 = b * S_ + q0 + wid * 16 + g;
    size_t o0 = (size_t)t0 * (H_ * HD_) + h * HD_;
    size_t o1 = (size_t)(t0 + 8) * (H_ * HD_) + h * HD_;
#pragma unroll
    for (int nt = 0; nt < 16; nt++) {
        int d = nt * 8 + tg * 2;
        float x0 = acc[nt][0] * rl0, x1 = acc[nt][1] * rl0;
        float y0 = acc[nt][2] * rl1, y1 = acc[nt][3] * rl1;
        uint32_t h0 = packh_hi(x0, x1);
        uint32_t l0w = packh_lo(x0, x1, h0);
        uint32_t h1 = packh_hi(y0, y1);
        uint32_t l1w = packh_lo(y0, y1, h1);
        *(uint32_t*)(Oh + o0 + d) = h0;
        *(uint32_t*)(Ol + o0 + d) = l0w;
        *(uint32_t*)(Oh + o1 + d) = h1;
        *(uint32_t*)(Ol + o1 + d) = l1w;
    }
}

// ---------------------------------------------------------------------------
extern "C" void kernel_launch(void* const* d_in, const int* in_sizes, int n_in,
                              void* d_out, int out_size)
{
    const float* hidden = (const float*)d_in[0];
    const float* wq     = (const float*)d_in[1];
    const float* wk     = (const float*)d_in[2];
    const float* wv     = (const float*)d_in[3];
    const float* wo     = (const float*)d_in[4];
    const float* qw     = (const float*)d_in[5];
    const float* kw     = (const float*)d_in[6];
    const int*   pos    = (const int*)d_in[7];
    float* out = (float*)d_out;

    float *qkvproj;
    cudaGetSymbolAddress((void**)&qkvproj, g_qkvproj);

    __half *hh, *hl, *wqkvT, *woT, *ath, *atl, *qh, *kh, *vth;
    cudaGetSymbolAddress((void**)&hh,    g_hid_hi);
    cudaGetSymbolAddress((void**)&hl,    g_hid_lo);
    cudaGetSymbolAddress((void**)&wqkvT, g_wqkvT);
    cudaGetSymbolAddress((void**)&woT,   g_woT);
    cudaGetSymbolAddress((void**)&ath,   g_at_hi);
    cudaGetSymbolAddress((void**)&atl,   g_at_lo);
    cudaGetSymbolAddress((void**)&qh,    g_qh);
    cudaGetSymbolAddress((void**)&kh,    g_kh);
    cudaGetSymbolAddress((void**)&vth,   g_vth);

    cudaFuncSetAttribute(gemm_mma, cudaFuncAttributeMaxDynamicSharedMemorySize,
                         (int)G_SMEM);
    cudaFuncSetAttribute(flash_mma, cudaFuncAttributeMaxDynamicSharedMemorySize,
                         (int)FLASH_SMEM);

    // split hidden into hi/lo fp16
    int n4 = NT * D_ / 4;
    split_f16<<<(n4 + 255) / 256, 256>>>((const float4*)hidden, (uint2*)hh, (uint2*)hl, n4);

    // transpose weights to single fp16 (concatenated QKV + WO)
    transpose_f16<<<dim3((H_*HD_)/32, D_/32), dim3(32, 8)>>>(wq, wqkvT, D_, H_*HD_);
    transpose_f16<<<dim3((HKV_*HD_)/32, D_/32), dim3(32, 8)>>>(
        wk, wqkvT + (size_t)2048 * D_, D_, HKV_*HD_);
    transpose_f16<<<dim3((HKV_*HD_)/32, D_/32), dim3(32, 8)>>>(
        wv, wqkvT + (size_t)2560 * D_, D_, HKV_*HD_);
    transpose_f16<<<dim3(D_/32, (H_*HD_)/32), dim3(32, 8)>>>(wo, woT, H_*HD_, D_);

    // fused QKV projection (fp16 2-term)
    gemm_mma<<<dim3(NQKV/256, NT/128), 256, G_SMEM>>>(hh, hl, wqkvT, qkvproj,
                                                      NT, NQKV, D_);

    // RMSNorm + RoPE -> Q fp16, K fp16, V^T fp16
    norm_rope_kernel<<<dim3(NT, H_ + 2*HKV_), 128>>>(qkvproj, qw, kw, pos, qh, kh, vth);

    // tensor-core causal flash attention (fp16 single-term) -> attn fp16 hi/lo
    flash_mma<<<dim3(S_/128, B_*H_), 256, FLASH_SMEM>>>(qh, kh, vth, ath, atl);

    // output projection (fp16 2-term)
    gemm_mma<<<dim3(D_/256, NT/128), 256, G_SMEM>>>(ath, atl, woT, out, NT, D_, D_);
}

// round 10
// speedup vs baseline: 11.6421x; 1.3566x over previous
#include <cuda_runtime.h>
#include <cuda_fp16.h>
#include <math.h>
#include <stdint.h>

#define B_   2
#define S_   2048
#define D_   2048
#define H_   16
#define HKV_ 4
#define HD_  128
#define NT   (B_ * S_)
#define NQKV 3072

// ---------------- scratch ---------------------------------------------------
__device__ float g_qkvproj[NT * NQKV];

__device__ __half g_hid[NT * D_];
__device__ __half g_wqkvT[NQKV * D_];
__device__ __half g_woT[(H_*HD_) * D_];
__device__ __half g_at[NT * (H_*HD_)];

__device__ __half g_qh[NT * H_ * HD_];     // Q fp16
__device__ __half g_kh[NT * HKV_ * HD_];   // K fp16
__device__ __half g_vth[NT * HKV_ * HD_];  // V^T fp16 [b,kvh,d,s]

// ---------------- helpers ---------------------------------------------------
__device__ __forceinline__ uint32_t s2u(const void* p) {
    return (uint32_t)__cvta_generic_to_shared(p);
}
__device__ __forceinline__ void cpasync16(uint32_t dst, const void* src) {
    asm volatile("cp.async.cg.shared.global [%0], [%1], 16;" :: "r"(dst), "l"(src));
}
#define CP_COMMIT() asm volatile("cp.async.commit_group;")
#define CP_WAIT(N)  asm volatile("cp.async.wait_group %0;" :: "n"(N))

__device__ __forceinline__ void mma_f16(float* d, const uint32_t* a, const uint32_t* b) {
    asm volatile(
        "mma.sync.aligned.m16n8k16.row.col.f32.f16.f16.f32 "
        "{%0,%1,%2,%3}, {%4,%5,%6,%7}, {%8,%9}, {%0,%1,%2,%3};"
        : "+f"(d[0]), "+f"(d[1]), "+f"(d[2]), "+f"(d[3])
        : "r"(a[0]), "r"(a[1]), "r"(a[2]), "r"(a[3]), "r"(b[0]), "r"(b[1]));
}
__device__ __forceinline__ void ldm_x4(uint32_t* r, uint32_t addr) {
    asm volatile("ldmatrix.sync.aligned.m8n8.x4.shared.b16 {%0,%1,%2,%3}, [%4];"
                 : "=r"(r[0]), "=r"(r[1]), "=r"(r[2]), "=r"(r[3]) : "r"(addr));
}
__device__ __forceinline__ uint32_t packh_hi(float x, float y) {
    __half2 h = __floats2half2_rn(x, y);
    return *(uint32_t*)&h;
}

// ---------------- fp32 -> fp16 convert --------------------------------------
__global__ __launch_bounds__(256) void convert_f16(
    const float4* __restrict__ src, uint2* __restrict__ dst, int n4)
{
    int i = blockIdx.x * 256 + threadIdx.x;
    if (i >= n4) return;
    float4 v = src[i];
    __half2 h0 = __floats2half2_rn(v.x, v.y);
    __half2 h1 = __floats2half2_rn(v.z, v.w);
    uint2 H;
    H.x = *(uint32_t*)&h0; H.y = *(uint32_t*)&h1;
    dst[i] = H;
}

// ---------------- W[K,N] -> WT[N,K] fp16 ------------------------------------
__global__ void transpose_f16(const float* __restrict__ W,
                              __half* __restrict__ T, int K, int N)
{
    __shared__ float t[32][33];
    int n0 = blockIdx.x * 32, k0 = blockIdx.y * 32;
    int tx = threadIdx.x, ty = threadIdx.y;
    for (int j = ty; j < 32; j += 8)
        t[j][tx] = W[(size_t)(k0 + j) * N + n0 + tx];
    __syncthreads();
    for (int j = ty; j < 32; j += 8)
        T[(size_t)(n0 + j) * K + k0 + tx] = __float2half(t[tx][j]);
}

// ---------------- mma.sync fp16 single-term GEMM ----------------------------
// C[M,N] = A[M,K] @ B[N,K]^T, fp16 x fp16, fp32 accum. Tile 128x256.
#define KC      64
#define RSTRIDE 144
#define OFF_B   18432
#define STAGE   55296
#define G_SMEM  (2 * STAGE)

__global__ __launch_bounds__(256, 1) void gemm_mma(
    const __half* __restrict__ A, const __half* __restrict__ B,
    float* __restrict__ C, int M, int N, int K)
{
    extern __shared__ char sm[];
    const uint32_t smb = s2u(sm);
    const int tid  = threadIdx.x;
    const int wid  = tid >> 5, lane = tid & 31;
    const int wm   = wid & 1, wn = wid >> 1;
    const int g    = lane >> 2, tg = lane & 3;
    const int lm   = lane >> 3, lr = lane & 7;
    const int m0   = blockIdx.y * 128, n0 = blockIdx.x * 256;

    float acc[4][8][4];
#pragma unroll
    for (int a = 0; a < 4; a++)
#pragma unroll
        for (int b = 0; b < 8; b++)
#pragma unroll
            for (int c = 0; c < 4; c++) acc[a][b][c] = 0.f;

    const int nchunks = K / KC;

    auto load_chunk = [&](int kc, int st) {
        uint32_t base = smb + st * STAGE;
        int k0 = kc * KC;
#pragma unroll
        for (int i = 0; i < 4; i++) {
            int lin = tid + i * 256;
            int r = lin >> 3, sg = lin & 7;
            uint32_t off = r * RSTRIDE + sg * 16;
            cpasync16(base + off, A + (size_t)(m0 + r) * K + k0 + sg * 8);
        }
#pragma unroll
        for (int i = 0; i < 8; i++) {
            int lin = tid + i * 256;
            int r = lin >> 3, sg = lin & 7;
            uint32_t off = r * RSTRIDE + sg * 16;
            cpasync16(base + OFF_B + off, B + (size_t)(n0 + r) * K + k0 + sg * 8);
        }
        CP_COMMIT();
    };

    auto compute = [&](int st) {
        uint32_t base = smb + st * STAGE;
        uint32_t aaddr = base + (wm * 64 + (lm & 1) * 8 + lr) * RSTRIDE + (lm >> 1) * 16;
        uint32_t baddr = base + OFF_B + (wn * 64 + (lm >> 1) * 8 + lr) * RSTRIDE + (lm & 1) * 16;
#pragma unroll
        for (int ks = 0; ks < 4; ks++) {
            int ko = ks * 32;
            uint32_t ah[4][4];
#pragma unroll
            for (int mt = 0; mt < 4; mt++)
                ldm_x4(ah[mt], aaddr + mt * 16 * RSTRIDE + ko);
#pragma unroll
            for (int p = 0; p < 4; p++) {
                uint32_t bq[4];
                ldm_x4(bq, baddr + p * 16 * RSTRIDE + ko);
#pragma unroll
                for (int mt = 0; mt < 4; mt++) {
                    mma_f16(acc[mt][2 * p],     ah[mt], bq);
                    mma_f16(acc[mt][2 * p + 1], ah[mt], bq + 2);
                }
            }
        }
    };

    load_chunk(0, 0);
    for (int kc = 0; kc < nchunks; kc++) {
        int st = kc & 1;
        if (kc + 1 < nchunks) load_chunk(kc + 1, st ^ 1);
        if (kc + 1 < nchunks) { CP_WAIT(1); } else { CP_WAIT(0); }
        __syncthreads();
        compute(st);
        __syncthreads();
    }

#pragma unroll
    for (int mt = 0; mt < 4; mt++)
#pragma unroll
        for (int nt = 0; nt < 8; nt++) {
            int r = m0 + wm * 64 + mt * 16 + g;
            int c = n0 + wn * 64 + nt * 8 + tg * 2;
            float2 v0 = make_float2(acc[mt][nt][0], acc[mt][nt][1]);
            float2 v1 = make_float2(acc[mt][nt][2], acc[mt][nt][3]);
            *(float2*)&C[(size_t)r * N + c]       = v0;
            *(float2*)&C[(size_t)(r + 8) * N + c] = v1;
        }
}

// ---------------- RMSNorm + RoPE -> Q fp16, K fp16, V^T fp16 ----------------
__global__ void norm_rope_kernel(
    const float* __restrict__ qkv, const float* __restrict__ qw,
    const float* __restrict__ kw, const int* __restrict__ pos_ids,
    __half* __restrict__ Qhh, __half* __restrict__ Khh, __half* __restrict__ Vth)
{
    const int token = blockIdx.x;
    const int b = token / S_, s = token % S_;
    const int hid = blockIdx.y;
    const int d = threadIdx.x;

    if (hid >= H_ + HKV_) {
        int h = hid - H_ - HKV_;
        float x = qkv[(size_t)token * NQKV + 2560 + h * HD_ + d];
        Vth[(((size_t)b * HKV_ + h) * HD_ + d) * S_ + s] = __float2half(x);
        return;
    }
    const bool isq = hid < H_;
    const int h = isq ? hid : hid - H_;
    const int nh = isq ? H_ : HKV_;
    const int coff = isq ? h * HD_ : 2048 + h * HD_;

    float x = qkv[(size_t)token * NQKV + coff + d];
    float ss = x * x;
#pragma unroll
    for (int o = 16; o > 0; o >>= 1) ss += __shfl_xor_sync(0xffffffffu, ss, o);
    __shared__ float sbuf[4];
    if ((d & 31) == 0) sbuf[d >> 5] = ss;
    __syncthreads();
    float var = (sbuf[0] + sbuf[1] + sbuf[2] + sbuf[3]) * (1.0f / HD_);
    float r = rsqrtf(var + 1e-6f);
    const float* w = isq ? qw : kw;
    float xn = w[d] * (x * r);

    __shared__ float xs[HD_];
    xs[d] = xn;
    __syncthreads();
    float rot = (d < 64) ? -xs[d + 64] : xs[d - 64];

    int p = pos_ids[token];
    float inv = exp2f(-13.287712379549449f * (float)(2 * (d & 63)) * (1.0f / 128.0f));
    float ang = (float)p * inv;
    float cs, sn;
    sincosf(ang, &sn, &cs);
    float out = xn * cs + rot * sn;

    size_t o = (((size_t)b * nh + h) * S_ + s) * HD_ + d;
    if (isq) Qhh[o] = __float2half(out);
    else     Khh[o] = __float2half(out);
}

// ---------------- mma.sync fp16 single-term causal flash --------------------
#define FQSTR 272
#define FKSTR 272
#define FVSTR 144
#define QBYTES (128 * FQSTR)
#define KSTAGE (64 * FKSTR)
#define VSTAGE (128 * FVSTR)
#define OFF_Q  0
#define OFF_K  QBYTES
#define OFF_V  (OFF_K + 2 * KSTAGE)
#define FLASH_SMEM (OFF_V + 2 * VSTAGE)      // 106496

__global__ __launch_bounds__(256, 1) void flash_mma(
    const __half* __restrict__ Qh, const __half* __restrict__ Kh,
    const __half* __restrict__ Vth, __half* __restrict__ Oh)
{
    extern __shared__ char sm[];
    const uint32_t smb = s2u(sm);
    const int tid = threadIdx.x, wid = tid >> 5, lane = tid & 31;
    const int g = lane >> 2, tg = lane & 3;
    const int lm = lane >> 3, lr = lane & 7;
    const int qb = gridDim.x - 1 - blockIdx.x;   // longest tiles first
    const int bh = blockIdx.y;
    const int b = bh / H_, h = bh % H_;
    const int kvh = h / (H_ / HKV_);
    const int q0 = qb * 128;
    const int nkb = 2 * qb + 2;

    const __half* Qhg = Qh + (((size_t)b * H_ + h) * S_ + q0) * HD_;
    const __half* Khg = Kh + ((size_t)b * HKV_ + kvh) * S_ * HD_;
    const __half* Vhg = Vth + ((size_t)b * HKV_ + kvh) * (size_t)HD_ * S_;

    for (int i = tid; i < 2048; i += 256) {
        int r = i >> 4, c = i & 15;
        cpasync16(smb + OFF_Q + r * FQSTR + c * 16, Qhg + (size_t)r * HD_ + c * 8);
    }
    CP_COMMIT();

    auto load_kv = [&](int kb, int st) {
        uint32_t kbase = smb + OFF_K + st * KSTAGE;
        const __half* kh = Khg + (size_t)kb * 64 * HD_;
        for (int i = tid; i < 1024; i += 256) {
            int r = i >> 4, c = i & 15;
            cpasync16(kbase + r * FKSTR + c * 16, kh + (size_t)r * HD_ + c * 8);
        }
        uint32_t vbase = smb + OFF_V + st * VSTAGE;
        const __half* vh = Vhg + kb * 64;
        for (int i = tid; i < 1024; i += 256) {
            int r = i >> 3, c = i & 7;
            cpasync16(vbase + r * FVSTR + c * 16, vh + (size_t)r * S_ + c * 8);
        }
        CP_COMMIT();
    };

    load_kv(0, 0);
    if (nkb > 1) load_kv(1, 1);

    float m0 = -1e30f, m1 = -1e30f, l0 = 0.f, l1 = 0.f;
    float acc[16][4];
#pragma unroll
    for (int i = 0; i < 16; i++)
#pragma unroll
        for (int j = 0; j < 4; j++) acc[i][j] = 0.f;

    const int qi0 = q0 + wid * 16 + g;
    const int qi1 = qi0 + 8;
    const int qimax = q0 + wid * 16 + 15;
    const float sc = 0.08838834764831845f;

    const uint32_t aaddr = smb + OFF_Q + (wid * 16 + (lm & 1) * 8 + lr) * FQSTR + (lm >> 1) * 16;
    const uint32_t brow_off = ((lm >> 1) * 8 + lr);
    const uint32_t bcol_off = (lm & 1) * 16;

    for (int kb = 0; kb < nkb; kb++) {
        int st = kb & 1;
        if (kb + 1 < nkb) { CP_WAIT(1); } else { CP_WAIT(0); }
        __syncthreads();

        if (kb * 64 <= qimax) {
            float c[8][4];
#pragma unroll
            for (int i = 0; i < 8; i++)
#pragma unroll
                for (int j = 0; j < 4; j++) c[i][j] = 0.f;

            uint32_t kaddr = smb + OFF_K + st * KSTAGE + brow_off * FKSTR + bcol_off;
#pragma unroll
            for (int ks = 0; ks < 8; ks++) {
                int ko = ks * 32;
                uint32_t ah[4];
                ldm_x4(ah, aaddr + ko);
#pragma unroll
                for (int p = 0; p < 4; p++) {
                    uint32_t bq[4];
                    ldm_x4(bq, kaddr + p * 16 * FKSTR + ko);
                    mma_f16(c[2 * p],     ah, bq);
                    mma_f16(c[2 * p + 1], ah, bq + 2);
                }
            }

#pragma unroll
            for (int nt = 0; nt < 8; nt++) {
                int k0c = kb * 64 + nt * 8 + tg * 2;
                c[nt][0] = (k0c     <= qi0) ? c[nt][0] * sc : -1e30f;
                c[nt][1] = (k0c + 1 <= qi0) ? c[nt][1] * sc : -1e30f;
                c[nt][2] = (k0c     <= qi1) ? c[nt][2] * sc : -1e30f;
                c[nt][3] = (k0c + 1 <= qi1) ? c[nt][3] * sc : -1e30f;
            }

            float rm0 = -1e30f, rm1 = -1e30f;
#pragma unroll
            for (int nt = 0; nt < 8; nt++) {
                rm0 = fmaxf(rm0, fmaxf(c[nt][0], c[nt][1]));
                rm1 = fmaxf(rm1, fmaxf(c[nt][2], c[nt][3]));
            }
            rm0 = fmaxf(rm0, __shfl_xor_sync(0xffffffffu, rm0, 1));
            rm0 = fmaxf(rm0, __shfl_xor_sync(0xffffffffu, rm0, 2));
            rm1 = fmaxf(rm1, __shfl_xor_sync(0xffffffffu, rm1, 1));
            rm1 = fmaxf(rm1, __shfl_xor_sync(0xffffffffu, rm1, 2));
            float mn0 = fmaxf(m0, rm0), mn1 = fmaxf(m1, rm1);
            float cr0 = __expf(m0 - mn0), cr1 = __expf(m1 - mn1);
            m0 = mn0; m1 = mn1;
            float rs0 = 0.f, rs1 = 0.f;
#pragma unroll
            for (int nt = 0; nt < 8; nt++) {
                c[nt][0] = __expf(c[nt][0] - mn0);
                c[nt][1] = __expf(c[nt][1] - mn0);
                c[nt][2] = __expf(c[nt][2] - mn1);
                c[nt][3] = __expf(c[nt][3] - mn1);
                rs0 += c[nt][0] + c[nt][1];
                rs1 += c[nt][2] + c[nt][3];
            }
            rs0 += __shfl_xor_sync(0xffffffffu, rs0, 1);
            rs0 += __shfl_xor_sync(0xffffffffu, rs0, 2);
            rs1 += __shfl_xor_sync(0xffffffffu, rs1, 1);
            rs1 += __shfl_xor_sync(0xffffffffu, rs1, 2);
            l0 = l0 * cr0 + rs0;
            l1 = l1 * cr1 + rs1;
#pragma unroll
            for (int nt = 0; nt < 16; nt++) {
                acc[nt][0] *= cr0; acc[nt][1] *= cr0;
                acc[nt][2] *= cr1; acc[nt][3] *= cr1;
            }

            uint32_t ph[4][4];
#pragma unroll
            for (int s = 0; s < 4; s++) {
                ph[s][0] = packh_hi(c[2*s][0],   c[2*s][1]);
                ph[s][1] = packh_hi(c[2*s][2],   c[2*s][3]);
                ph[s][2] = packh_hi(c[2*s+1][0], c[2*s+1][1]);
                ph[s][3] = packh_hi(c[2*s+1][2], c[2*s+1][3]);
            }

            uint32_t vaddr = smb + OFF_V + st * VSTAGE + brow_off * FVSTR + bcol_off;
#pragma unroll
            for (int s = 0; s < 4; s++) {
#pragma unroll
                for (int p = 0; p < 8; p++) {
                    uint32_t bq[4];
                    ldm_x4(bq, vaddr + p * 16 * FVSTR + s * 32);
                    mma_f16(acc[2 * p],     ph[s], bq);
                    mma_f16(acc[2 * p + 1], ph[s], bq + 2);
                }
            }
        }

        __syncthreads();
        if (kb + 2 < nkb) load_kv(kb + 2, st);
    }

    float rl0 = 1.f / l0, rl1 = 1.f / l1;
    int t0 = b * S_ + q0 + wid * 16 + g;
    size_t o0 = (size_t)t0 * (H_ * HD_) + h * HD_;
    size_t o1 = (size_t)(t0 + 8) * (H_ * HD_) + h * HD_;
#pragma unroll
    for (int nt = 0; nt < 16; nt++) {
        int d = nt * 8 + tg * 2;
        *(uint32_t*)(Oh + o0 + d) = packh_hi(acc[nt][0] * rl0, acc[nt][1] * rl0);
        *(uint32_t*)(Oh + o1 + d) = packh_hi(acc[nt][2] * rl1, acc[nt][3] * rl1);
    }
}

// ---------------------------------------------------------------------------
extern "C" void kernel_launch(void* const* d_in, const int* in_sizes, int n_in,
                              void* d_out, int out_size)
{
    const float* hidden = (const float*)d_in[0];
    const float* wq     = (const float*)d_in[1];
    const float* wk     = (const float*)d_in[2];
    const float* wv     = (const float*)d_in[3];
    const float* wo     = (const float*)d_in[4];
    const float* qw     = (const float*)d_in[5];
    const float* kw     = (const float*)d_in[6];
    const int*   pos    = (const int*)d_in[7];
    float* out = (float*)d_out;

    float *qkvproj;
    cudaGetSymbolAddress((void**)&qkvproj, g_qkvproj);

    __half *hid16, *wqkvT, *woT, *at16, *qh, *kh, *vth;
    cudaGetSymbolAddress((void**)&hid16, g_hid);
    cudaGetSymbolAddress((void**)&wqkvT, g_wqkvT);
    cudaGetSymbolAddress((void**)&woT,   g_woT);
    cudaGetSymbolAddress((void**)&at16,  g_at);
    cudaGetSymbolAddress((void**)&qh,    g_qh);
    cudaGetSymbolAddress((void**)&kh,    g_kh);
    cudaGetSymbolAddress((void**)&vth,   g_vth);

    cudaFuncSetAttribute(gemm_mma, cudaFuncAttributeMaxDynamicSharedMemorySize,
                         (int)G_SMEM);
    cudaFuncSetAttribute(flash_mma, cudaFuncAttributeMaxDynamicSharedMemorySize,
                         (int)FLASH_SMEM);

    // convert hidden to fp16
    int n4 = NT * D_ / 4;
    convert_f16<<<(n4 + 255) / 256, 256>>>((const float4*)hidden, (uint2*)hid16, n4);

    // transpose weights to fp16 (concatenated QKV + WO)
    transpose_f16<<<dim3((H_*HD_)/32, D_/32), dim3(32, 8)>>>(wq, wqkvT, D_, H_*HD_);
    transpose_f16<<<dim3((HKV_*HD_)/32, D_/32), dim3(32, 8)>>>(
        wk, wqkvT + (size_t)2048 * D_, D_, HKV_*HD_);
    transpose_f16<<<dim3((HKV_*HD_)/32, D_/32), dim3(32, 8)>>>(
        wv, wqkvT + (size_t)2560 * D_, D_, HKV_*HD_);
    transpose_f16<<<dim3(D_/32, (H_*HD_)/32), dim3(32, 8)>>>(wo, woT, H_*HD_, D_);

    // fused QKV projection (fp16 single-term)
    gemm_mma<<<dim3(NQKV/256, NT/128), 256, G_SMEM>>>(hid16, wqkvT, qkvproj,
                                                      NT, NQKV, D_);

    // RMSNorm + RoPE -> Q fp16, K fp16, V^T fp16
    norm_rope_kernel<<<dim3(NT, H_ + 2*HKV_), 128>>>(qkvproj, qw, kw, pos, qh, kh, vth);

    // tensor-core causal flash attention (fp16) -> attn fp16
    flash_mma<<<dim3(S_/128, B_*H_), 256, FLASH_SMEM>>>(qh, kh, vth, at16);

    // output projection (fp16 single-term)
    gemm_mma<<<dim3(D_/256, NT/128), 256, G_SMEM>>>(at16, woT, out, NT, D_, D_);
}

// round 11
// speedup vs baseline: 12.5909x; 1.0815x over previous
#include <cuda_runtime.h>
#include <cuda_fp16.h>
#include <math.h>
#include <stdint.h>

#define B_   2
#define S_   2048
#define D_   2048
#define H_   16
#define HKV_ 4
#define HD_  128
#define NT   (B_ * S_)
#define NQKV 3072

// ---------------- scratch ---------------------------------------------------
__device__ __half g_hid[NT * D_];
__device__ __half g_wqkvT[NQKV * D_];
__device__ __half g_woT[(H_*HD_) * D_];
__device__ __half g_at[NT * (H_*HD_)];

__device__ __half g_qh[NT * H_ * HD_];     // Q fp16 [b,h,s,d]
__device__ __half g_kh[NT * HKV_ * HD_];   // K fp16 [b,kvh,s,d]
__device__ __half g_vth[NT * HKV_ * HD_];  // V^T fp16 [b,kvh,d,s]
__device__ float4 g_rope[S_ * 32];         // (cos,sin,cos,sin) per (pos, freq-pair)

// ---------------- helpers ---------------------------------------------------
__device__ __forceinline__ uint32_t s2u(const void* p) {
    return (uint32_t)__cvta_generic_to_shared(p);
}
__device__ __forceinline__ void cpasync16(uint32_t dst, const void* src) {
    asm volatile("cp.async.cg.shared.global [%0], [%1], 16;" :: "r"(dst), "l"(src));
}
#define CP_COMMIT() asm volatile("cp.async.commit_group;")
#define CP_WAIT(N)  asm volatile("cp.async.wait_group %0;" :: "n"(N))

__device__ __forceinline__ void mma_f16(float* d, const uint32_t* a, const uint32_t* b) {
    asm volatile(
        "mma.sync.aligned.m16n8k16.row.col.f32.f16.f16.f32 "
        "{%0,%1,%2,%3}, {%4,%5,%6,%7}, {%8,%9}, {%0,%1,%2,%3};"
        : "+f"(d[0]), "+f"(d[1]), "+f"(d[2]), "+f"(d[3])
        : "r"(a[0]), "r"(a[1]), "r"(a[2]), "r"(a[3]), "r"(b[0]), "r"(b[1]));
}
__device__ __forceinline__ void ldm_x4(uint32_t* r, uint32_t addr) {
    asm volatile("ldmatrix.sync.aligned.m8n8.x4.shared.b16 {%0,%1,%2,%3}, [%4];"
                 : "=r"(r[0]), "=r"(r[1]), "=r"(r[2]), "=r"(r[3]) : "r"(addr));
}
__device__ __forceinline__ uint32_t packh_hi(float x, float y) {
    __half2 h = __floats2half2_rn(x, y);
    return *(uint32_t*)&h;
}

// ---------------- fp32 -> fp16 convert --------------------------------------
__global__ __launch_bounds__(256) void convert_f16(
    const float4* __restrict__ src, uint2* __restrict__ dst, int n4)
{
    int i = blockIdx.x * 256 + threadIdx.x;
    if (i >= n4) return;
    float4 v = src[i];
    __half2 h0 = __floats2half2_rn(v.x, v.y);
    __half2 h1 = __floats2half2_rn(v.z, v.w);
    uint2 H;
    H.x = *(uint32_t*)&h0; H.y = *(uint32_t*)&h1;
    dst[i] = H;
}

// ---------------- W[K,N] -> WT[N,K] fp16 ------------------------------------
__global__ void transpose_f16(const float* __restrict__ W,
                              __half* __restrict__ T, int K, int N)
{
    __shared__ float t[32][33];
    int n0 = blockIdx.x * 32, k0 = blockIdx.y * 32;
    int tx = threadIdx.x, ty = threadIdx.y;
    for (int j = ty; j < 32; j += 8)
        t[j][tx] = W[(size_t)(k0 + j) * N + n0 + tx];
    __syncthreads();
    for (int j = ty; j < 32; j += 8)
        T[(size_t)(n0 + j) * K + k0 + tx] = __float2half(t[tx][j]);
}

// ---------------- RoPE cos/sin table ----------------------------------------
__global__ void rope_table(float4* __restrict__ tab)
{
    int p = blockIdx.x, j = threadIdx.x;   // j = freq pair index, f0=2j, f1=2j+1
    float i0 = exp2f(-13.287712379549449f * (float)(2 * j)     * (1.0f / 64.0f));
    float i1 = exp2f(-13.287712379549449f * (float)(2 * j + 1) * (1.0f / 64.0f));
    float a0 = (float)p * i0, a1 = (float)p * i1;
    float c0, s0, c1, s1;
    sincosf(a0, &s0, &c0);
    sincosf(a1, &s1, &c1);
    tab[p * 32 + j] = make_float4(c0, s0, c1, s1);
}

// ---------------- GEMM tiling constants -------------------------------------
#define KC      64
#define RSTRIDE 144
#define OFF_B   18432
#define STAGE   55296
#define G_SMEM  (2 * STAGE)     // 110592; epilogue xbuf(67584)+ssbuf(2048) fits

// ---------------- QKV GEMM fused with RMSNorm+RoPE+transpose ----------------
__global__ __launch_bounds__(256, 1) void gemm_qkv_fused(
    const __half* __restrict__ A, const __half* __restrict__ B,
    const float* __restrict__ qw, const float* __restrict__ kw,
    const int* __restrict__ pos_ids, const float4* __restrict__ rope,
    __half* __restrict__ Qo, __half* __restrict__ Ko, __half* __restrict__ Vo)
{
    extern __shared__ char sm[];
    const uint32_t smb = s2u(sm);
    const int tid  = threadIdx.x;
    const int wid  = tid >> 5, lane = tid & 31;
    const int wm   = wid & 1, wn = wid >> 1;
    const int g    = lane >> 2, tg = lane & 3;
    const int lm   = lane >> 3, lr = lane & 7;
    const int m0   = blockIdx.y * 128, n0 = blockIdx.x * 256;
    const int bx   = blockIdx.x;
    const int K    = D_, N = NQKV;

    float acc[4][8][4];
#pragma unroll
    for (int a = 0; a < 4; a++)
#pragma unroll
        for (int b2 = 0; b2 < 8; b2++)
#pragma unroll
            for (int c = 0; c < 4; c++) acc[a][b2][c] = 0.f;

    const int nchunks = K / KC;

    auto load_chunk = [&](int kc, int st) {
        uint32_t base = smb + st * STAGE;
        int k0 = kc * KC;
#pragma unroll
        for (int i = 0; i < 4; i++) {
            int lin = tid + i * 256;
            int r = lin >> 3, sg = lin & 7;
            uint32_t off = r * RSTRIDE + sg * 16;
            cpasync16(base + off, A + (size_t)(m0 + r) * K + k0 + sg * 8);
        }
#pragma unroll
        for (int i = 0; i < 8; i++) {
            int lin = tid + i * 256;
            int r = lin >> 3, sg = lin & 7;
            uint32_t off = r * RSTRIDE + sg * 16;
            cpasync16(base + OFF_B + off, B + (size_t)(n0 + r) * K + k0 + sg * 8);
        }
        CP_COMMIT();
    };

    auto compute = [&](int st) {
        uint32_t base = smb + st * STAGE;
        uint32_t aaddr = base + (wm * 64 + (lm & 1) * 8 + lr) * RSTRIDE + (lm >> 1) * 16;
        uint32_t baddr = base + OFF_B + (wn * 64 + (lm >> 1) * 8 + lr) * RSTRIDE + (lm & 1) * 16;
#pragma unroll
        for (int ks = 0; ks < 4; ks++) {
            int ko = ks * 32;
            uint32_t ah[4][4];
#pragma unroll
            for (int mt = 0; mt < 4; mt++)
                ldm_x4(ah[mt], aaddr + mt * 16 * RSTRIDE + ko);
#pragma unroll
            for (int p = 0; p < 4; p++) {
                uint32_t bq[4];
                ldm_x4(bq, baddr + p * 16 * RSTRIDE + ko);
#pragma unroll
                for (int mt = 0; mt < 4; mt++) {
                    mma_f16(acc[mt][2 * p],     ah[mt], bq);
                    mma_f16(acc[mt][2 * p + 1], ah[mt], bq + 2);
                }
            }
        }
    };

    load_chunk(0, 0);
    for (int kc = 0; kc < nchunks; kc++) {
        int st = kc & 1;
        if (kc + 1 < nchunks) load_chunk(kc + 1, st ^ 1);
        if (kc + 1 < nchunks) { CP_WAIT(1); } else { CP_WAIT(0); }
        __syncthreads();
        compute(st);
        __syncthreads();
    }

    // ================= fused epilogue =================
    __half* xbuf = (__half*)sm;                 // [128][264] fp16
    float*  ssbuf = (float*)(sm + 67584);       // [128][4]

    if (bx < 10) {
        const bool isq = bx < 8;
        const float* w = isq ? qw : kw;

        // 1. per-row sum of squares (partial per warp-col-half)
#pragma unroll
        for (int mt = 0; mt < 4; mt++) {
            float s0 = 0.f, s1 = 0.f;
#pragma unroll
            for (int nt = 0; nt < 8; nt++) {
                s0 += acc[mt][nt][0] * acc[mt][nt][0] + acc[mt][nt][1] * acc[mt][nt][1];
                s1 += acc[mt][nt][2] * acc[mt][nt][2] + acc[mt][nt][3] * acc[mt][nt][3];
            }
            s0 += __shfl_xor_sync(0xffffffffu, s0, 1);
            s0 += __shfl_xor_sync(0xffffffffu, s0, 2);
            s1 += __shfl_xor_sync(0xffffffffu, s1, 1);
            s1 += __shfl_xor_sync(0xffffffffu, s1, 2);
            if (tg == 0) {
                int R = wm * 64 + mt * 16 + g;
                ssbuf[R * 4 + wn]       = s0;
                ssbuf[(R + 8) * 4 + wn] = s1;
            }
        }
        __syncthreads();

        // 2. normalize + weight; keep fp32 in acc, stage fp16 copy for partner
        const int hh = wn >> 1;
#pragma unroll
        for (int mt = 0; mt < 4; mt++) {
            int R0 = wm * 64 + mt * 16 + g, R1 = R0 + 8;
            float v0 = ssbuf[R0 * 4 + 2 * hh] + ssbuf[R0 * 4 + 2 * hh + 1];
            float v1 = ssbuf[R1 * 4 + 2 * hh] + ssbuf[R1 * 4 + 2 * hh + 1];
            float r0 = rsqrtf(v0 * (1.0f / 128.0f) + 1e-6f);
            float r1 = rsqrtf(v1 * (1.0f / 128.0f) + 1e-6f);
#pragma unroll
            for (int nt = 0; nt < 8; nt++) {
                int d = (wn & 1) * 64 + nt * 8 + tg * 2;
                float w0 = w[d], w1 = w[d + 1];
                acc[mt][nt][0] *= r0 * w0; acc[mt][nt][1] *= r0 * w1;
                acc[mt][nt][2] *= r1 * w0; acc[mt][nt][3] *= r1 * w1;
                int c = wn * 64 + nt * 8 + tg * 2;
                *(uint32_t*)(xbuf + R0 * 264 + c) = packh_hi(acc[mt][nt][0], acc[mt][nt][1]);
                *(uint32_t*)(xbuf + R1 * 264 + c) = packh_hi(acc[mt][nt][2], acc[mt][nt][3]);
            }
        }
        __syncthreads();

        // 3. RoPE + transposed store
        __half* dst = isq ? Qo : Ko;
        const int nheads = isq ? H_ : HKV_;
        const int cbase = isq ? 0 : 2048;
#pragma unroll
        for (int mt = 0; mt < 4; mt++) {
#pragma unroll
            for (int hf = 0; hf < 2; hf++) {
                int R = wm * 64 + mt * 16 + g + hf * 8;
                int tok = blockIdx.y * 128 + R;
                int b = tok >> 11, s = tok & 2047;
                int p = pos_ids[tok];
#pragma unroll
                for (int nt = 0; nt < 8; nt++) {
                    int c = wn * 64 + nt * 8 + tg * 2;
                    int C = bx * 256 + c;
                    int head = (C - cbase) >> 7;
                    int d = C & 127;
                    float4 cs = rope[p * 32 + ((d & 63) >> 1)];
                    uint32_t pv = *(uint32_t*)(xbuf + R * 264 + (c ^ 64));
                    __half2 ph2 = *(__half2*)&pv;
                    float rt0 = __half2float(ph2.x), rt1 = __half2float(ph2.y);
                    if (d < 64) { rt0 = -rt0; rt1 = -rt1; }
                    float x0 = acc[mt][nt][hf * 2 + 0], x1 = acc[mt][nt][hf * 2 + 1];
                    float o0 = x0 * cs.x + rt0 * cs.y;
                    float o1 = x1 * cs.z + rt1 * cs.w;
                    size_t off = (((size_t)b * nheads + head) * S_ + s) * HD_ + d;
                    *(uint32_t*)(dst + off) = packh_hi(o0, o1);
                }
            }
        }
    } else {
        // V: straight fp16 convert + transpose to [b,kvh,d,s]
#pragma unroll
        for (int mt = 0; mt < 4; mt++) {
#pragma unroll
            for (int hf = 0; hf < 2; hf++) {
                int R = wm * 64 + mt * 16 + g + hf * 8;
                int tok = blockIdx.y * 128 + R;
                int b = tok >> 11, s = tok & 2047;
#pragma unroll
                for (int nt = 0; nt < 8; nt++) {
                    int c = wn * 64 + nt * 8 + tg * 2;
                    int C = bx * 256 + c - 2560;
                    int kvh = C >> 7, d = C & 127;
                    size_t off = (((size_t)b * HKV_ + kvh) * HD_ + d) * S_ + s;
                    Vo[off]      = __float2half(acc[mt][nt][hf * 2 + 0]);
                    Vo[off + S_] = __float2half(acc[mt][nt][hf * 2 + 1]);
                }
            }
        }
    }
}

// ---------------- generic fp16 GEMM (WO projection) -------------------------
__global__ __launch_bounds__(256, 1) void gemm_mma(
    const __half* __restrict__ A, const __half* __restrict__ B,
    float* __restrict__ C, int M, int N, int K)
{
    extern __shared__ char sm[];
    const uint32_t smb = s2u(sm);
    const int tid  = threadIdx.x;
    const int wid  = tid >> 5, lane = tid & 31;
    const int wm   = wid & 1, wn = wid >> 1;
    const int g    = lane >> 2, tg = lane & 3;
    const int lm   = lane >> 3, lr = lane & 7;
    const int m0   = blockIdx.y * 128, n0 = blockIdx.x * 256;

    float acc[4][8][4];
#pragma unroll
    for (int a = 0; a < 4; a++)
#pragma unroll
        for (int b = 0; b < 8; b++)
#pragma unroll
            for (int c = 0; c < 4; c++) acc[a][b][c] = 0.f;

    const int nchunks = K / KC;

    auto load_chunk = [&](int kc, int st) {
        uint32_t base = smb + st * STAGE;
        int k0 = kc * KC;
#pragma unroll
        for (int i = 0; i < 4; i++) {
            int lin = tid + i * 256;
            int r = lin >> 3, sg = lin & 7;
            uint32_t off = r * RSTRIDE + sg * 16;
            cpasync16(base + off, A + (size_t)(m0 + r) * K + k0 + sg * 8);
        }
#pragma unroll
        for (int i = 0; i < 8; i++) {
            int lin = tid + i * 256;
            int r = lin >> 3, sg = lin & 7;
            uint32_t off = r * RSTRIDE + sg * 16;
            cpasync16(base + OFF_B + off, B + (size_t)(n0 + r) * K + k0 + sg * 8);
        }
        CP_COMMIT();
    };

    auto compute = [&](int st) {
        uint32_t base = smb + st * STAGE;
        uint32_t aaddr = base + (wm * 64 + (lm & 1) * 8 + lr) * RSTRIDE + (lm >> 1) * 16;
        uint32_t baddr = base + OFF_B + (wn * 64 + (lm >> 1) * 8 + lr) * RSTRIDE + (lm & 1) * 16;
#pragma unroll
        for (int ks = 0; ks < 4; ks++) {
            int ko = ks * 32;
            uint32_t ah[4][4];
#pragma unroll
            for (int mt = 0; mt < 4; mt++)
                ldm_x4(ah[mt], aaddr + mt * 16 * RSTRIDE + ko);
#pragma unroll
            for (int p = 0; p < 4; p++) {
                uint32_t bq[4];
                ldm_x4(bq, baddr + p * 16 * RSTRIDE + ko);
#pragma unroll
                for (int mt = 0; mt < 4; mt++) {
                    mma_f16(acc[mt][2 * p],     ah[mt], bq);
                    mma_f16(acc[mt][2 * p + 1], ah[mt], bq + 2);
                }
            }
        }
    };

    load_chunk(0, 0);
    for (int kc = 0; kc < nchunks; kc++) {
        int st = kc & 1;
        if (kc + 1 < nchunks) load_chunk(kc + 1, st ^ 1);
        if (kc + 1 < nchunks) { CP_WAIT(1); } else { CP_WAIT(0); }
        __syncthreads();
        compute(st);
        __syncthreads();
    }

#pragma unroll
    for (int mt = 0; mt < 4; mt++)
#pragma unroll
        for (int nt = 0; nt < 8; nt++) {
            int r = m0 + wm * 64 + mt * 16 + g;
            int c = n0 + wn * 64 + nt * 8 + tg * 2;
            float2 v0 = make_float2(acc[mt][nt][0], acc[mt][nt][1]);
            float2 v1 = make_float2(acc[mt][nt][2], acc[mt][nt][3]);
            *(float2*)&C[(size_t)r * N + c]       = v0;
            *(float2*)&C[(size_t)(r + 8) * N + c] = v1;
        }
}

// ---------------- mma.sync fp16 causal flash attention ----------------------
#define FQSTR 272
#define FKSTR 272
#define FVSTR 144
#define QBYTES (128 * FQSTR)
#define KSTAGE (64 * FKSTR)
#define VSTAGE (128 * FVSTR)
#define OFF_Q  0
#define OFF_K  QBYTES
#define OFF_V  (OFF_K + 2 * KSTAGE)
#define FLASH_SMEM (OFF_V + 2 * VSTAGE)      // 106496

__global__ __launch_bounds__(256, 1) void flash_mma(
    const __half* __restrict__ Qh, const __half* __restrict__ Kh,
    const __half* __restrict__ Vth, __half* __restrict__ Oh)
{
    extern __shared__ char sm[];
    const uint32_t smb = s2u(sm);
    const int tid = threadIdx.x, wid = tid >> 5, lane = tid & 31;
    const int g = lane >> 2, tg = lane & 3;
    const int lm = lane >> 3, lr = lane & 7;
    const int qb = gridDim.x - 1 - blockIdx.x;
    const int bh = blockIdx.y;
    const int b = bh / H_, h = bh % H_;
    const int kvh = h / (H_ / HKV_);
    const int q0 = qb * 128;
    const int nkb = 2 * qb + 2;

    const __half* Qhg = Qh + (((size_t)b * H_ + h) * S_ + q0) * HD_;
    const __half* Khg = Kh + ((size_t)b * HKV_ + kvh) * S_ * HD_;
    const __half* Vhg = Vth + ((size_t)b * HKV_ + kvh) * (size_t)HD_ * S_;

    for (int i = tid; i < 2048; i += 256) {
        int r = i >> 4, c = i & 15;
        cpasync16(smb + OFF_Q + r * FQSTR + c * 16, Qhg + (size_t)r * HD_ + c * 8);
    }
    CP_COMMIT();

    auto load_kv = [&](int kb, int st) {
        uint32_t kbase = smb + OFF_K + st * KSTAGE;
        const __half* kh = Khg + (size_t)kb * 64 * HD_;
        for (int i = tid; i < 1024; i += 256) {
            int r = i >> 4, c = i & 15;
            cpasync16(kbase + r * FKSTR + c * 16, kh + (size_t)r * HD_ + c * 8);
        }
        uint32_t vbase = smb + OFF_V + st * VSTAGE;
        const __half* vh = Vhg + kb * 64;
        for (int i = tid; i < 1024; i += 256) {
            int r = i >> 3, c = i & 7;
            cpasync16(vbase + r * FVSTR + c * 16, vh + (size_t)r * S_ + c * 8);
        }
        CP_COMMIT();
    };

    load_kv(0, 0);
    if (nkb > 1) load_kv(1, 1);

    float m0 = -1e30f, m1 = -1e30f, l0 = 0.f, l1 = 0.f;
    float acc[16][4];
#pragma unroll
    for (int i = 0; i < 16; i++)
#pragma unroll
        for (int j = 0; j < 4; j++) acc[i][j] = 0.f;

    const int qi0 = q0 + wid * 16 + g;
    const int qi1 = qi0 + 8;
    const int qimax = q0 + wid * 16 + 15;
    const float sc = 0.08838834764831845f;

    const uint32_t aaddr = smb + OFF_Q + (wid * 16 + (lm & 1) * 8 + lr) * FQSTR + (lm >> 1) * 16;
    const uint32_t brow_off = ((lm >> 1) * 8 + lr);
    const uint32_t bcol_off = (lm & 1) * 16;

    for (int kb = 0; kb < nkb; kb++) {
        int st = kb & 1;
        if (kb + 1 < nkb) { CP_WAIT(1); } else { CP_WAIT(0); }
        __syncthreads();

        if (kb * 64 <= qimax) {
            float c[8][4];
#pragma unroll
            for (int i = 0; i < 8; i++)
#pragma unroll
                for (int j = 0; j < 4; j++) c[i][j] = 0.f;

            uint32_t kaddr = smb + OFF_K + st * KSTAGE + brow_off * FKSTR + bcol_off;
#pragma unroll
            for (int ks = 0; ks < 8; ks++) {
                int ko = ks * 32;
                uint32_t ah[4];
                ldm_x4(ah, aaddr + ko);
#pragma unroll
                for (int p = 0; p < 4; p++) {
                    uint32_t bq[4];
                    ldm_x4(bq, kaddr + p * 16 * FKSTR + ko);
                    mma_f16(c[2 * p],     ah, bq);
                    mma_f16(c[2 * p + 1], ah, bq + 2);
                }
            }

#pragma unroll
            for (int nt = 0; nt < 8; nt++) {
                int k0c = kb * 64 + nt * 8 + tg * 2;
                c[nt][0] = (k0c     <= qi0) ? c[nt][0] * sc : -1e30f;
                c[nt][1] = (k0c + 1 <= qi0) ? c[nt][1] * sc : -1e30f;
                c[nt][2] = (k0c     <= qi1) ? c[nt][2] * sc : -1e30f;
                c[nt][3] = (k0c + 1 <= qi1) ? c[nt][3] * sc : -1e30f;
            }

            float rm0 = -1e30f, rm1 = -1e30f;
#pragma unroll
            for (int nt = 0; nt < 8; nt++) {
                rm0 = fmaxf(rm0, fmaxf(c[nt][0], c[nt][1]));
                rm1 = fmaxf(rm1, fmaxf(c[nt][2], c[nt][3]));
            }
            rm0 = fmaxf(rm0, __shfl_xor_sync(0xffffffffu, rm0, 1));
            rm0 = fmaxf(rm0, __shfl_xor_sync(0xffffffffu, rm0, 2));
            rm1 = fmaxf(rm1, __shfl_xor_sync(0xffffffffu, rm1, 1));
            rm1 = fmaxf(rm1, __shfl_xor_sync(0xffffffffu, rm1, 2));
            float mn0 = fmaxf(m0, rm0), mn1 = fmaxf(m1, rm1);
            float cr0 = __expf(m0 - mn0), cr1 = __expf(m1 - mn1);
            m0 = mn0; m1 = mn1;
            float rs0 = 0.f, rs1 = 0.f;
#pragma unroll
            for (int nt = 0; nt < 8; nt++) {
                c[nt][0] = __expf(c[nt][0] - mn0);
                c[nt][1] = __expf(c[nt][1] - mn0);
                c[nt][2] = __expf(c[nt][2] - mn1);
                c[nt][3] = __expf(c[nt][3] - mn1);
                rs0 += c[nt][0] + c[nt][1];
                rs1 += c[nt][2] + c[nt][3];
            }
            rs0 += __shfl_xor_sync(0xffffffffu, rs0, 1);
            rs0 += __shfl_xor_sync(0xffffffffu, rs0, 2);
            rs1 += __shfl_xor_sync(0xffffffffu, rs1, 1);
            rs1 += __shfl_xor_sync(0xffffffffu, rs1, 2);
            l0 = l0 * cr0 + rs0;
            l1 = l1 * cr1 + rs1;
#pragma unroll
            for (int nt = 0; nt < 16; nt++) {
                acc[nt][0] *= cr0; acc[nt][1] *= cr0;
                acc[nt][2] *= cr1; acc[nt][3] *= cr1;
            }

            uint32_t ph[4][4];
#pragma unroll
            for (int s = 0; s < 4; s++) {
                ph[s][0] = packh_hi(c[2*s][0],   c[2*s][1]);
                ph[s][1] = packh_hi(c[2*s][2],   c[2*s][3]);
                ph[s][2] = packh_hi(c[2*s+1][0], c[2*s+1][1]);
                ph[s][3] = packh_hi(c[2*s+1][2], c[2*s+1][3]);
            }

            uint32_t vaddr = smb + OFF_V + st * VSTAGE + brow_off * FVSTR + bcol_off;
#pragma unroll
            for (int s = 0; s < 4; s++) {
#pragma unroll
                for (int p = 0; p < 8; p++) {
                    uint32_t bq[4];
                    ldm_x4(bq, vaddr + p * 16 * FVSTR + s * 32);
                    mma_f16(acc[2 * p],     ph[s], bq);
                    mma_f16(acc[2 * p + 1], ph[s], bq + 2);
                }
            }
        }

        __syncthreads();
        if (kb + 2 < nkb) load_kv(kb + 2, st);
    }

    float rl0 = 1.f / l0, rl1 = 1.f / l1;
    int t0 = b * S_ + q0 + wid * 16 + g;
    size_t o0 = (size_t)t0 * (H_ * HD_) + h * HD_;
    size_t o1 = (size_t)(t0 + 8) * (H_ * HD_) + h * HD_;
#pragma unroll
    for (int nt = 0; nt < 16; nt++) {
        int d = nt * 8 + tg * 2;
        *(uint32_t*)(Oh + o0 + d) = packh_hi(acc[nt][0] * rl0, acc[nt][1] * rl0);
        *(uint32_t*)(Oh + o1 + d) = packh_hi(acc[nt][2] * rl1, acc[nt][3] * rl1);
    }
}

// ---------------------------------------------------------------------------
extern "C" void kernel_launch(void* const* d_in, const int* in_sizes, int n_in,
                              void* d_out, int out_size)
{
    const float* hidden = (const float*)d_in[0];
    const float* wq     = (const float*)d_in[1];
    const float* wk     = (const float*)d_in[2];
    const float* wv     = (const float*)d_in[3];
    const float* wo     = (const float*)d_in[4];
    const float* qw     = (const float*)d_in[5];
    const float* kw     = (const float*)d_in[6];
    const int*   pos    = (const int*)d_in[7];
    float* out = (float*)d_out;

    __half *hid16, *wqkvT, *woT, *at16, *qh, *kh, *vth;
    float4* rope;
    cudaGetSymbolAddress((void**)&hid16, g_hid);
    cudaGetSymbolAddress((void**)&wqkvT, g_wqkvT);
    cudaGetSymbolAddress((void**)&woT,   g_woT);
    cudaGetSymbolAddress((void**)&at16,  g_at);
    cudaGetSymbolAddress((void**)&qh,    g_qh);
    cudaGetSymbolAddress((void**)&kh,    g_kh);
    cudaGetSymbolAddress((void**)&vth,   g_vth);
    cudaGetSymbolAddress((void**)&rope,  g_rope);

    cudaFuncSetAttribute(gemm_qkv_fused, cudaFuncAttributeMaxDynamicSharedMemorySize,
                         (int)G_SMEM);
    cudaFuncSetAttribute(gemm_mma, cudaFuncAttributeMaxDynamicSharedMemorySize,
                         (int)G_SMEM);
    cudaFuncSetAttribute(flash_mma, cudaFuncAttributeMaxDynamicSharedMemorySize,
                         (int)FLASH_SMEM);

    // convert hidden to fp16; build RoPE table
    int n4 = NT * D_ / 4;
    convert_f16<<<(n4 + 255) / 256, 256>>>((const float4*)hidden, (uint2*)hid16, n4);
    rope_table<<<S_, 32>>>(rope);

    // transpose weights to fp16 (concatenated QKV + WO)
    transpose_f16<<<dim3((H_*HD_)/32, D_/32), dim3(32, 8)>>>(wq, wqkvT, D_, H_*HD_);
    transpose_f16<<<dim3((HKV_*HD_)/32, D_/32), dim3(32, 8)>>>(
        wk, wqkvT + (size_t)2048 * D_, D_, HKV_*HD_);
    transpose_f16<<<dim3((HKV_*HD_)/32, D_/32), dim3(32, 8)>>>(
        wv, wqkvT + (size_t)2560 * D_, D_, HKV_*HD_);
    transpose_f16<<<dim3(D_/32, (H_*HD_)/32), dim3(32, 8)>>>(wo, woT, H_*HD_, D_);

    // fused QKV projection + RMSNorm + RoPE + head transpose
    gemm_qkv_fused<<<dim3(NQKV/256, NT/128), 256, G_SMEM>>>(
        hid16, wqkvT, qw, kw, pos, rope, qh, kh, vth);

    // tensor-core causal flash attention (fp16) -> attn fp16
    flash_mma<<<dim3(S_/128, B_*H_), 256, FLASH_SMEM>>>(qh, kh, vth, at16);

    // output projection (fp16)
    gemm_mma<<<dim3(D_/256, NT/128), 256, G_SMEM>>>(at16, woT, out, NT, D_, D_);
}

// round 12
// speedup vs baseline: 13.6586x; 1.0848x over previous
#include <cuda_runtime.h>
#include <cuda_fp16.h>
#include <math.h>
#include <stdint.h>

#define B_   2
#define S_   2048
#define D_   2048
#define H_   16
#define HKV_ 4
#define HD_  128
#define NT   (B_ * S_)
#define NQKV 3072

// ---------------- scratch ---------------------------------------------------
__device__ __half g_hid[NT * D_];
__device__ __half g_wqkvT[NQKV * D_];
__device__ __half g_woT[(H_*HD_) * D_];
__device__ __half g_at[NT * (H_*HD_)];

__device__ __half g_qh[NT * H_ * HD_];
__device__ __half g_kh[NT * HKV_ * HD_];
__device__ __half g_vth[NT * HKV_ * HD_];
__device__ float4 g_rope[S_ * 32];

// ---------------- helpers ---------------------------------------------------
__device__ __forceinline__ uint32_t s2u(const void* p) {
    return (uint32_t)__cvta_generic_to_shared(p);
}
__device__ __forceinline__ void cpasync16(uint32_t dst, const void* src) {
    asm volatile("cp.async.cg.shared.global [%0], [%1], 16;" :: "r"(dst), "l"(src));
}
#define CP_COMMIT() asm volatile("cp.async.commit_group;")
#define CP_WAIT(N)  asm volatile("cp.async.wait_group %0;" :: "n"(N))

__device__ __forceinline__ void mma_f16(float* d, const uint32_t* a, const uint32_t* b) {
    asm volatile(
        "mma.sync.aligned.m16n8k16.row.col.f32.f16.f16.f32 "
        "{%0,%1,%2,%3}, {%4,%5,%6,%7}, {%8,%9}, {%0,%1,%2,%3};"
        : "+f"(d[0]), "+f"(d[1]), "+f"(d[2]), "+f"(d[3])
        : "r"(a[0]), "r"(a[1]), "r"(a[2]), "r"(a[3]), "r"(b[0]), "r"(b[1]));
}
__device__ __forceinline__ void ldm_x4(uint32_t* r, uint32_t addr) {
    asm volatile("ldmatrix.sync.aligned.m8n8.x4.shared.b16 {%0,%1,%2,%3}, [%4];"
                 : "=r"(r[0]), "=r"(r[1]), "=r"(r[2]), "=r"(r[3]) : "r"(addr));
}
__device__ __forceinline__ uint32_t packh_hi(float x, float y) {
    __half2 h = __floats2half2_rn(x, y);
    return *(uint32_t*)&h;
}

// ---------------- merged prep kernel ----------------------------------------
// blocks [0,8192): convert hidden fp32->fp16
// [8192,12288): transpose wq   [12288,13312): wk   [13312,14336): wv
// [14336,18432): transpose wo  [18432,20480): rope table
__global__ __launch_bounds__(256) void prep_kernel(
    const float4* __restrict__ hid, uint2* __restrict__ hid16,
    const float* __restrict__ wq, const float* __restrict__ wk,
    const float* __restrict__ wv, const float* __restrict__ wo,
    __half* __restrict__ wqkvT, __half* __restrict__ woT,
    float4* __restrict__ rope)
{
    const int bid = blockIdx.x;
    const int tid = threadIdx.x;

    if (bid < 8192) {
        int i = bid * 256 + tid;
        float4 v = hid[i];
        __half2 h0 = __floats2half2_rn(v.x, v.y);
        __half2 h1 = __floats2half2_rn(v.z, v.w);
        uint2 H;
        H.x = *(uint32_t*)&h0; H.y = *(uint32_t*)&h1;
        hid16[i] = H;
        return;
    }
    if (bid >= 18432) {
        if (tid >= 32) return;
        int p = bid - 18432, j = tid;
        float i0 = exp2f(-13.287712379549449f * (float)(2 * j)     * (1.0f / 64.0f));
        float i1 = exp2f(-13.287712379549449f * (float)(2 * j + 1) * (1.0f / 64.0f));
        float c0, s0, c1, s1;
        sincosf((float)p * i0, &s0, &c0);
        sincosf((float)p * i1, &s1, &c1);
        rope[p * 32 + j] = make_float4(c0, s0, c1, s1);
        return;
    }

    // transpose W[K,N] -> T[N,K]
    const float* W; __half* T; int K, N, t;
    if (bid < 12288)      { t = bid - 8192;  W = wq; T = wqkvT;                    K = D_;     N = 2048; }
    else if (bid < 13312) { t = bid - 12288; W = wk; T = wqkvT + (size_t)2048*D_;  K = D_;     N = 512;  }
    else if (bid < 14336) { t = bid - 13312; W = wv; T = wqkvT + (size_t)2560*D_;  K = D_;     N = 512;  }
    else                  { t = bid - 14336; W = wo; T = woT;                      K = H_*HD_; N = D_;   }
    int nb = N / 32;
    int n0 = (t % nb) * 32, k0 = (t / nb) * 32;
    int tx = tid & 31, ty = tid >> 5;

    __shared__ float tbuf[32][33];
    for (int j = ty; j < 32; j += 8)
        tbuf[j][tx] = W[(size_t)(k0 + j) * N + n0 + tx];
    __syncthreads();
    for (int j = ty; j < 32; j += 8)
        T[(size_t)(n0 + j) * K + k0 + tx] = __float2half(tbuf[tx][j]);
}

// ---------------- GEMM tiling: 128x128, 8 warps (32x64 each), 2 CTA/SM ------
#define KC      64
#define RSTRIDE 144
#define OFF_B   18432
#define STAGE   36864
#define G_SMEM  (2 * STAGE)     // 73728

// ---------------- QKV GEMM fused with RMSNorm+RoPE+transpose ----------------
__global__ __launch_bounds__(256, 2) void gemm_qkv_fused(
    const __half* __restrict__ A, const __half* __restrict__ B,
    const float* __restrict__ qw, const float* __restrict__ kw,
    const int* __restrict__ pos_ids, const float4* __restrict__ rope,
    __half* __restrict__ Qo, __half* __restrict__ Ko, __half* __restrict__ Vo)
{
    extern __shared__ char sm[];
    const uint32_t smb = s2u(sm);
    const int tid  = threadIdx.x;
    const int wid  = tid >> 5, lane = tid & 31;
    const int wm   = wid & 3, wn = wid >> 2;       // 4 x 2 warp grid
    const int g    = lane >> 2, tg = lane & 3;
    const int lm   = lane >> 3, lr = lane & 7;
    const int m0   = blockIdx.y * 128;
    const int bx   = blockIdx.x;
    const int n0   = bx * 128;
    const int K    = D_;

    float acc[2][8][4];
#pragma unroll
    for (int a = 0; a < 2; a++)
#pragma unroll
        for (int b2 = 0; b2 < 8; b2++)
#pragma unroll
            for (int c = 0; c < 4; c++) acc[a][b2][c] = 0.f;

    const int nchunks = K / KC;

    auto load_chunk = [&](int kc, int st) {
        uint32_t base = smb + st * STAGE;
        int k0 = kc * KC;
#pragma unroll
        for (int i = 0; i < 4; i++) {
            int lin = tid + i * 256;
            int r = lin >> 3, sg = lin & 7;
            uint32_t off = r * RSTRIDE + sg * 16;
            cpasync16(base + off,         A + (size_t)(m0 + r) * K + k0 + sg * 8);
            cpasync16(base + OFF_B + off, B + (size_t)(n0 + r) * K + k0 + sg * 8);
        }
        CP_COMMIT();
    };

    auto compute = [&](int st) {
        uint32_t base = smb + st * STAGE;
        uint32_t aaddr = base + (wm * 32 + (lm & 1) * 8 + lr) * RSTRIDE + (lm >> 1) * 16;
        uint32_t baddr = base + OFF_B + (wn * 64 + (lm >> 1) * 8 + lr) * RSTRIDE + (lm & 1) * 16;
#pragma unroll
        for (int ks = 0; ks < 4; ks++) {
            int ko = ks * 32;
            uint32_t ah[2][4];
            ldm_x4(ah[0], aaddr + ko);
            ldm_x4(ah[1], aaddr + 16 * RSTRIDE + ko);
#pragma unroll
            for (int p = 0; p < 4; p++) {
                uint32_t bq[4];
                ldm_x4(bq, baddr + p * 16 * RSTRIDE + ko);
#pragma unroll
                for (int mt = 0; mt < 2; mt++) {
                    mma_f16(acc[mt][2 * p],     ah[mt], bq);
                    mma_f16(acc[mt][2 * p + 1], ah[mt], bq + 2);
                }
            }
        }
    };

    load_chunk(0, 0);
    for (int kc = 0; kc < nchunks; kc++) {
        int st = kc & 1;
        if (kc + 1 < nchunks) load_chunk(kc + 1, st ^ 1);
        if (kc + 1 < nchunks) { CP_WAIT(1); } else { CP_WAIT(0); }
        __syncthreads();
        compute(st);
        __syncthreads();
    }

    // ================= fused epilogue (one head per N-block) =================
    __half* xbuf  = (__half*)sm;            // [128][136] fp16 = 34816 B
    float*  ssbuf = (float*)(sm + 34816);   // [128][2]

    if (bx < 20) {
        const bool isq = bx < 16;
        const float* w = isq ? qw : kw;

        // 1. per-row sum of squares
#pragma unroll
        for (int mt = 0; mt < 2; mt++) {
            float s0 = 0.f, s1 = 0.f;
#pragma unroll
            for (int nt = 0; nt < 8; nt++) {
                s0 += acc[mt][nt][0] * acc[mt][nt][0] + acc[mt][nt][1] * acc[mt][nt][1];
                s1 += acc[mt][nt][2] * acc[mt][nt][2] + acc[mt][nt][3] * acc[mt][nt][3];
            }
            s0 += __shfl_xor_sync(0xffffffffu, s0, 1);
            s0 += __shfl_xor_sync(0xffffffffu, s0, 2);
            s1 += __shfl_xor_sync(0xffffffffu, s1, 1);
            s1 += __shfl_xor_sync(0xffffffffu, s1, 2);
            if (tg == 0) {
                int R = wm * 32 + mt * 16 + g;
                ssbuf[R * 2 + wn]       = s0;
                ssbuf[(R + 8) * 2 + wn] = s1;
            }
        }
        __syncthreads();

        // 2. normalize + weight; fp32 in acc, fp16 copy to xbuf for partner
#pragma unroll
        for (int mt = 0; mt < 2; mt++) {
            int R0 = wm * 32 + mt * 16 + g, R1 = R0 + 8;
            float r0 = rsqrtf((ssbuf[R0 * 2] + ssbuf[R0 * 2 + 1]) * (1.0f / 128.0f) + 1e-6f);
            float r1 = rsqrtf((ssbuf[R1 * 2] + ssbuf[R1 * 2 + 1]) * (1.0f / 128.0f) + 1e-6f);
#pragma unroll
            for (int nt = 0; nt < 8; nt++) {
                int c = wn * 64 + nt * 8 + tg * 2;
                float w0 = w[c], w1 = w[c + 1];
                acc[mt][nt][0] *= r0 * w0; acc[mt][nt][1] *= r0 * w1;
                acc[mt][nt][2] *= r1 * w0; acc[mt][nt][3] *= r1 * w1;
                *(uint32_t*)(xbuf + R0 * 136 + c) = packh_hi(acc[mt][nt][0], acc[mt][nt][1]);
                *(uint32_t*)(xbuf + R1 * 136 + c) = packh_hi(acc[mt][nt][2], acc[mt][nt][3]);
            }
        }
        __syncthreads();

        // 3. RoPE + transposed store
        __half* dst = isq ? Qo : Ko;
        const int nheads = isq ? H_ : HKV_;
        const int head = isq ? bx : bx - 16;
#pragma unroll
        for (int mt = 0; mt < 2; mt++) {
#pragma unroll
            for (int hf = 0; hf < 2; hf++) {
                int R = wm * 32 + mt * 16 + g + hf * 8;
                int tok = blockIdx.y * 128 + R;
                int b = tok >> 11, s = tok & 2047;
                int p = pos_ids[tok];
#pragma unroll
                for (int nt = 0; nt < 8; nt++) {
                    int d = wn * 64 + nt * 8 + tg * 2;
                    float4 cs = rope[p * 32 + ((d & 63) >> 1)];
                    uint32_t pv = *(uint32_t*)(xbuf + R * 136 + (d ^ 64));
                    __half2 ph2 = *(__half2*)&pv;
                    float rt0 = __half2float(ph2.x), rt1 = __half2float(ph2.y);
                    if (d < 64) { rt0 = -rt0; rt1 = -rt1; }
                    float x0 = acc[mt][nt][hf * 2 + 0], x1 = acc[mt][nt][hf * 2 + 1];
                    float o0 = x0 * cs.x + rt0 * cs.y;
                    float o1 = x1 * cs.z + rt1 * cs.w;
                    size_t off = (((size_t)b * nheads + head) * S_ + s) * HD_ + d;
                    *(uint32_t*)(dst + off) = packh_hi(o0, o1);
                }
            }
        }
    } else {
        // V: fp16 convert + transpose to [b,kvh,d,s]
        const int kvh = bx - 20;
#pragma unroll
        for (int mt = 0; mt < 2; mt++) {
#pragma unroll
            for (int hf = 0; hf < 2; hf++) {
                int R = wm * 32 + mt * 16 + g + hf * 8;
                int tok = blockIdx.y * 128 + R;
                int b = tok >> 11, s = tok & 2047;
#pragma unroll
                for (int nt = 0; nt < 8; nt++) {
                    int d = wn * 64 + nt * 8 + tg * 2;
                    size_t off = (((size_t)b * HKV_ + kvh) * HD_ + d) * S_ + s;
                    Vo[off]      = __float2half(acc[mt][nt][hf * 2 + 0]);
                    Vo[off + S_] = __float2half(acc[mt][nt][hf * 2 + 1]);
                }
            }
        }
    }
}

// ---------------- generic fp16 GEMM (WO), 128x128, 2 CTA/SM -----------------
__global__ __launch_bounds__(256, 2) void gemm_mma(
    const __half* __restrict__ A, const __half* __restrict__ B,
    float* __restrict__ C, int M, int N, int K)
{
    extern __shared__ char sm[];
    const uint32_t smb = s2u(sm);
    const int tid  = threadIdx.x;
    const int wid  = tid >> 5, lane = tid & 31;
    const int wm   = wid & 3, wn = wid >> 2;
    const int g    = lane >> 2, tg = lane & 3;
    const int lm   = lane >> 3, lr = lane & 7;
    const int m0   = blockIdx.y * 128, n0 = blockIdx.x * 128;

    float acc[2][8][4];
#pragma unroll
    for (int a = 0; a < 2; a++)
#pragma unroll
        for (int b = 0; b < 8; b++)
#pragma unroll
            for (int c = 0; c < 4; c++) acc[a][b][c] = 0.f;

    const int nchunks = K / KC;

    auto load_chunk = [&](int kc, int st) {
        uint32_t base = smb + st * STAGE;
        int k0 = kc * KC;
#pragma unroll
        for (int i = 0; i < 4; i++) {
            int lin = tid + i * 256;
            int r = lin >> 3, sg = lin & 7;
            uint32_t off = r * RSTRIDE + sg * 16;
            cpasync16(base + off,         A + (size_t)(m0 + r) * K + k0 + sg * 8);
            cpasync16(base + OFF_B + off, B + (size_t)(n0 + r) * K + k0 + sg * 8);
        }
        CP_COMMIT();
    };

    auto compute = [&](int st) {
        uint32_t base = smb + st * STAGE;
        uint32_t aaddr = base + (wm * 32 + (lm & 1) * 8 + lr) * RSTRIDE + (lm >> 1) * 16;
        uint32_t baddr = base + OFF_B + (wn * 64 + (lm >> 1) * 8 + lr) * RSTRIDE + (lm & 1) * 16;
#pragma unroll
        for (int ks = 0; ks < 4; ks++) {
            int ko = ks * 32;
            uint32_t ah[2][4];
            ldm_x4(ah[0], aaddr + ko);
            ldm_x4(ah[1], aaddr + 16 * RSTRIDE + ko);
#pragma unroll
            for (int p = 0; p < 4; p++) {
                uint32_t bq[4];
                ldm_x4(bq, baddr + p * 16 * RSTRIDE + ko);
#pragma unroll
                for (int mt = 0; mt < 2; mt++) {
                    mma_f16(acc[mt][2 * p],     ah[mt], bq);
                    mma_f16(acc[mt][2 * p + 1], ah[mt], bq + 2);
                }
            }
        }
    };

    load_chunk(0, 0);
    for (int kc = 0; kc < nchunks; kc++) {
        int st = kc & 1;
        if (kc + 1 < nchunks) load_chunk(kc + 1, st ^ 1);
        if (kc + 1 < nchunks) { CP_WAIT(1); } else { CP_WAIT(0); }
        __syncthreads();
        compute(st);
        __syncthreads();
    }

#pragma unroll
    for (int mt = 0; mt < 2; mt++)
#pragma unroll
        for (int nt = 0; nt < 8; nt++) {
            int r = m0 + wm * 32 + mt * 16 + g;
            int c = n0 + wn * 64 + nt * 8 + tg * 2;
            float2 v0 = make_float2(acc[mt][nt][0], acc[mt][nt][1]);
            float2 v1 = make_float2(acc[mt][nt][2], acc[mt][nt][3]);
            *(float2*)&C[(size_t)r * N + c]       = v0;
            *(float2*)&C[(size_t)(r + 8) * N + c] = v1;
        }
}

// ---------------- mma.sync fp16 causal flash attention ----------------------
#define FQSTR 272
#define FKSTR 272
#define FVSTR 144
#define QBYTES (128 * FQSTR)
#define KSTAGE (64 * FKSTR)
#define VSTAGE (128 * FVSTR)
#define OFF_Q  0
#define OFF_K  QBYTES
#define OFF_V  (OFF_K + 2 * KSTAGE)
#define FLASH_SMEM (OFF_V + 2 * VSTAGE)      // 106496

__global__ __launch_bounds__(256, 1) void flash_mma(
    const __half* __restrict__ Qh, const __half* __restrict__ Kh,
    const __half* __restrict__ Vth, __half* __restrict__ Oh)
{
    extern __shared__ char sm[];
    const uint32_t smb = s2u(sm);
    const int tid = threadIdx.x, wid = tid >> 5, lane = tid & 31;
    const int g = lane >> 2, tg = lane & 3;
    const int lm = lane >> 3, lr = lane & 7;
    const int qb = gridDim.x - 1 - blockIdx.x;
    const int bh = blockIdx.y;
    const int b = bh / H_, h = bh % H_;
    const int kvh = h / (H_ / HKV_);
    const int q0 = qb * 128;
    const int nkb = 2 * qb + 2;

    const __half* Qhg = Qh + (((size_t)b * H_ + h) * S_ + q0) * HD_;
    const __half* Khg = Kh + ((size_t)b * HKV_ + kvh) * S_ * HD_;
    const __half* Vhg = Vth + ((size_t)b * HKV_ + kvh) * (size_t)HD_ * S_;

    for (int i = tid; i < 2048; i += 256) {
        int r = i >> 4, c = i & 15;
        cpasync16(smb + OFF_Q + r * FQSTR + c * 16, Qhg + (size_t)r * HD_ + c * 8);
    }
    CP_COMMIT();

    auto load_kv = [&](int kb, int st) {
        uint32_t kbase = smb + OFF_K + st * KSTAGE;
        const __half* kh = Khg + (size_t)kb * 64 * HD_;
        for (int i = tid; i < 1024; i += 256) {
            int r = i >> 4, c = i & 15;
            cpasync16(kbase + r * FKSTR + c * 16, kh + (size_t)r * HD_ + c * 8);
        }
        uint32_t vbase = smb + OFF_V + st * VSTAGE;
        const __half* vh = Vhg + kb * 64;
        for (int i = tid; i < 1024; i += 256) {
            int r = i >> 3, c = i & 7;
            cpasync16(vbase + r * FVSTR + c * 16, vh + (size_t)r * S_ + c * 8);
        }
        CP_COMMIT();
    };

    load_kv(0, 0);
    if (nkb > 1) load_kv(1, 1);

    float m0 = -1e30f, m1 = -1e30f, l0 = 0.f, l1 = 0.f;
    float acc[16][4];
#pragma unroll
    for (int i = 0; i < 16; i++)
#pragma unroll
        for (int j = 0; j < 4; j++) acc[i][j] = 0.f;

    const int qi0 = q0 + wid * 16 + g;
    const int qi1 = qi0 + 8;
    const int qimax = q0 + wid * 16 + 15;
    const float sc = 0.08838834764831845f;

    const uint32_t aaddr = smb + OFF_Q + (wid * 16 + (lm & 1) * 8 + lr) * FQSTR + (lm >> 1) * 16;
    const uint32_t brow_off = ((lm >> 1) * 8 + lr);
    const uint32_t bcol_off = (lm & 1) * 16;

    for (int kb = 0; kb < nkb; kb++) {
        int st = kb & 1;
        if (kb + 1 < nkb) { CP_WAIT(1); } else { CP_WAIT(0); }
        __syncthreads();

        if (kb * 64 <= qimax) {
            float c[8][4];
#pragma unroll
            for (int i = 0; i < 8; i++)
#pragma unroll
                for (int j = 0; j < 4; j++) c[i][j] = 0.f;

            uint32_t kaddr = smb + OFF_K + st * KSTAGE + brow_off * FKSTR + bcol_off;
#pragma unroll
            for (int ks = 0; ks < 8; ks++) {
                int ko = ks * 32;
                uint32_t ah[4];
                ldm_x4(ah, aaddr + ko);
#pragma unroll
                for (int p = 0; p < 4; p++) {
                    uint32_t bq[4];
                    ldm_x4(bq, kaddr + p * 16 * FKSTR + ko);
                    mma_f16(c[2 * p],     ah, bq);
                    mma_f16(c[2 * p + 1], ah, bq + 2);
                }
            }

#pragma unroll
            for (int nt = 0; nt < 8; nt++) {
                int k0c = kb * 64 + nt * 8 + tg * 2;
                c[nt][0] = (k0c     <= qi0) ? c[nt][0] * sc : -1e30f;
                c[nt][1] = (k0c + 1 <= qi0) ? c[nt][1] * sc : -1e30f;
                c[nt][2] = (k0c     <= qi1) ? c[nt][2] * sc : -1e30f;
                c[nt][3] = (k0c + 1 <= qi1) ? c[nt][3] * sc : -1e30f;
            }

            float rm0 = -1e30f, rm1 = -1e30f;
#pragma unroll
            for (int nt = 0; nt < 8; nt++) {
                rm0 = fmaxf(rm0, fmaxf(c[nt][0], c[nt][1]));
                rm1 = fmaxf(rm1, fmaxf(c[nt][2], c[nt][3]));
            }
            rm0 = fmaxf(rm0, __shfl_xor_sync(0xffffffffu, rm0, 1));
            rm0 = fmaxf(rm0, __shfl_xor_sync(0xffffffffu, rm0, 2));
            rm1 = fmaxf(rm1, __shfl_xor_sync(0xffffffffu, rm1, 1));
            rm1 = fmaxf(rm1, __shfl_xor_sync(0xffffffffu, rm1, 2));
            float mn0 = fmaxf(m0, rm0), mn1 = fmaxf(m1, rm1);
            float cr0 = __expf(m0 - mn0), cr1 = __expf(m1 - mn1);
            m0 = mn0; m1 = mn1;
            float rs0 = 0.f, rs1 = 0.f;
#pragma unroll
            for (int nt = 0; nt < 8; nt++) {
                c[nt][0] = __expf(c[nt][0] - mn0);
                c[nt][1] = __expf(c[nt][1] - mn0);
                c[nt][2] = __expf(c[nt][2] - mn1);
                c[nt][3] = __expf(c[nt][3] - mn1);
                rs0 += c[nt][0] + c[nt][1];
                rs1 += c[nt][2] + c[nt][3];
            }
            rs0 += __shfl_xor_sync(0xffffffffu, rs0, 1);
            rs0 += __shfl_xor_sync(0xffffffffu, rs0, 2);
            rs1 += __shfl_xor_sync(0xffffffffu, rs1, 1);
            rs1 += __shfl_xor_sync(0xffffffffu, rs1, 2);
            l0 = l0 * cr0 + rs0;
            l1 = l1 * cr1 + rs1;
#pragma unroll
            for (int nt = 0; nt < 16; nt++) {
                acc[nt][0] *= cr0; acc[nt][1] *= cr0;
                acc[nt][2] *= cr1; acc[nt][3] *= cr1;
            }

            uint32_t ph[4][4];
#pragma unroll
            for (int s = 0; s < 4; s++) {
                ph[s][0] = packh_hi(c[2*s][0],   c[2*s][1]);
                ph[s][1] = packh_hi(c[2*s][2],   c[2*s][3]);
                ph[s][2] = packh_hi(c[2*s+1][0], c[2*s+1][1]);
                ph[s][3] = packh_hi(c[2*s+1][2], c[2*s+1][3]);
            }

            uint32_t vaddr = smb + OFF_V + st * VSTAGE + brow_off * FVSTR + bcol_off;
#pragma unroll
            for (int s = 0; s < 4; s++) {
#pragma unroll
                for (int p = 0; p < 8; p++) {
                    uint32_t bq[4];
                    ldm_x4(bq, vaddr + p * 16 * FVSTR + s * 32);
                    mma_f16(acc[2 * p],     ph[s], bq);
                    mma_f16(acc[2 * p + 1], ph[s], bq + 2);
                }
            }
        }

        __syncthreads();
        if (kb + 2 < nkb) load_kv(kb + 2, st);
    }

    float rl0 = 1.f / l0, rl1 = 1.f / l1;
    int t0 = b * S_ + q0 + wid * 16 + g;
    size_t o0 = (size_t)t0 * (H_ * HD_) + h * HD_;
    size_t o1 = (size_t)(t0 + 8) * (H_ * HD_) + h * HD_;
#pragma unroll
    for (int nt = 0; nt < 16; nt++) {
        int d = nt * 8 + tg * 2;
        *(uint32_t*)(Oh + o0 + d) = packh_hi(acc[nt][0] * rl0, acc[nt][1] * rl0);
        *(uint32_t*)(Oh + o1 + d) = packh_hi(acc[nt][2] * rl1, acc[nt][3] * rl1);
    }
}

// ---------------------------------------------------------------------------
extern "C" void kernel_launch(void* const* d_in, const int* in_sizes, int n_in,
                              void* d_out, int out_size)
{
    const float* hidden = (const float*)d_in[0];
    const float* wq     = (const float*)d_in[1];
    const float* wk     = (const float*)d_in[2];
    const float* wv     = (const float*)d_in[3];
    const float* wo     = (const float*)d_in[4];
    const float* qw     = (const float*)d_in[5];
    const float* kw     = (const float*)d_in[6];
    const int*   pos    = (const int*)d_in[7];
    float* out = (float*)d_out;

    __half *hid16, *wqkvT, *woT, *at16, *qh, *kh, *vth;
    float4* rope;
    cudaGetSymbolAddress((void**)&hid16, g_hid);
    cudaGetSymbolAddress((void**)&wqkvT, g_wqkvT);
    cudaGetSymbolAddress((void**)&woT,   g_woT);
    cudaGetSymbolAddress((void**)&at16,  g_at);
    cudaGetSymbolAddress((void**)&qh,    g_qh);
    cudaGetSymbolAddress((void**)&kh,    g_kh);
    cudaGetSymbolAddress((void**)&vth,   g_vth);
    cudaGetSymbolAddress((void**)&rope,  g_rope);

    cudaFuncSetAttribute(gemm_qkv_fused, cudaFuncAttributeMaxDynamicSharedMemorySize,
                         (int)G_SMEM);
    cudaFuncSetAttribute(gemm_mma, cudaFuncAttributeMaxDynamicSharedMemorySize,
                         (int)G_SMEM);
    cudaFuncSetAttribute(flash_mma, cudaFuncAttributeMaxDynamicSharedMemorySize,
                         (int)FLASH_SMEM);

    // one prep launch: convert + 4 weight transposes + rope table
    prep_kernel<<<20480, 256>>>((const float4*)hidden, (uint2*)hid16,
                                wq, wk, wv, wo, wqkvT, woT, rope);

    // fused QKV projection + RMSNorm + RoPE + head transpose (24 x 32 grid)
    gemm_qkv_fused<<<dim3(NQKV/128, NT/128), 256, G_SMEM>>>(
        hid16, wqkvT, qw, kw, pos, rope, qh, kh, vth);

    // tensor-core causal flash attention (fp16) -> attn fp16
    flash_mma<<<dim3(S_/128, B_*H_), 256, FLASH_SMEM>>>(qh, kh, vth, at16);

    // output projection (fp16, 16 x 32 grid)
    gemm_mma<<<dim3(D_/128, NT/128), 256, G_SMEM>>>(at16, woT, out, NT, D_, D_);
}